// round 7
// baseline (speedup 1.0000x reference)
#include <cuda_runtime.h>
#include <cuda_bf16.h>
#include <math.h>
#include <stdint.h>

#define BL     8192
#define DMODEL 1024
#define DLLM   4096
#define DINNER 1024
#define SEQ_S  1000
#define NHEAD  16
#define EDIM   64

// ---------------------------------------------------------------------------
// Portable PTX helpers (base compute_103 target — NO tcgen05)
// ---------------------------------------------------------------------------
__device__ __forceinline__ uint32_t smem_u32(const void* p) {
    uint32_t a;
    asm("{ .reg .u64 t; cvta.to.shared.u64 t, %1; cvt.u32.u64 %0, t; }"
        : "=r"(a) : "l"(p));
    return a;
}

#define SWZ(o) ((o) ^ (((o) >> 3) & 0x70))

#define CP_ASYNC16(dst, src) \
    asm volatile("cp.async.cg.shared.global [%0], [%1], 16;\n" :: "r"(dst), "l"(src))
#define CP_COMMIT() asm volatile("cp.async.commit_group;\n" ::: "memory")
#define CP_WAIT1()  asm volatile("cp.async.wait_group 1;\n" ::: "memory")
#define CP_WAIT0()  asm volatile("cp.async.wait_group 0;\n" ::: "memory")
#define STS_ZERO16(addr) \
    asm volatile("st.shared.v4.b32 [%0], {%1,%1,%1,%1};\n" :: "r"(addr), "r"(0u) : "memory")

__device__ __forceinline__ void ldsm4(uint32_t* r, uint32_t a) {
    asm volatile("ldmatrix.sync.aligned.m8n8.x4.shared.b16 {%0,%1,%2,%3}, [%4];\n"
        : "=r"(r[0]), "=r"(r[1]), "=r"(r[2]), "=r"(r[3]) : "r"(a));
}
__device__ __forceinline__ void ldsm4t(uint32_t* r, uint32_t a) {
    asm volatile("ldmatrix.sync.aligned.m8n8.x4.trans.shared.b16 {%0,%1,%2,%3}, [%4];\n"
        : "=r"(r[0]), "=r"(r[1]), "=r"(r[2]), "=r"(r[3]) : "r"(a));
}
__device__ __forceinline__ void mma16816(float* c, const uint32_t* a,
                                         uint32_t b0, uint32_t b1) {
    asm volatile(
        "mma.sync.aligned.m16n8k16.row.col.f32.bf16.bf16.f32 "
        "{%0,%1,%2,%3}, {%4,%5,%6,%7}, {%8,%9}, {%0,%1,%2,%3};\n"
        : "+f"(c[0]), "+f"(c[1]), "+f"(c[2]), "+f"(c[3])
        : "r"(a[0]), "r"(a[1]), "r"(a[2]), "r"(a[3]), "r"(b0), "r"(b1));
}

__device__ __forceinline__ void pack_split(float a, float b, uint32_t& hi, uint32_t& lo) {
    __nv_bfloat162 h = __floats2bfloat162_rn(a, b);
    float ra = a - __bfloat162float(h.x);
    float rb = b - __bfloat162float(h.y);
    __nv_bfloat162 l = __floats2bfloat162_rn(ra, rb);
    hi = *reinterpret_cast<uint32_t*>(&h);
    lo = *reinterpret_cast<uint32_t*>(&l);
}

// ---------------------------------------------------------------------------
// Scratch (device globals — no allocation allowed)
// ---------------------------------------------------------------------------
__device__ __nv_bfloat16 g_th[BL * DMODEL],  g_tl[BL * DMODEL];
__device__ __nv_bfloat16 g_sh[SEQ_S * DLLM], g_sl[SEQ_S * DLLM];
__device__ __nv_bfloat16 g_vh[SEQ_S * DLLM], g_vl2[SEQ_S * DLLM];
__device__ __nv_bfloat16 g_qsh[BL * DINNER],    g_qsl[BL * DINNER];
__device__ __nv_bfloat16 g_qlh[BL * DINNER],    g_qll[BL * DINNER];
__device__ __nv_bfloat16 g_ksh[SEQ_S * DINNER], g_ksl[SEQ_S * DINNER];
__device__ __nv_bfloat16 g_vsh[SEQ_S * DINNER], g_vsl[SEQ_S * DINNER];
__device__ __nv_bfloat16 g_klh[SEQ_S * DINNER], g_kll[SEQ_S * DINNER];
__device__ __nv_bfloat16 g_vlh[SEQ_S * DINNER], g_vll[SEQ_S * DINNER];
__device__ __nv_bfloat16 g_ah[BL * DINNER], g_al[BL * DINNER];
__device__ __nv_bfloat16 g_wqsh[DINNER * DMODEL], g_wqsl[DINNER * DMODEL];
__device__ __nv_bfloat16 g_wqlh[DINNER * DMODEL], g_wqll[DINNER * DMODEL];
__device__ __nv_bfloat16 g_wksh[DINNER * DLLM],   g_wksl[DINNER * DLLM];
__device__ __nv_bfloat16 g_wvsh[DINNER * DLLM],   g_wvsl[DINNER * DLLM];
__device__ __nv_bfloat16 g_wklh[DINNER * DLLM],   g_wkll[DINNER * DLLM];
__device__ __nv_bfloat16 g_wvlh[DINNER * DLLM],   g_wvll[DINNER * DLLM];
__device__ __nv_bfloat16 g_woh[DLLM * DINNER],    g_wol[DLLM * DINNER];

// ---------------------------------------------------------------------------
// Merged prepass (unchanged from R6)
// ---------------------------------------------------------------------------
struct PrepassParams {
    const float* W[7];
    __nv_bfloat16 *Th[7], *Tl[7];
    int K[7], N[7];
    int t_ofs[8];
    const float* X[3];
    __nv_bfloat16 *H[3], *L[3];
    int s_ofs[4];
    int total_trans;
};

__global__ __launch_bounds__(256)
void prepass(PrepassParams p)
{
    __shared__ float tsm[32][33];
    const int bid = blockIdx.x;
    if (bid < p.total_trans) {
        int w = 0;
        while (bid >= p.t_ofs[w + 1]) w++;
        const int t = bid - p.t_ofs[w];
        const int K = p.K[w], N = p.N[w];
        const int tiles_x = N >> 5;
        const int n0 = (t % tiles_x) << 5, k0 = (t / tiles_x) << 5;
        const float* __restrict__ W = p.W[w];
        __nv_bfloat16* __restrict__ Th = p.Th[w];
        __nv_bfloat16* __restrict__ Tl = p.Tl[w];
        const int tx = threadIdx.x & 31, ty = threadIdx.x >> 5;
#pragma unroll
        for (int i = 0; i < 32; i += 8)
            tsm[ty + i][tx] = W[(size_t)(k0 + ty + i) * N + n0 + tx];
        __syncthreads();
#pragma unroll
        for (int i = 0; i < 32; i += 8) {
            int n = n0 + ty + i;
            float v = tsm[tx][ty + i];
            __nv_bfloat16 h = __float2bfloat16(v);
            Th[(size_t)n * K + k0 + tx] = h;
            Tl[(size_t)n * K + k0 + tx] = __float2bfloat16(v - __bfloat162float(h));
        }
    } else {
        const int sb = bid - p.total_trans;
        int a = 0;
        while (sb >= p.s_ofs[a + 1]) a++;
        const int rel = sb - p.s_ofs[a];
        const float* __restrict__ X = p.X[a];
        __nv_bfloat16* __restrict__ H = p.H[a];
        __nv_bfloat16* __restrict__ L = p.L[a];
#pragma unroll
        for (int i = 0; i < 16; i++) {
            int idx = rel * 16384 + (i * 256 + threadIdx.x) * 4;
            float4 v = *(const float4*)(X + idx);
            uint32_t h01, l01, h23, l23;
            pack_split(v.x, v.y, h01, l01);
            pack_split(v.z, v.w, h23, l23);
            *(uint2*)(H + idx) = make_uint2(h01, h23);
            *(uint2*)(L + idx) = make_uint2(l01, l23);
        }
    }
}

// ---------------------------------------------------------------------------
// Paired projection GEMM: one CTA computes BOTH jobs of a pair sharing A.
// Tile 128(M) x 64(N) per job, BK=64, 8 warps (4m x 2n), 2-stage, 1 sync/chunk.
// Stage: A hi/lo 32KB + 2 jobs' B hi/lo 32KB = 64KB; x2 = 128KB smem.
// ---------------------------------------------------------------------------
struct PairJobs {
    const __nv_bfloat16 *Ah[3], *Al[3];
    const __nv_bfloat16 *Bh[3][2], *Bl[3][2];
    const float* bias[3][2];
    __nv_bfloat16 *Ch[3][2], *Cl[3][2];
    int M[3], K[3];
    int ofs[4];
};

#define P_AH  0
#define P_AL  16384
#define P_B0H 32768
#define P_B0L 40960
#define P_B1H 49152
#define P_B1L 57344
#define PSTG  65536
#define PAIR_SMEM (2 * PSTG)    // 128 KB

__global__ __launch_bounds__(256, 1)
void gemm_pair(PairJobs p)
{
    extern __shared__ __align__(1024) char smem[];
    const int bid = blockIdx.x;
    int z = 0;
    while (bid >= p.ofs[z + 1]) z++;
    const int rel = bid - p.ofs[z];
    const int bx = rel & 15, by = rel >> 4;    // gx = 16 for all pairs
    const int M = p.M[z], K = p.K[z];
    const int N = DINNER;

    const __nv_bfloat16* __restrict__ Ah  = p.Ah[z];
    const __nv_bfloat16* __restrict__ Al  = p.Al[z];
    const __nv_bfloat16* __restrict__ B0h = p.Bh[z][0];
    const __nv_bfloat16* __restrict__ B0l = p.Bl[z][0];
    const __nv_bfloat16* __restrict__ B1h = p.Bh[z][1];
    const __nv_bfloat16* __restrict__ B1l = p.Bl[z][1];

    const int tid = threadIdx.x;
    const int wid = tid >> 5, lid = tid & 31;
    const int wm = wid & 3, wn = wid >> 2;
    const int m0 = by * 128, n0 = bx * 64;
    const uint32_t sb = smem_u32(smem);

    float c[2][2][4][4];   // [job][mi][nj][q]
#pragma unroll
    for (int j = 0; j < 2; j++)
#pragma unroll
        for (int i = 0; i < 2; i++)
#pragma unroll
            for (int n = 0; n < 4; n++)
#pragma unroll
                for (int q = 0; q < 4; q++) c[j][i][n][q] = 0.f;

    const int NC = K >> 6;

    auto load_stage = [&](int cchunk) {
        const uint32_t st_ = sb + (cchunk & 1) * PSTG;
        const int k0_ = cchunk << 6;
#pragma unroll
        for (int i_ = 0; i_ < 4; i_++) {
            int idx_ = i_ * 256 + tid;
            int r_ = idx_ >> 3, u_ = idx_ & 7;
            uint32_t sw_ = SWZ((uint32_t)(r_ * 128 + u_ * 16));
            int gm_ = m0 + r_;
            if (gm_ < M) {
                CP_ASYNC16(st_ + P_AH + sw_, (const char*)(Ah + (size_t)gm_ * K + k0_) + u_ * 16);
                CP_ASYNC16(st_ + P_AL + sw_, (const char*)(Al + (size_t)gm_ * K + k0_) + u_ * 16);
            } else {
                STS_ZERO16(st_ + P_AH + sw_);
                STS_ZERO16(st_ + P_AL + sw_);
            }
        }
#pragma unroll
        for (int i_ = 0; i_ < 2; i_++) {
            int idx_ = i_ * 256 + tid;
            int r_ = idx_ >> 3, u_ = idx_ & 7;
            uint32_t sw_ = SWZ((uint32_t)(r_ * 128 + u_ * 16));
            int gn_ = n0 + r_;
            CP_ASYNC16(st_ + P_B0H + sw_, (const char*)(B0h + (size_t)gn_ * K + k0_) + u_ * 16);
            CP_ASYNC16(st_ + P_B0L + sw_, (const char*)(B0l + (size_t)gn_ * K + k0_) + u_ * 16);
            CP_ASYNC16(st_ + P_B1H + sw_, (const char*)(B1h + (size_t)gn_ * K + k0_) + u_ * 16);
            CP_ASYNC16(st_ + P_B1L + sw_, (const char*)(B1l + (size_t)gn_ * K + k0_) + u_ * 16);
        }
        CP_COMMIT();
    };

    load_stage(0);

    const int q8 = lid >> 3, lr = lid & 7;

    for (int cc = 0; cc < NC; cc++) {
        CP_WAIT0();                  // chunk cc resident (newest committed group)
        __syncthreads();             // visible to all; all warps done with cc-1
        if (cc + 1 < NC) { load_stage(cc + 1); } else { CP_COMMIT(); }

        const uint32_t st = sb + (cc & 1) * PSTG;
#pragma unroll
        for (int ks = 0; ks < 4; ks++) {
            const int kb = ks * 32;
            uint32_t ah[2][4], al[2][4];
#pragma unroll
            for (int mi = 0; mi < 2; mi++) {
                uint32_t off = SWZ((uint32_t)(
                    (wm * 32 + mi * 16 + lr + (q8 & 1) * 8) * 128 + kb + (q8 >> 1) * 16));
                ldsm4(ah[mi], st + P_AH + off);
                ldsm4(al[mi], st + P_AL + off);
            }
#pragma unroll
            for (int j = 0; j < 2; j++) {
                const uint32_t bhh = (j == 0) ? P_B0H : P_B1H;
                const uint32_t bll = (j == 0) ? P_B0L : P_B1L;
                uint32_t bh[4][2], bl[4][2];
#pragma unroll
                for (int njp = 0; njp < 2; njp++) {
                    uint32_t off = SWZ((uint32_t)(
                        (wn * 32 + njp * 16 + lr + (q8 >> 1) * 8) * 128 + kb + (q8 & 1) * 16));
                    uint32_t t0[4], t1[4];
                    ldsm4(t0, st + bhh + off);
                    ldsm4(t1, st + bll + off);
                    bh[2 * njp][0] = t0[0]; bh[2 * njp][1] = t0[1];
                    bh[2 * njp + 1][0] = t0[2]; bh[2 * njp + 1][1] = t0[3];
                    bl[2 * njp][0] = t1[0]; bl[2 * njp][1] = t1[1];
                    bl[2 * njp + 1][0] = t1[2]; bl[2 * njp + 1][1] = t1[3];
                }
#pragma unroll
                for (int mi = 0; mi < 2; mi++)
#pragma unroll
                    for (int nj = 0; nj < 4; nj++) {
                        mma16816(c[j][mi][nj], ah[mi], bh[nj][0], bh[nj][1]);
                        mma16816(c[j][mi][nj], ah[mi], bl[nj][0], bl[nj][1]);
                        mma16816(c[j][mi][nj], al[mi], bh[nj][0], bh[nj][1]);
                    }
            }
        }
    }

    const int lr4 = lid >> 2, lc = (lid & 3) * 2;
#pragma unroll
    for (int j = 0; j < 2; j++) {
        const float* __restrict__ bias = p.bias[z][j];
        __nv_bfloat16* Ch = p.Ch[z][j];
        __nv_bfloat16* Cl = p.Cl[z][j];
#pragma unroll
        for (int mi = 0; mi < 2; mi++) {
            int row = m0 + wm * 32 + mi * 16 + lr4;
#pragma unroll
            for (int nj = 0; nj < 4; nj++) {
                int col = n0 + wn * 32 + nj * 8 + lc;
                float2 b2 = *(const float2*)(bias + col);
                uint32_t h0, l0, h1, l1;
                pack_split(c[j][mi][nj][0] + b2.x, c[j][mi][nj][1] + b2.y, h0, l0);
                pack_split(c[j][mi][nj][2] + b2.x, c[j][mi][nj][3] + b2.y, h1, l1);
                if (row < M) {
                    *(uint32_t*)(Ch + (size_t)row * N + col) = h0;
                    *(uint32_t*)(Cl + (size_t)row * N + col) = l0;
                }
                if (row + 8 < M) {
                    *(uint32_t*)(Ch + (size_t)(row + 8) * N + col) = h1;
                    *(uint32_t*)(Cl + (size_t)(row + 8) * N + col) = l1;
                }
            }
        }
    }
}

// ---------------------------------------------------------------------------
// Output GEMM: C[8192,4096] = (Ah+Al)(Wh+Wl)^T + bias. Tile 128x128, BK=64,
// 3-stage pipeline (192KB smem), single sync per chunk. All dims exact.
// ---------------------------------------------------------------------------
#define O_AH 0
#define O_AL 16384
#define O_BH 32768
#define O_BL 49152
#define OSTG 65536
#define OUT_SMEM (3 * OSTG)   // 192 KB

__global__ __launch_bounds__(256, 1)
void gemm_out(const __nv_bfloat16* __restrict__ Ah, const __nv_bfloat16* __restrict__ Al,
              const __nv_bfloat16* __restrict__ Bh, const __nv_bfloat16* __restrict__ Bl,
              const float* __restrict__ bias, float* __restrict__ C)
{
    extern __shared__ __align__(1024) char smem[];
    const int tid = threadIdx.x;
    const int wid = tid >> 5, lid = tid & 31;
    const int wm = wid & 3, wn = wid >> 2;
    const int m0 = blockIdx.y * 128, n0 = blockIdx.x * 128;
    const uint32_t sb = smem_u32(smem);
    const int K = DINNER, N = DLLM;
    const int NC = K >> 6;   // 16

    float c[2][8][4];
#pragma unroll
    for (int i = 0; i < 2; i++)
#pragma unroll
        for (int j = 0; j < 8; j++)
#pragma unroll
            for (int q = 0; q < 4; q++) c[i][j][q] = 0.f;

    auto load_stage = [&](int cchunk) {
        const uint32_t st_ = sb + (cchunk % 3) * OSTG;
        const int k0_ = cchunk << 6;
#pragma unroll
        for (int i_ = 0; i_ < 4; i_++) {
            int idx_ = i_ * 256 + tid;
            int r_ = idx_ >> 3, u_ = idx_ & 7;
            uint32_t sw_ = SWZ((uint32_t)(r_ * 128 + u_ * 16));
            CP_ASYNC16(st_ + O_AH + sw_, (const char*)(Ah + (size_t)(m0 + r_) * K + k0_) + u_ * 16);
            CP_ASYNC16(st_ + O_AL + sw_, (const char*)(Al + (size_t)(m0 + r_) * K + k0_) + u_ * 16);
            CP_ASYNC16(st_ + O_BH + sw_, (const char*)(Bh + (size_t)(n0 + r_) * K + k0_) + u_ * 16);
            CP_ASYNC16(st_ + O_BL + sw_, (const char*)(Bl + (size_t)(n0 + r_) * K + k0_) + u_ * 16);
        }
        CP_COMMIT();
    };

    load_stage(0);
    load_stage(1);

    const int q8 = lid >> 3, lr = lid & 7;

    for (int cc = 0; cc < NC; cc++) {
        CP_WAIT1();                  // chunk cc done (cc+1 may be in flight)
        __syncthreads();
        if (cc + 2 < NC) { load_stage(cc + 2); } else { CP_COMMIT(); }

        const uint32_t st = sb + (cc % 3) * OSTG;
#pragma unroll
        for (int ks = 0; ks < 4; ks++) {
            const int kb = ks * 32;
            uint32_t ah[2][4], al[2][4], bh[8][2], bl[8][2];
#pragma unroll
            for (int mi = 0; mi < 2; mi++) {
                uint32_t off = SWZ((uint32_t)(
                    (wm * 32 + mi * 16 + lr + (q8 & 1) * 8) * 128 + kb + (q8 >> 1) * 16));
                ldsm4(ah[mi], st + O_AH + off);
                ldsm4(al[mi], st + O_AL + off);
            }
#pragma unroll
            for (int njp = 0; njp < 4; njp++) {
                uint32_t off = SWZ((uint32_t)(
                    (wn * 64 + njp * 16 + lr + (q8 >> 1) * 8) * 128 + kb + (q8 & 1) * 16));
                uint32_t t0[4], t1[4];
                ldsm4(t0, st + O_BH + off);
                ldsm4(t1, st + O_BL + off);
                bh[2 * njp][0] = t0[0]; bh[2 * njp][1] = t0[1];
                bh[2 * njp + 1][0] = t0[2]; bh[2 * njp + 1][1] = t0[3];
                bl[2 * njp][0] = t1[0]; bl[2 * njp][1] = t1[1];
                bl[2 * njp + 1][0] = t1[2]; bl[2 * njp + 1][1] = t1[3];
            }
#pragma unroll
            for (int mi = 0; mi < 2; mi++)
#pragma unroll
                for (int nj = 0; nj < 8; nj++) {
                    mma16816(c[mi][nj], ah[mi], bh[nj][0], bh[nj][1]);
                    mma16816(c[mi][nj], ah[mi], bl[nj][0], bl[nj][1]);
                    mma16816(c[mi][nj], al[mi], bh[nj][0], bh[nj][1]);
                }
        }
    }

    const int lr4 = lid >> 2, lc = (lid & 3) * 2;
#pragma unroll
    for (int mi = 0; mi < 2; mi++) {
        int row = m0 + wm * 32 + mi * 16 + lr4;
#pragma unroll
        for (int nj = 0; nj < 8; nj++) {
            int col = n0 + wn * 64 + nj * 8 + lc;
            float2 b2 = *(const float2*)(bias + col);
            *(float2*)(C + (size_t)row * N + col) =
                make_float2(c[mi][nj][0] + b2.x, c[mi][nj][1] + b2.y);
            *(float2*)(C + (size_t)(row + 8) * N + col) =
                make_float2(c[mi][nj][2] + b2.x, c[mi][nj][3] + b2.y);
        }
    }
}

// ---------------------------------------------------------------------------
// HMMA flash attention, dual-stream, bf16 split-2 — now 3-stage, 1 sync/chunk.
// ---------------------------------------------------------------------------
struct AttnParams {
    const __nv_bfloat16 *qh[2], *ql[2], *kh[2], *kl[2], *vh[2], *vl[2];
    const float *alpha, *beta;
    __nv_bfloat16 *oh, *ol;
};

#define ATT_STAGE 32768
#define A_KH 0
#define A_KL 8192
#define A_VH 16384
#define A_VL 24576
#define ATT_SMEM (3 * ATT_STAGE)   // 96 KB
#define NCH 16
#define SOFTMAX_SCALE 0.125f

__global__ __launch_bounds__(128)
void attn_mma(AttnParams p)
{
    extern __shared__ __align__(1024) char smem[];
    const uint32_t sb = smem_u32(smem);
    const int tid = threadIdx.x;
    const int w = tid >> 5, lid = tid & 31;
    const int q8 = lid >> 3, lr = lid & 7;
    const int h = blockIdx.y;
    const int qbase = blockIdx.x * 64;
    const int colbase = h * EDIM;

    const float alpha = *p.alpha;
    const float beta  = *p.beta;

    float osave[8][4];

    for (int st = 0; st < 2; st++) {
        const __nv_bfloat16* __restrict__ qhp = p.qh[st];
        const __nv_bfloat16* __restrict__ qlp = p.ql[st];
        const __nv_bfloat16* __restrict__ khp = p.kh[st];
        const __nv_bfloat16* __restrict__ klp = p.kl[st];
        const __nv_bfloat16* __restrict__ vhp = p.vh[st];
        const __nv_bfloat16* __restrict__ vlp = p.vl[st];

        // ---- stage Q (64x64 hi/lo) into stage-2 K area ----
        const uint32_t qst = sb + 2 * ATT_STAGE;
#pragma unroll
        for (int i = 0; i < 4; i++) {
            int idx = i * 128 + tid;
            int r = idx >> 3, u = idx & 7;
            uint32_t sw = SWZ((uint32_t)(r * 128 + u * 16));
            CP_ASYNC16(qst + A_KH + sw,
                       (const char*)(qhp + (size_t)(qbase + r) * DINNER + colbase) + u * 16);
            CP_ASYNC16(qst + A_KL + sw,
                       (const char*)(qlp + (size_t)(qbase + r) * DINNER + colbase) + u * 16);
        }
        CP_COMMIT();
        CP_WAIT0();
        __syncthreads();

        uint32_t qfh[4][4], qfl[4][4];
#pragma unroll
        for (int ks = 0; ks < 4; ks++) {
            uint32_t off = SWZ((uint32_t)(
                (w * 16 + lr + (q8 & 1) * 8) * 128 + ks * 32 + (q8 >> 1) * 16));
            ldsm4(qfh[ks], qst + A_KH + off);
            ldsm4(qfl[ks], qst + A_KL + off);
        }

        float o[8][4];
#pragma unroll
        for (int t = 0; t < 8; t++)
#pragma unroll
            for (int i = 0; i < 4; i++) o[t][i] = 0.f;
        float m0r = -INFINITY, m1r = -INFINITY;
        float l0 = 0.f, l1 = 0.f;

#define LOAD_KV(cchunk) do { \
            const uint32_t stg_ = sb + ((cchunk) % 3) * ATT_STAGE; \
            const int s0_ = (cchunk) * 64; \
            _Pragma("unroll") \
            for (int i_ = 0; i_ < 4; i_++) { \
                int idx_ = i_ * 128 + tid; \
                int r_ = idx_ >> 3, u_ = idx_ & 7; \
                uint32_t sw_ = SWZ((uint32_t)(r_ * 128 + u_ * 16)); \
                if (s0_ + r_ < SEQ_S) { \
                    const size_t go_ = (size_t)(s0_ + r_) * DINNER + colbase; \
                    CP_ASYNC16(stg_ + A_KH + sw_, (const char*)(khp + go_) + u_ * 16); \
                    CP_ASYNC16(stg_ + A_KL + sw_, (const char*)(klp + go_) + u_ * 16); \
                    CP_ASYNC16(stg_ + A_VH + sw_, (const char*)(vhp + go_) + u_ * 16); \
                    CP_ASYNC16(stg_ + A_VL + sw_, (const char*)(vlp + go_) + u_ * 16); \
                } else { \
                    STS_ZERO16(stg_ + A_KH + sw_); \
                    STS_ZERO16(stg_ + A_KL + sw_); \
                    STS_ZERO16(stg_ + A_VH + sw_); \
                    STS_ZERO16(stg_ + A_VL + sw_); \
                } \
            } \
            CP_COMMIT(); \
        } while (0)

        LOAD_KV(0);
        LOAD_KV(1);

        for (int cc = 0; cc < NCH; cc++) {
            CP_WAIT1();              // chunk cc done
            __syncthreads();         // visible everywhere; all warps past cc-1
            if (cc + 2 < NCH) { LOAD_KV(cc + 2); } else { CP_COMMIT(); }
            const uint32_t stg = sb + (cc % 3) * ATT_STAGE;

            float s[8][4];
#pragma unroll
            for (int t = 0; t < 8; t++)
#pragma unroll
                for (int i = 0; i < 4; i++) s[t][i] = 0.f;

#pragma unroll
            for (int ks = 0; ks < 4; ks++) {
                uint32_t bh[8][2], bl[8][2];
#pragma unroll
                for (int njp = 0; njp < 4; njp++) {
                    uint32_t off = SWZ((uint32_t)(
                        (njp * 16 + lr + (q8 >> 1) * 8) * 128 + ks * 32 + (q8 & 1) * 16));
                    uint32_t t0[4], t1[4];
                    ldsm4(t0, stg + A_KH + off);
                    ldsm4(t1, stg + A_KL + off);
                    bh[2 * njp][0] = t0[0]; bh[2 * njp][1] = t0[1];
                    bh[2 * njp + 1][0] = t0[2]; bh[2 * njp + 1][1] = t0[3];
                    bl[2 * njp][0] = t1[0]; bl[2 * njp][1] = t1[1];
                    bl[2 * njp + 1][0] = t1[2]; bl[2 * njp + 1][1] = t1[3];
                }
#pragma unroll
                for (int t = 0; t < 8; t++) {
                    mma16816(s[t], qfh[ks], bh[t][0], bh[t][1]);
                    mma16816(s[t], qfh[ks], bl[t][0], bl[t][1]);
                    mma16816(s[t], qfl[ks], bh[t][0], bh[t][1]);
                }
            }

            if (cc == NCH - 1) {
#pragma unroll
                for (int t = 5; t < 8; t++)
#pragma unroll
                    for (int i = 0; i < 4; i++) s[t][i] = -1e30f;
            }

            float ml0 = -1e30f, ml1 = -1e30f;
#pragma unroll
            for (int t = 0; t < 8; t++) {
                ml0 = fmaxf(ml0, fmaxf(s[t][0], s[t][1]));
                ml1 = fmaxf(ml1, fmaxf(s[t][2], s[t][3]));
            }
            ml0 = fmaxf(ml0, __shfl_xor_sync(0xffffffffu, ml0, 1));
            ml0 = fmaxf(ml0, __shfl_xor_sync(0xffffffffu, ml0, 2));
            ml1 = fmaxf(ml1, __shfl_xor_sync(0xffffffffu, ml1, 1));
            ml1 = fmaxf(ml1, __shfl_xor_sync(0xffffffffu, ml1, 2));

            float mn0 = fmaxf(m0r, ml0), mn1 = fmaxf(m1r, ml1);
            float c0 = __expf((m0r - mn0) * SOFTMAX_SCALE);
            float c1 = __expf((m1r - mn1) * SOFTMAX_SCALE);
            m0r = mn0; m1r = mn1;
            l0 *= c0; l1 *= c1;
#pragma unroll
            for (int t = 0; t < 8; t++) {
                o[t][0] *= c0; o[t][1] *= c0;
                o[t][2] *= c1; o[t][3] *= c1;
            }
#pragma unroll
            for (int t = 0; t < 8; t++) {
                float p0 = __expf((s[t][0] - mn0) * SOFTMAX_SCALE);
                float p1 = __expf((s[t][1] - mn0) * SOFTMAX_SCALE);
                float p2 = __expf((s[t][2] - mn1) * SOFTMAX_SCALE);
                float p3 = __expf((s[t][3] - mn1) * SOFTMAX_SCALE);
                l0 += p0 + p1; l1 += p2 + p3;
                s[t][0] = p0; s[t][1] = p1; s[t][2] = p2; s[t][3] = p3;
            }

#pragma unroll
            for (int ks = 0; ks < 4; ks++) {
                uint32_t pah[4], pal[4];
                pack_split(s[2 * ks][0],     s[2 * ks][1],     pah[0], pal[0]);
                pack_split(s[2 * ks][2],     s[2 * ks][3],     pah[1], pal[1]);
                pack_split(s[2 * ks + 1][0], s[2 * ks + 1][1], pah[2], pal[2]);
                pack_split(s[2 * ks + 1][2], s[2 * ks + 1][3], pah[3], pal[3]);
#pragma unroll
                for (int ep = 0; ep < 4; ep++) {
                    uint32_t off = SWZ((uint32_t)(
                        (ks * 16 + lr + (q8 & 1) * 8) * 128 + ep * 32 + (q8 >> 1) * 16));
                    uint32_t tv0[4], tv1[4];
                    ldsm4t(tv0, stg + A_VH + off);
                    ldsm4t(tv1, stg + A_VL + off);
                    mma16816(o[2 * ep],     pah, tv0[0], tv0[1]);
                    mma16816(o[2 * ep],     pah, tv1[0], tv1[1]);
                    mma16816(o[2 * ep],     pal, tv0[0], tv0[1]);
                    mma16816(o[2 * ep + 1], pah, tv0[2], tv0[3]);
                    mma16816(o[2 * ep + 1], pah, tv1[2], tv1[3]);
                    mma16816(o[2 * ep + 1], pal, tv0[2], tv0[3]);
                }
            }
        }

        l0 += __shfl_xor_sync(0xffffffffu, l0, 1);
        l0 += __shfl_xor_sync(0xffffffffu, l0, 2);
        l1 += __shfl_xor_sync(0xffffffffu, l1, 1);
        l1 += __shfl_xor_sync(0xffffffffu, l1, 2);
        float wgt = (st == 0) ? alpha : beta;
        float f0 = wgt / l0, f1 = wgt / l1;
        if (st == 0) {
#pragma unroll
            for (int t = 0; t < 8; t++) {
                osave[t][0] = o[t][0] * f0; osave[t][1] = o[t][1] * f0;
                osave[t][2] = o[t][2] * f1; osave[t][3] = o[t][3] * f1;
            }
        } else {
#pragma unroll
            for (int t = 0; t < 8; t++) {
                osave[t][0] += o[t][0] * f0; osave[t][1] += o[t][1] * f0;
                osave[t][2] += o[t][2] * f1; osave[t][3] += o[t][3] * f1;
            }
        }
        __syncthreads();   // all warps done with smem before next stream
    }

    const int r0 = qbase + w * 16 + (lid >> 2);
#pragma unroll
    for (int t = 0; t < 8; t++) {
        int col = colbase + t * 8 + (lid & 3) * 2;
        uint32_t h0, lo0, h1, lo1;
        pack_split(osave[t][0], osave[t][1], h0, lo0);
        pack_split(osave[t][2], osave[t][3], h1, lo1);
        *(uint32_t*)(p.oh + (size_t)r0 * DINNER + col) = h0;
        *(uint32_t*)(p.ol + (size_t)r0 * DINNER + col) = lo0;
        *(uint32_t*)(p.oh + (size_t)(r0 + 8) * DINNER + col) = h1;
        *(uint32_t*)(p.ol + (size_t)(r0 + 8) * DINNER + col) = lo1;
    }
}

// ---------------------------------------------------------------------------
// Launch
// ---------------------------------------------------------------------------
extern "C" void kernel_launch(void* const* d_in, const int* in_sizes, int n_in,
                              void* d_out, int out_size)
{
    const float* target = (const float*)d_in[0];
    const float* source = (const float*)d_in[1];
    const float* value  = (const float*)d_in[2];
    const float* Wq_s = (const float*)d_in[3];  const float* bq_s = (const float*)d_in[4];
    const float* Wk_s = (const float*)d_in[5];  const float* bk_s = (const float*)d_in[6];
    const float* Wv_s = (const float*)d_in[7];  const float* bv_s = (const float*)d_in[8];
    const float* Wq_l = (const float*)d_in[9];  const float* bq_l = (const float*)d_in[10];
    const float* Wk_l = (const float*)d_in[11]; const float* bk_l = (const float*)d_in[12];
    const float* Wv_l = (const float*)d_in[13]; const float* bv_l = (const float*)d_in[14];
    const float* Wo   = (const float*)d_in[15]; const float* bo   = (const float*)d_in[16];
    const float* alpha = (const float*)d_in[17];
    const float* beta  = (const float*)d_in[18];
    float* out = (float*)d_out;

    __nv_bfloat16 *th, *tl, *sh, *sl, *vh, *vl2, *ah, *al;
    cudaGetSymbolAddress((void**)&th,  g_th);  cudaGetSymbolAddress((void**)&tl,  g_tl);
    cudaGetSymbolAddress((void**)&sh,  g_sh);  cudaGetSymbolAddress((void**)&sl,  g_sl);
    cudaGetSymbolAddress((void**)&vh,  g_vh);  cudaGetSymbolAddress((void**)&vl2, g_vl2);
    cudaGetSymbolAddress((void**)&ah,  g_ah);  cudaGetSymbolAddress((void**)&al,  g_al);

    __nv_bfloat16 *qsh, *qsl, *qlh, *qll, *ksh, *ksl, *vsh, *vsl, *klh, *kll, *vlh, *vll;
    cudaGetSymbolAddress((void**)&qsh, g_qsh); cudaGetSymbolAddress((void**)&qsl, g_qsl);
    cudaGetSymbolAddress((void**)&qlh, g_qlh); cudaGetSymbolAddress((void**)&qll, g_qll);
    cudaGetSymbolAddress((void**)&ksh, g_ksh); cudaGetSymbolAddress((void**)&ksl, g_ksl);
    cudaGetSymbolAddress((void**)&vsh, g_vsh); cudaGetSymbolAddress((void**)&vsl, g_vsl);
    cudaGetSymbolAddress((void**)&klh, g_klh); cudaGetSymbolAddress((void**)&kll, g_kll);
    cudaGetSymbolAddress((void**)&vlh, g_vlh); cudaGetSymbolAddress((void**)&vll, g_vll);

    __nv_bfloat16 *wqsh, *wqsl, *wqlh, *wqll, *wksh, *wksl, *wvsh, *wvsl;
    __nv_bfloat16 *wklh, *wkll, *wvlh, *wvll, *woh, *wol;
    cudaGetSymbolAddress((void**)&wqsh, g_wqsh); cudaGetSymbolAddress((void**)&wqsl, g_wqsl);
    cudaGetSymbolAddress((void**)&wqlh, g_wqlh); cudaGetSymbolAddress((void**)&wqll, g_wqll);
    cudaGetSymbolAddress((void**)&wksh, g_wksh); cudaGetSymbolAddress((void**)&wksl, g_wksl);
    cudaGetSymbolAddress((void**)&wvsh, g_wvsh); cudaGetSymbolAddress((void**)&wvsl, g_wvsl);
    cudaGetSymbolAddress((void**)&wklh, g_wklh); cudaGetSymbolAddress((void**)&wkll, g_wkll);
    cudaGetSymbolAddress((void**)&wvlh, g_wvlh); cudaGetSymbolAddress((void**)&wvll, g_wvll);
    cudaGetSymbolAddress((void**)&woh,  g_woh);  cudaGetSymbolAddress((void**)&wol,  g_wol);

    cudaFuncSetAttribute(gemm_pair, cudaFuncAttributeMaxDynamicSharedMemorySize, PAIR_SMEM);
    cudaFuncSetAttribute(gemm_out,  cudaFuncAttributeMaxDynamicSharedMemorySize, OUT_SMEM);
    cudaFuncSetAttribute(attn_mma,  cudaFuncAttributeMaxDynamicSharedMemorySize, ATT_SMEM);

    // --- merged prepass ---
    {
        PrepassParams pp = {};
        const float* Ws[7]   = {Wq_s, Wq_l, Wk_s, Wv_s, Wk_l, Wv_l, Wo};
        __nv_bfloat16* Ths[7] = {wqsh, wqlh, wksh, wvsh, wklh, wvlh, woh};
        __nv_bfloat16* Tls[7] = {wqsl, wqll, wksl, wvsl, wkll, wvll, wol};
        const int Ks[7] = {DMODEL, DMODEL, DLLM, DLLM, DLLM, DLLM, DINNER};
        const int Ns[7] = {DINNER, DINNER, DINNER, DINNER, DINNER, DINNER, DLLM};
        int acc = 0;
        pp.t_ofs[0] = 0;
        for (int i = 0; i < 7; i++) {
            pp.W[i] = Ws[i]; pp.Th[i] = Ths[i]; pp.Tl[i] = Tls[i];
            pp.K[i] = Ks[i]; pp.N[i] = Ns[i];
            acc += (Ks[i] / 32) * (Ns[i] / 32);
            pp.t_ofs[i + 1] = acc;
        }
        pp.total_trans = acc;
        pp.X[0] = target; pp.H[0] = th; pp.L[0] = tl;
        pp.X[1] = source; pp.H[1] = sh; pp.L[1] = sl;
        pp.X[2] = value;  pp.H[2] = vh; pp.L[2] = vl2;
        pp.s_ofs[0] = 0;
        pp.s_ofs[1] = (BL * DMODEL) / 16384;
        pp.s_ofs[2] = pp.s_ofs[1] + (SEQ_S * DLLM) / 16384;
        pp.s_ofs[3] = pp.s_ofs[2] + (SEQ_S * DLLM) / 16384;
        prepass<<<pp.total_trans + pp.s_ofs[3], 256>>>(pp);
    }

    // --- all 6 projections as 3 A-sharing pairs, ONE launch ---
    {
        PairJobs p = {};
        // pair 0: target -> {Wq_s, Wq_l}
        p.Ah[0] = th; p.Al[0] = tl;
        p.Bh[0][0] = wqsh; p.Bl[0][0] = wqsl; p.bias[0][0] = bq_s;
        p.Ch[0][0] = qsh;  p.Cl[0][0] = qsl;
        p.Bh[0][1] = wqlh; p.Bl[0][1] = wqll; p.bias[0][1] = bq_l;
        p.Ch[0][1] = qlh;  p.Cl[0][1] = qll;
        p.M[0] = BL; p.K[0] = DMODEL;
        // pair 1: source -> {Wk_s, Wk_l}
        p.Ah[1] = sh; p.Al[1] = sl;
        p.Bh[1][0] = wksh; p.Bl[1][0] = wksl; p.bias[1][0] = bk_s;
        p.Ch[1][0] = ksh;  p.Cl[1][0] = ksl;
        p.Bh[1][1] = wklh; p.Bl[1][1] = wkll; p.bias[1][1] = bk_l;
        p.Ch[1][1] = klh;  p.Cl[1][1] = kll;
        p.M[1] = SEQ_S; p.K[1] = DLLM;
        // pair 2: value -> {Wv_s, Wv_l}
        p.Ah[2] = vh; p.Al[2] = vl2;
        p.Bh[2][0] = wvsh; p.Bl[2][0] = wvsl; p.bias[2][0] = bv_s;
        p.Ch[2][0] = vsh;  p.Cl[2][0] = vsl;
        p.Bh[2][1] = wvlh; p.Bl[2][1] = wvll; p.bias[2][1] = bv_l;
        p.Ch[2][1] = vlh;  p.Cl[2][1] = vll;
        p.M[2] = SEQ_S; p.K[2] = DLLM;

        p.ofs[0] = 0;
        p.ofs[1] = 16 * (BL / 128);                       // 1024
        p.ofs[2] = p.ofs[1] + 16 * ((SEQ_S + 127) / 128); // +128
        p.ofs[3] = p.ofs[2] + 16 * ((SEQ_S + 127) / 128); // +128
        gemm_pair<<<p.ofs[3], 256, PAIR_SMEM>>>(p);       // 1280 blocks
    }

    // --- fused dual-stream flash attention ---
    {
        AttnParams ap = {};
        ap.qh[0] = qsh; ap.ql[0] = qsl; ap.kh[0] = ksh; ap.kl[0] = ksl;
        ap.vh[0] = vsh; ap.vl[0] = vsl;
        ap.qh[1] = qlh; ap.ql[1] = qll; ap.kh[1] = klh; ap.kl[1] = kll;
        ap.vh[1] = vlh; ap.vl[1] = vll;
        ap.alpha = alpha; ap.beta = beta;
        ap.oh = ah; ap.ol = al;
        dim3 g(BL / 64, NHEAD);
        attn_mma<<<g, 128, ATT_SMEM>>>(ap);
    }

    // --- output projection ---
    {
        dim3 g(DLLM / 128, BL / 128);                     // (32, 64)
        gemm_out<<<g, 256, OUT_SMEM>>>(ah, al, woh, wol, bo, out);
    }
}

// round 8
// speedup vs baseline: 1.0110x; 1.0110x over previous
#include <cuda_runtime.h>
#include <cuda_bf16.h>
#include <math.h>
#include <stdint.h>

#define BL     8192
#define DMODEL 1024
#define DLLM   4096
#define DINNER 1024
#define SEQ_S  1000
#define NHEAD  16
#define EDIM   64

// ---------------------------------------------------------------------------
// Portable PTX helpers (base compute_103 target — NO tcgen05)
// ---------------------------------------------------------------------------
__device__ __forceinline__ uint32_t smem_u32(const void* p) {
    uint32_t a;
    asm("{ .reg .u64 t; cvta.to.shared.u64 t, %1; cvt.u32.u64 %0, t; }"
        : "=r"(a) : "l"(p));
    return a;
}

#define SWZ(o) ((o) ^ (((o) >> 3) & 0x70))

#define CP_ASYNC16(dst, src) \
    asm volatile("cp.async.cg.shared.global [%0], [%1], 16;\n" :: "r"(dst), "l"(src))
#define CP_COMMIT() asm volatile("cp.async.commit_group;\n" ::: "memory")
#define CP_WAIT1()  asm volatile("cp.async.wait_group 1;\n" ::: "memory")
#define CP_WAIT0()  asm volatile("cp.async.wait_group 0;\n" ::: "memory")
#define STS_ZERO16(addr) \
    asm volatile("st.shared.v4.b32 [%0], {%1,%1,%1,%1};\n" :: "r"(addr), "r"(0u) : "memory")

__device__ __forceinline__ void ldsm4(uint32_t* r, uint32_t a) {
    asm volatile("ldmatrix.sync.aligned.m8n8.x4.shared.b16 {%0,%1,%2,%3}, [%4];\n"
        : "=r"(r[0]), "=r"(r[1]), "=r"(r[2]), "=r"(r[3]) : "r"(a));
}
__device__ __forceinline__ void ldsm4t(uint32_t* r, uint32_t a) {
    asm volatile("ldmatrix.sync.aligned.m8n8.x4.trans.shared.b16 {%0,%1,%2,%3}, [%4];\n"
        : "=r"(r[0]), "=r"(r[1]), "=r"(r[2]), "=r"(r[3]) : "r"(a));
}
__device__ __forceinline__ void mma16816(float* c, const uint32_t* a,
                                         uint32_t b0, uint32_t b1) {
    asm volatile(
        "mma.sync.aligned.m16n8k16.row.col.f32.bf16.bf16.f32 "
        "{%0,%1,%2,%3}, {%4,%5,%6,%7}, {%8,%9}, {%0,%1,%2,%3};\n"
        : "+f"(c[0]), "+f"(c[1]), "+f"(c[2]), "+f"(c[3])
        : "r"(a[0]), "r"(a[1]), "r"(a[2]), "r"(a[3]), "r"(b0), "r"(b1));
}

__device__ __forceinline__ void pack_split(float a, float b, uint32_t& hi, uint32_t& lo) {
    __nv_bfloat162 h = __floats2bfloat162_rn(a, b);
    float ra = a - __bfloat162float(h.x);
    float rb = b - __bfloat162float(h.y);
    __nv_bfloat162 l = __floats2bfloat162_rn(ra, rb);
    hi = *reinterpret_cast<uint32_t*>(&h);
    lo = *reinterpret_cast<uint32_t*>(&l);
}

// ---------------------------------------------------------------------------
// Scratch (device globals — no allocation allowed)
// ---------------------------------------------------------------------------
__device__ __nv_bfloat16 g_th[BL * DMODEL],  g_tl[BL * DMODEL];
__device__ __nv_bfloat16 g_sh[SEQ_S * DLLM], g_sl[SEQ_S * DLLM];
__device__ __nv_bfloat16 g_vh[SEQ_S * DLLM], g_vl2[SEQ_S * DLLM];
__device__ __nv_bfloat16 g_qsh[BL * DINNER],    g_qsl[BL * DINNER];
__device__ __nv_bfloat16 g_qlh[BL * DINNER],    g_qll[BL * DINNER];
__device__ __nv_bfloat16 g_ksh[SEQ_S * DINNER], g_ksl[SEQ_S * DINNER];
__device__ __nv_bfloat16 g_vsh[SEQ_S * DINNER], g_vsl[SEQ_S * DINNER];
__device__ __nv_bfloat16 g_klh[SEQ_S * DINNER], g_kll[SEQ_S * DINNER];
__device__ __nv_bfloat16 g_vlh[SEQ_S * DINNER], g_vll[SEQ_S * DINNER];
__device__ __nv_bfloat16 g_ah[BL * DINNER], g_al[BL * DINNER];
__device__ __nv_bfloat16 g_wqsh[DINNER * DMODEL], g_wqsl[DINNER * DMODEL];
__device__ __nv_bfloat16 g_wqlh[DINNER * DMODEL], g_wqll[DINNER * DMODEL];
__device__ __nv_bfloat16 g_wksh[DINNER * DLLM],   g_wksl[DINNER * DLLM];
__device__ __nv_bfloat16 g_wvsh[DINNER * DLLM],   g_wvsl[DINNER * DLLM];
__device__ __nv_bfloat16 g_wklh[DINNER * DLLM],   g_wkll[DINNER * DLLM];
__device__ __nv_bfloat16 g_wvlh[DINNER * DLLM],   g_wvll[DINNER * DLLM];
__device__ __nv_bfloat16 g_woh[DLLM * DINNER],    g_wol[DLLM * DINNER];

// ---------------------------------------------------------------------------
// Merged prepass (unchanged)
// ---------------------------------------------------------------------------
struct PrepassParams {
    const float* W[7];
    __nv_bfloat16 *Th[7], *Tl[7];
    int K[7], N[7];
    int t_ofs[8];
    const float* X[3];
    __nv_bfloat16 *H[3], *L[3];
    int s_ofs[4];
    int total_trans;
};

__global__ __launch_bounds__(256)
void prepass(PrepassParams p)
{
    __shared__ float tsm[32][33];
    const int bid = blockIdx.x;
    if (bid < p.total_trans) {
        int w = 0;
        while (bid >= p.t_ofs[w + 1]) w++;
        const int t = bid - p.t_ofs[w];
        const int K = p.K[w], N = p.N[w];
        const int tiles_x = N >> 5;
        const int n0 = (t % tiles_x) << 5, k0 = (t / tiles_x) << 5;
        const float* __restrict__ W = p.W[w];
        __nv_bfloat16* __restrict__ Th = p.Th[w];
        __nv_bfloat16* __restrict__ Tl = p.Tl[w];
        const int tx = threadIdx.x & 31, ty = threadIdx.x >> 5;
#pragma unroll
        for (int i = 0; i < 32; i += 8)
            tsm[ty + i][tx] = W[(size_t)(k0 + ty + i) * N + n0 + tx];
        __syncthreads();
#pragma unroll
        for (int i = 0; i < 32; i += 8) {
            int n = n0 + ty + i;
            float v = tsm[tx][ty + i];
            __nv_bfloat16 h = __float2bfloat16(v);
            Th[(size_t)n * K + k0 + tx] = h;
            Tl[(size_t)n * K + k0 + tx] = __float2bfloat16(v - __bfloat162float(h));
        }
    } else {
        const int sb = bid - p.total_trans;
        int a = 0;
        while (sb >= p.s_ofs[a + 1]) a++;
        const int rel = sb - p.s_ofs[a];
        const float* __restrict__ X = p.X[a];
        __nv_bfloat16* __restrict__ H = p.H[a];
        __nv_bfloat16* __restrict__ L = p.L[a];
#pragma unroll
        for (int i = 0; i < 16; i++) {
            int idx = rel * 16384 + (i * 256 + threadIdx.x) * 4;
            float4 v = *(const float4*)(X + idx);
            uint32_t h01, l01, h23, l23;
            pack_split(v.x, v.y, h01, l01);
            pack_split(v.z, v.w, h23, l23);
            *(uint2*)(H + idx) = make_uint2(h01, h23);
            *(uint2*)(L + idx) = make_uint2(l01, l23);
        }
    }
}

// ---------------------------------------------------------------------------
// Projection GEMM (R6 config, proven best): tile 128x64, BK=64, 8 warps,
// 2-stage, 96KB smem -> 2 CTAs/SM. Now SINGLE sync per chunk.
// Flat 1D grid over 6 jobs, bf16-split epilogue.
// ---------------------------------------------------------------------------
struct GemmJobs {
    const __nv_bfloat16 *Ah[6], *Al[6], *Bh[6], *Bl[6];
    const float* bias[6];
    __nv_bfloat16 *Ch[6], *Cl[6];
    int M[6], K[6];
    int ofs[7];
};

#define G_AH 0
#define G_AL 16384
#define G_BH 32768
#define G_BL 40960
#define GSTG 49152
#define PROJ_SMEM (2 * GSTG)    // 96 KB

__global__ __launch_bounds__(256, 2)
void gemm_proj(GemmJobs p)
{
    extern __shared__ __align__(1024) char smem[];
    const int bid = blockIdx.x;
    int z = 0;
    while (bid >= p.ofs[z + 1]) z++;
    const int rel = bid - p.ofs[z];
    const int bx = rel & 15, by = rel >> 4;      // gx = 16 (N=1024/64)
    const int M = p.M[z], K = p.K[z];
    const int N = DINNER;

    const __nv_bfloat16* __restrict__ Ah = p.Ah[z];
    const __nv_bfloat16* __restrict__ Al = p.Al[z];
    const __nv_bfloat16* __restrict__ Bh = p.Bh[z];
    const __nv_bfloat16* __restrict__ Bl = p.Bl[z];

    const int tid = threadIdx.x;
    const int wid = tid >> 5, lid = tid & 31;
    const int wm = wid & 3, wn = wid >> 2;
    const int m0 = by * 128, n0 = bx * 64;
    const uint32_t sb = smem_u32(smem);

    float c[2][4][4];
#pragma unroll
    for (int i = 0; i < 2; i++)
#pragma unroll
        for (int j = 0; j < 4; j++)
#pragma unroll
            for (int q = 0; q < 4; q++) c[i][j][q] = 0.f;

    const int NC = K >> 6;

    auto load_stage = [&](int cchunk) {
        const uint32_t st_ = sb + (cchunk & 1) * GSTG;
        const int k0_ = cchunk << 6;
#pragma unroll
        for (int i_ = 0; i_ < 4; i_++) {
            int idx_ = i_ * 256 + tid;
            int r_ = idx_ >> 3, u_ = idx_ & 7;
            uint32_t sw_ = SWZ((uint32_t)(r_ * 128 + u_ * 16));
            int gm_ = m0 + r_;
            if (gm_ < M) {
                CP_ASYNC16(st_ + G_AH + sw_, (const char*)(Ah + (size_t)gm_ * K + k0_) + u_ * 16);
                CP_ASYNC16(st_ + G_AL + sw_, (const char*)(Al + (size_t)gm_ * K + k0_) + u_ * 16);
            } else {
                STS_ZERO16(st_ + G_AH + sw_);
                STS_ZERO16(st_ + G_AL + sw_);
            }
        }
#pragma unroll
        for (int i_ = 0; i_ < 2; i_++) {
            int idx_ = i_ * 256 + tid;
            int r_ = idx_ >> 3, u_ = idx_ & 7;
            uint32_t sw_ = SWZ((uint32_t)(r_ * 128 + u_ * 16));
            int gn_ = n0 + r_;
            CP_ASYNC16(st_ + G_BH + sw_, (const char*)(Bh + (size_t)gn_ * K + k0_) + u_ * 16);
            CP_ASYNC16(st_ + G_BL + sw_, (const char*)(Bl + (size_t)gn_ * K + k0_) + u_ * 16);
        }
        CP_COMMIT();
    };

    load_stage(0);

    const int q8 = lid >> 3, lr = lid & 7;

    for (int cc = 0; cc < NC; cc++) {
        CP_WAIT0();                  // chunk cc resident
        __syncthreads();             // all warps past chunk cc-1 compute
        if (cc + 1 < NC) load_stage(cc + 1);

        const uint32_t st = sb + (cc & 1) * GSTG;
#pragma unroll
        for (int ks = 0; ks < 4; ks++) {
            const int kb = ks * 32;
            uint32_t ah[2][4], al[2][4], bh[4][2], bl[4][2];
#pragma unroll
            for (int mi = 0; mi < 2; mi++) {
                uint32_t off = SWZ((uint32_t)(
                    (wm * 32 + mi * 16 + lr + (q8 & 1) * 8) * 128 + kb + (q8 >> 1) * 16));
                ldsm4(ah[mi], st + G_AH + off);
                ldsm4(al[mi], st + G_AL + off);
            }
#pragma unroll
            for (int njp = 0; njp < 2; njp++) {
                uint32_t off = SWZ((uint32_t)(
                    (wn * 32 + njp * 16 + lr + (q8 >> 1) * 8) * 128 + kb + (q8 & 1) * 16));
                uint32_t t0[4], t1[4];
                ldsm4(t0, st + G_BH + off);
                ldsm4(t1, st + G_BL + off);
                bh[2 * njp][0] = t0[0]; bh[2 * njp][1] = t0[1];
                bh[2 * njp + 1][0] = t0[2]; bh[2 * njp + 1][1] = t0[3];
                bl[2 * njp][0] = t1[0]; bl[2 * njp][1] = t1[1];
                bl[2 * njp + 1][0] = t1[2]; bl[2 * njp + 1][1] = t1[3];
            }
#pragma unroll
            for (int mi = 0; mi < 2; mi++)
#pragma unroll
                for (int nj = 0; nj < 4; nj++) {
                    mma16816(c[mi][nj], ah[mi], bh[nj][0], bh[nj][1]);
                    mma16816(c[mi][nj], ah[mi], bl[nj][0], bl[nj][1]);
                    mma16816(c[mi][nj], al[mi], bh[nj][0], bh[nj][1]);
                }
        }
    }

    const int lr4 = lid >> 2, lc = (lid & 3) * 2;
    const float* __restrict__ bias = p.bias[z];
    __nv_bfloat16* Ch = p.Ch[z];
    __nv_bfloat16* Cl = p.Cl[z];
#pragma unroll
    for (int mi = 0; mi < 2; mi++) {
        int row = m0 + wm * 32 + mi * 16 + lr4;
#pragma unroll
        for (int nj = 0; nj < 4; nj++) {
            int col = n0 + wn * 32 + nj * 8 + lc;
            float2 b2 = *(const float2*)(bias + col);
            uint32_t h0, l0, h1, l1;
            pack_split(c[mi][nj][0] + b2.x, c[mi][nj][1] + b2.y, h0, l0);
            pack_split(c[mi][nj][2] + b2.x, c[mi][nj][3] + b2.y, h1, l1);
            if (row < M) {
                *(uint32_t*)(Ch + (size_t)row * N + col) = h0;
                *(uint32_t*)(Cl + (size_t)row * N + col) = l0;
            }
            if (row + 8 < M) {
                *(uint32_t*)(Ch + (size_t)(row + 8) * N + col) = h1;
                *(uint32_t*)(Cl + (size_t)(row + 8) * N + col) = l1;
            }
        }
    }
}

// ---------------------------------------------------------------------------
// Output GEMM: 128x128, BK=64, 3-stage (192KB), single sync per chunk.
// (R7 version, measured 476us.)
// ---------------------------------------------------------------------------
#define O_AH 0
#define O_AL 16384
#define O_BH 32768
#define O_BL 49152
#define OSTG 65536
#define OUT_SMEM (3 * OSTG)

__global__ __launch_bounds__(256, 1)
void gemm_out(const __nv_bfloat16* __restrict__ Ah, const __nv_bfloat16* __restrict__ Al,
              const __nv_bfloat16* __restrict__ Bh, const __nv_bfloat16* __restrict__ Bl,
              const float* __restrict__ bias, float* __restrict__ C)
{
    extern __shared__ __align__(1024) char smem[];
    const int tid = threadIdx.x;
    const int wid = tid >> 5, lid = tid & 31;
    const int wm = wid & 3, wn = wid >> 2;
    const int m0 = blockIdx.y * 128, n0 = blockIdx.x * 128;
    const uint32_t sb = smem_u32(smem);
    const int K = DINNER, N = DLLM;
    const int NC = K >> 6;

    float c[2][8][4];
#pragma unroll
    for (int i = 0; i < 2; i++)
#pragma unroll
        for (int j = 0; j < 8; j++)
#pragma unroll
            for (int q = 0; q < 4; q++) c[i][j][q] = 0.f;

    auto load_stage = [&](int cchunk) {
        const uint32_t st_ = sb + (cchunk % 3) * OSTG;
        const int k0_ = cchunk << 6;
#pragma unroll
        for (int i_ = 0; i_ < 4; i_++) {
            int idx_ = i_ * 256 + tid;
            int r_ = idx_ >> 3, u_ = idx_ & 7;
            uint32_t sw_ = SWZ((uint32_t)(r_ * 128 + u_ * 16));
            CP_ASYNC16(st_ + O_AH + sw_, (const char*)(Ah + (size_t)(m0 + r_) * K + k0_) + u_ * 16);
            CP_ASYNC16(st_ + O_AL + sw_, (const char*)(Al + (size_t)(m0 + r_) * K + k0_) + u_ * 16);
            CP_ASYNC16(st_ + O_BH + sw_, (const char*)(Bh + (size_t)(n0 + r_) * K + k0_) + u_ * 16);
            CP_ASYNC16(st_ + O_BL + sw_, (const char*)(Bl + (size_t)(n0 + r_) * K + k0_) + u_ * 16);
        }
        CP_COMMIT();
    };

    load_stage(0);
    load_stage(1);

    const int q8 = lid >> 3, lr = lid & 7;

    for (int cc = 0; cc < NC; cc++) {
        CP_WAIT1();
        __syncthreads();
        if (cc + 2 < NC) { load_stage(cc + 2); } else { CP_COMMIT(); }

        const uint32_t st = sb + (cc % 3) * OSTG;
#pragma unroll
        for (int ks = 0; ks < 4; ks++) {
            const int kb = ks * 32;
            uint32_t ah[2][4], al[2][4], bh[8][2], bl[8][2];
#pragma unroll
            for (int mi = 0; mi < 2; mi++) {
                uint32_t off = SWZ((uint32_t)(
                    (wm * 32 + mi * 16 + lr + (q8 & 1) * 8) * 128 + kb + (q8 >> 1) * 16));
                ldsm4(ah[mi], st + O_AH + off);
                ldsm4(al[mi], st + O_AL + off);
            }
#pragma unroll
            for (int njp = 0; njp < 4; njp++) {
                uint32_t off = SWZ((uint32_t)(
                    (wn * 64 + njp * 16 + lr + (q8 >> 1) * 8) * 128 + kb + (q8 & 1) * 16));
                uint32_t t0[4], t1[4];
                ldsm4(t0, st + O_BH + off);
                ldsm4(t1, st + O_BL + off);
                bh[2 * njp][0] = t0[0]; bh[2 * njp][1] = t0[1];
                bh[2 * njp + 1][0] = t0[2]; bh[2 * njp + 1][1] = t0[3];
                bl[2 * njp][0] = t1[0]; bl[2 * njp][1] = t1[1];
                bl[2 * njp + 1][0] = t1[2]; bl[2 * njp + 1][1] = t1[3];
            }
#pragma unroll
            for (int mi = 0; mi < 2; mi++)
#pragma unroll
                for (int nj = 0; nj < 8; nj++) {
                    mma16816(c[mi][nj], ah[mi], bh[nj][0], bh[nj][1]);
                    mma16816(c[mi][nj], ah[mi], bl[nj][0], bl[nj][1]);
                    mma16816(c[mi][nj], al[mi], bh[nj][0], bh[nj][1]);
                }
        }
    }

    const int lr4 = lid >> 2, lc = (lid & 3) * 2;
#pragma unroll
    for (int mi = 0; mi < 2; mi++) {
        int row = m0 + wm * 32 + mi * 16 + lr4;
#pragma unroll
        for (int nj = 0; nj < 8; nj++) {
            int col = n0 + wn * 64 + nj * 8 + lc;
            float2 b2 = *(const float2*)(bias + col);
            *(float2*)(C + (size_t)row * N + col) =
                make_float2(c[mi][nj][0] + b2.x, c[mi][nj][1] + b2.y);
            *(float2*)(C + (size_t)(row + 8) * N + col) =
                make_float2(c[mi][nj][2] + b2.x, c[mi][nj][3] + b2.y);
        }
    }
}

// ---------------------------------------------------------------------------
// HMMA flash attention (R6 version: 2-stage, race-free Q staging) with
// min-3-blocks/SM occupancy hint.
// ---------------------------------------------------------------------------
struct AttnParams {
    const __nv_bfloat16 *qh[2], *ql[2], *kh[2], *kl[2], *vh[2], *vl[2];
    const float *alpha, *beta;
    __nv_bfloat16 *oh, *ol;
};

#define ATT_STAGE 32768
#define A_KH 0
#define A_KL 8192
#define A_VH 16384
#define A_VL 24576
#define ATT_SMEM (2 * ATT_STAGE)   // 64 KB -> 3 CTAs/SM
#define NCH 16
#define SOFTMAX_SCALE 0.125f

__global__ __launch_bounds__(128, 3)
void attn_mma(AttnParams p)
{
    extern __shared__ __align__(1024) char smem[];
    const uint32_t sb = smem_u32(smem);
    const int tid = threadIdx.x;
    const int w = tid >> 5, lid = tid & 31;
    const int q8 = lid >> 3, lr = lid & 7;
    const int h = blockIdx.y;
    const int qbase = blockIdx.x * 64;
    const int colbase = h * EDIM;

    const float alpha = *p.alpha;
    const float beta  = *p.beta;

    float osave[8][4];

    for (int st = 0; st < 2; st++) {
        const __nv_bfloat16* __restrict__ qhp = p.qh[st];
        const __nv_bfloat16* __restrict__ qlp = p.ql[st];
        const __nv_bfloat16* __restrict__ khp = p.kh[st];
        const __nv_bfloat16* __restrict__ klp = p.kl[st];
        const __nv_bfloat16* __restrict__ vhp = p.vh[st];
        const __nv_bfloat16* __restrict__ vlp = p.vl[st];

#pragma unroll
        for (int i = 0; i < 4; i++) {
            int idx = i * 128 + tid;
            int r = idx >> 3, u = idx & 7;
            uint32_t sw = SWZ((uint32_t)(r * 128 + u * 16));
            CP_ASYNC16(sb + A_KH + sw,
                       (const char*)(qhp + (size_t)(qbase + r) * DINNER + colbase) + u * 16);
            CP_ASYNC16(sb + A_KL + sw,
                       (const char*)(qlp + (size_t)(qbase + r) * DINNER + colbase) + u * 16);
        }
        CP_COMMIT();
        CP_WAIT0();
        __syncthreads();

        uint32_t qfh[4][4], qfl[4][4];
#pragma unroll
        for (int ks = 0; ks < 4; ks++) {
            uint32_t off = SWZ((uint32_t)(
                (w * 16 + lr + (q8 & 1) * 8) * 128 + ks * 32 + (q8 >> 1) * 16));
            ldsm4(qfh[ks], sb + A_KH + off);
            ldsm4(qfl[ks], sb + A_KL + off);
        }
        __syncthreads();

        float o[8][4];
#pragma unroll
        for (int t = 0; t < 8; t++)
#pragma unroll
            for (int i = 0; i < 4; i++) o[t][i] = 0.f;
        float m0r = -INFINITY, m1r = -INFINITY;
        float l0 = 0.f, l1 = 0.f;

#define LOAD_KV(cchunk) do { \
            const uint32_t stg_ = sb + ((cchunk) & 1) * ATT_STAGE; \
            const int s0_ = (cchunk) * 64; \
            _Pragma("unroll") \
            for (int i_ = 0; i_ < 4; i_++) { \
                int idx_ = i_ * 128 + tid; \
                int r_ = idx_ >> 3, u_ = idx_ & 7; \
                uint32_t sw_ = SWZ((uint32_t)(r_ * 128 + u_ * 16)); \
                if (s0_ + r_ < SEQ_S) { \
                    const size_t go_ = (size_t)(s0_ + r_) * DINNER + colbase; \
                    CP_ASYNC16(stg_ + A_KH + sw_, (const char*)(khp + go_) + u_ * 16); \
                    CP_ASYNC16(stg_ + A_KL + sw_, (const char*)(klp + go_) + u_ * 16); \
                    CP_ASYNC16(stg_ + A_VH + sw_, (const char*)(vhp + go_) + u_ * 16); \
                    CP_ASYNC16(stg_ + A_VL + sw_, (const char*)(vlp + go_) + u_ * 16); \
                } else { \
                    STS_ZERO16(stg_ + A_KH + sw_); \
                    STS_ZERO16(stg_ + A_KL + sw_); \
                    STS_ZERO16(stg_ + A_VH + sw_); \
                    STS_ZERO16(stg_ + A_VL + sw_); \
                } \
            } \
            CP_COMMIT(); \
        } while (0)

        LOAD_KV(0);

        for (int cc = 0; cc < NCH; cc++) {
            CP_WAIT0();              // chunk cc resident
            __syncthreads();         // all warps past cc-1
            if (cc + 1 < NCH) LOAD_KV(cc + 1);
            const uint32_t stg = sb + (cc & 1) * ATT_STAGE;

            float s[8][4];
#pragma unroll
            for (int t = 0; t < 8; t++)
#pragma unroll
                for (int i = 0; i < 4; i++) s[t][i] = 0.f;

#pragma unroll
            for (int ks = 0; ks < 4; ks++) {
                uint32_t bh[8][2], bl[8][2];
#pragma unroll
                for (int njp = 0; njp < 4; njp++) {
                    uint32_t off = SWZ((uint32_t)(
                        (njp * 16 + lr + (q8 >> 1) * 8) * 128 + ks * 32 + (q8 & 1) * 16));
                    uint32_t t0[4], t1[4];
                    ldsm4(t0, stg + A_KH + off);
                    ldsm4(t1, stg + A_KL + off);
                    bh[2 * njp][0] = t0[0]; bh[2 * njp][1] = t0[1];
                    bh[2 * njp + 1][0] = t0[2]; bh[2 * njp + 1][1] = t0[3];
                    bl[2 * njp][0] = t1[0]; bl[2 * njp][1] = t1[1];
                    bl[2 * njp + 1][0] = t1[2]; bl[2 * njp + 1][1] = t1[3];
                }
#pragma unroll
                for (int t = 0; t < 8; t++) {
                    mma16816(s[t], qfh[ks], bh[t][0], bh[t][1]);
                    mma16816(s[t], qfh[ks], bl[t][0], bl[t][1]);
                    mma16816(s[t], qfl[ks], bh[t][0], bh[t][1]);
                }
            }

            if (cc == NCH - 1) {
#pragma unroll
                for (int t = 5; t < 8; t++)
#pragma unroll
                    for (int i = 0; i < 4; i++) s[t][i] = -1e30f;
            }

            float ml0 = -1e30f, ml1 = -1e30f;
#pragma unroll
            for (int t = 0; t < 8; t++) {
                ml0 = fmaxf(ml0, fmaxf(s[t][0], s[t][1]));
                ml1 = fmaxf(ml1, fmaxf(s[t][2], s[t][3]));
            }
            ml0 = fmaxf(ml0, __shfl_xor_sync(0xffffffffu, ml0, 1));
            ml0 = fmaxf(ml0, __shfl_xor_sync(0xffffffffu, ml0, 2));
            ml1 = fmaxf(ml1, __shfl_xor_sync(0xffffffffu, ml1, 1));
            ml1 = fmaxf(ml1, __shfl_xor_sync(0xffffffffu, ml1, 2));

            float mn0 = fmaxf(m0r, ml0), mn1 = fmaxf(m1r, ml1);
            float c0 = __expf((m0r - mn0) * SOFTMAX_SCALE);
            float c1 = __expf((m1r - mn1) * SOFTMAX_SCALE);
            m0r = mn0; m1r = mn1;
            l0 *= c0; l1 *= c1;
#pragma unroll
            for (int t = 0; t < 8; t++) {
                o[t][0] *= c0; o[t][1] *= c0;
                o[t][2] *= c1; o[t][3] *= c1;
            }
#pragma unroll
            for (int t = 0; t < 8; t++) {
                float p0 = __expf((s[t][0] - mn0) * SOFTMAX_SCALE);
                float p1 = __expf((s[t][1] - mn0) * SOFTMAX_SCALE);
                float p2 = __expf((s[t][2] - mn1) * SOFTMAX_SCALE);
                float p3 = __expf((s[t][3] - mn1) * SOFTMAX_SCALE);
                l0 += p0 + p1; l1 += p2 + p3;
                s[t][0] = p0; s[t][1] = p1; s[t][2] = p2; s[t][3] = p3;
            }

#pragma unroll
            for (int ks = 0; ks < 4; ks++) {
                uint32_t pah[4], pal[4];
                pack_split(s[2 * ks][0],     s[2 * ks][1],     pah[0], pal[0]);
                pack_split(s[2 * ks][2],     s[2 * ks][3],     pah[1], pal[1]);
                pack_split(s[2 * ks + 1][0], s[2 * ks + 1][1], pah[2], pal[2]);
                pack_split(s[2 * ks + 1][2], s[2 * ks + 1][3], pah[3], pal[3]);
#pragma unroll
                for (int ep = 0; ep < 4; ep++) {
                    uint32_t off = SWZ((uint32_t)(
                        (ks * 16 + lr + (q8 & 1) * 8) * 128 + ep * 32 + (q8 >> 1) * 16));
                    uint32_t tv0[4], tv1[4];
                    ldsm4t(tv0, stg + A_VH + off);
                    ldsm4t(tv1, stg + A_VL + off);
                    mma16816(o[2 * ep],     pah, tv0[0], tv0[1]);
                    mma16816(o[2 * ep],     pah, tv1[0], tv1[1]);
                    mma16816(o[2 * ep],     pal, tv0[0], tv0[1]);
                    mma16816(o[2 * ep + 1], pah, tv0[2], tv0[3]);
                    mma16816(o[2 * ep + 1], pah, tv1[2], tv1[3]);
                    mma16816(o[2 * ep + 1], pal, tv0[2], tv0[3]);
                }
            }
        }

        l0 += __shfl_xor_sync(0xffffffffu, l0, 1);
        l0 += __shfl_xor_sync(0xffffffffu, l0, 2);
        l1 += __shfl_xor_sync(0xffffffffu, l1, 1);
        l1 += __shfl_xor_sync(0xffffffffu, l1, 2);
        float wgt = (st == 0) ? alpha : beta;
        float f0 = wgt / l0, f1 = wgt / l1;
        if (st == 0) {
#pragma unroll
            for (int t = 0; t < 8; t++) {
                osave[t][0] = o[t][0] * f0; osave[t][1] = o[t][1] * f0;
                osave[t][2] = o[t][2] * f1; osave[t][3] = o[t][3] * f1;
            }
        } else {
#pragma unroll
            for (int t = 0; t < 8; t++) {
                osave[t][0] += o[t][0] * f0; osave[t][1] += o[t][1] * f0;
                osave[t][2] += o[t][2] * f1; osave[t][3] += o[t][3] * f1;
            }
        }
        __syncthreads();
    }

    const int r0 = qbase + w * 16 + (lid >> 2);
#pragma unroll
    for (int t = 0; t < 8; t++) {
        int col = colbase + t * 8 + (lid & 3) * 2;
        uint32_t h0, lo0, h1, lo1;
        pack_split(osave[t][0], osave[t][1], h0, lo0);
        pack_split(osave[t][2], osave[t][3], h1, lo1);
        *(uint32_t*)(p.oh + (size_t)r0 * DINNER + col) = h0;
        *(uint32_t*)(p.ol + (size_t)r0 * DINNER + col) = lo0;
        *(uint32_t*)(p.oh + (size_t)(r0 + 8) * DINNER + col) = h1;
        *(uint32_t*)(p.ol + (size_t)(r0 + 8) * DINNER + col) = lo1;
    }
}

// ---------------------------------------------------------------------------
// Launch
// ---------------------------------------------------------------------------
extern "C" void kernel_launch(void* const* d_in, const int* in_sizes, int n_in,
                              void* d_out, int out_size)
{
    const float* target = (const float*)d_in[0];
    const float* source = (const float*)d_in[1];
    const float* value  = (const float*)d_in[2];
    const float* Wq_s = (const float*)d_in[3];  const float* bq_s = (const float*)d_in[4];
    const float* Wk_s = (const float*)d_in[5];  const float* bk_s = (const float*)d_in[6];
    const float* Wv_s = (const float*)d_in[7];  const float* bv_s = (const float*)d_in[8];
    const float* Wq_l = (const float*)d_in[9];  const float* bq_l = (const float*)d_in[10];
    const float* Wk_l = (const float*)d_in[11]; const float* bk_l = (const float*)d_in[12];
    const float* Wv_l = (const float*)d_in[13]; const float* bv_l = (const float*)d_in[14];
    const float* Wo   = (const float*)d_in[15]; const float* bo   = (const float*)d_in[16];
    const float* alpha = (const float*)d_in[17];
    const float* beta  = (const float*)d_in[18];
    float* out = (float*)d_out;

    __nv_bfloat16 *th, *tl, *sh, *sl, *vh, *vl2, *ah, *al;
    cudaGetSymbolAddress((void**)&th,  g_th);  cudaGetSymbolAddress((void**)&tl,  g_tl);
    cudaGetSymbolAddress((void**)&sh,  g_sh);  cudaGetSymbolAddress((void**)&sl,  g_sl);
    cudaGetSymbolAddress((void**)&vh,  g_vh);  cudaGetSymbolAddress((void**)&vl2, g_vl2);
    cudaGetSymbolAddress((void**)&ah,  g_ah);  cudaGetSymbolAddress((void**)&al,  g_al);

    __nv_bfloat16 *qsh, *qsl, *qlh, *qll, *ksh, *ksl, *vsh, *vsl, *klh, *kll, *vlh, *vll;
    cudaGetSymbolAddress((void**)&qsh, g_qsh); cudaGetSymbolAddress((void**)&qsl, g_qsl);
    cudaGetSymbolAddress((void**)&qlh, g_qlh); cudaGetSymbolAddress((void**)&qll, g_qll);
    cudaGetSymbolAddress((void**)&ksh, g_ksh); cudaGetSymbolAddress((void**)&ksl, g_ksl);
    cudaGetSymbolAddress((void**)&vsh, g_vsh); cudaGetSymbolAddress((void**)&vsl, g_vsl);
    cudaGetSymbolAddress((void**)&klh, g_klh); cudaGetSymbolAddress((void**)&kll, g_kll);
    cudaGetSymbolAddress((void**)&vlh, g_vlh); cudaGetSymbolAddress((void**)&vll, g_vll);

    __nv_bfloat16 *wqsh, *wqsl, *wqlh, *wqll, *wksh, *wksl, *wvsh, *wvsl;
    __nv_bfloat16 *wklh, *wkll, *wvlh, *wvll, *woh, *wol;
    cudaGetSymbolAddress((void**)&wqsh, g_wqsh); cudaGetSymbolAddress((void**)&wqsl, g_wqsl);
    cudaGetSymbolAddress((void**)&wqlh, g_wqlh); cudaGetSymbolAddress((void**)&wqll, g_wqll);
    cudaGetSymbolAddress((void**)&wksh, g_wksh); cudaGetSymbolAddress((void**)&wksl, g_wksl);
    cudaGetSymbolAddress((void**)&wvsh, g_wvsh); cudaGetSymbolAddress((void**)&wvsl, g_wvsl);
    cudaGetSymbolAddress((void**)&wklh, g_wklh); cudaGetSymbolAddress((void**)&wkll, g_wkll);
    cudaGetSymbolAddress((void**)&wvlh, g_wvlh); cudaGetSymbolAddress((void**)&wvll, g_wvll);
    cudaGetSymbolAddress((void**)&woh,  g_woh);  cudaGetSymbolAddress((void**)&wol,  g_wol);

    cudaFuncSetAttribute(gemm_proj, cudaFuncAttributeMaxDynamicSharedMemorySize, PROJ_SMEM);
    cudaFuncSetAttribute(gemm_out,  cudaFuncAttributeMaxDynamicSharedMemorySize, OUT_SMEM);
    cudaFuncSetAttribute(attn_mma,  cudaFuncAttributeMaxDynamicSharedMemorySize, ATT_SMEM);

    // --- merged prepass ---
    {
        PrepassParams pp = {};
        const float* Ws[7]   = {Wq_s, Wq_l, Wk_s, Wv_s, Wk_l, Wv_l, Wo};
        __nv_bfloat16* Ths[7] = {wqsh, wqlh, wksh, wvsh, wklh, wvlh, woh};
        __nv_bfloat16* Tls[7] = {wqsl, wqll, wksl, wvsl, wkll, wvll, wol};
        const int Ks[7] = {DMODEL, DMODEL, DLLM, DLLM, DLLM, DLLM, DINNER};
        const int Ns[7] = {DINNER, DINNER, DINNER, DINNER, DINNER, DINNER, DLLM};
        int acc = 0;
        pp.t_ofs[0] = 0;
        for (int i = 0; i < 7; i++) {
            pp.W[i] = Ws[i]; pp.Th[i] = Ths[i]; pp.Tl[i] = Tls[i];
            pp.K[i] = Ks[i]; pp.N[i] = Ns[i];
            acc += (Ks[i] / 32) * (Ns[i] / 32);
            pp.t_ofs[i + 1] = acc;
        }
        pp.total_trans = acc;
        pp.X[0] = target; pp.H[0] = th; pp.L[0] = tl;
        pp.X[1] = source; pp.H[1] = sh; pp.L[1] = sl;
        pp.X[2] = value;  pp.H[2] = vh; pp.L[2] = vl2;
        pp.s_ofs[0] = 0;
        pp.s_ofs[1] = (BL * DMODEL) / 16384;
        pp.s_ofs[2] = pp.s_ofs[1] + (SEQ_S * DLLM) / 16384;
        pp.s_ofs[3] = pp.s_ofs[2] + (SEQ_S * DLLM) / 16384;
        prepass<<<pp.total_trans + pp.s_ofs[3], 256>>>(pp);
    }

    // --- all 6 projection GEMMs, one flat launch (TN=64, 2 CTAs/SM) ---
    {
        GemmJobs p = {};
        const __nv_bfloat16* Ahs[6] = {th, th, sh, vh, sh, vh};
        const __nv_bfloat16* Als[6] = {tl, tl, sl, vl2, sl, vl2};
        const __nv_bfloat16* Bhs[6] = {wqsh, wqlh, wksh, wvsh, wklh, wvlh};
        const __nv_bfloat16* Bls[6] = {wqsl, wqll, wksl, wvsl, wkll, wvll};
        const float* bs[6] = {bq_s, bq_l, bk_s, bv_s, bk_l, bv_l};
        __nv_bfloat16* Chs[6] = {qsh, qlh, ksh, vsh, klh, vlh};
        __nv_bfloat16* Cls[6] = {qsl, qll, ksl, vsl, kll, vll};
        const int Ms[6] = {BL, BL, SEQ_S, SEQ_S, SEQ_S, SEQ_S};
        const int Ks2[6] = {DMODEL, DMODEL, DLLM, DLLM, DLLM, DLLM};
        int acc = 0;
        p.ofs[0] = 0;
        for (int i = 0; i < 6; i++) {
            p.Ah[i] = Ahs[i]; p.Al[i] = Als[i]; p.Bh[i] = Bhs[i]; p.Bl[i] = Bls[i];
            p.bias[i] = bs[i]; p.Ch[i] = Chs[i]; p.Cl[i] = Cls[i];
            p.M[i] = Ms[i]; p.K[i] = Ks2[i];
            acc += 16 * ((Ms[i] + 127) / 128);
            p.ofs[i + 1] = acc;
        }
        gemm_proj<<<acc, 256, PROJ_SMEM>>>(p);   // 2560 blocks
    }

    // --- fused dual-stream flash attention ---
    {
        AttnParams ap = {};
        ap.qh[0] = qsh; ap.ql[0] = qsl; ap.kh[0] = ksh; ap.kl[0] = ksl;
        ap.vh[0] = vsh; ap.vl[0] = vsl;
        ap.qh[1] = qlh; ap.ql[1] = qll; ap.kh[1] = klh; ap.kl[1] = kll;
        ap.vh[1] = vlh; ap.vl[1] = vll;
        ap.alpha = alpha; ap.beta = beta;
        ap.oh = ah; ap.ol = al;
        dim3 g(BL / 64, NHEAD);
        attn_mma<<<g, 128, ATT_SMEM>>>(ap);
    }

    // --- output projection (3-stage, measured best) ---
    {
        dim3 g(DLLM / 128, BL / 128);
        gemm_out<<<g, 256, OUT_SMEM>>>(ah, al, woh, wol, bo, out);
    }
}

// round 9
// speedup vs baseline: 1.2952x; 1.2812x over previous
#include <cuda_runtime.h>
#include <cuda_bf16.h>
#include <cuda_fp16.h>
#include <math.h>
#include <stdint.h>

#define BL     8192
#define DMODEL 1024
#define DLLM   4096
#define DINNER 1024
#define SEQ_S  1000
#define NHEAD  16
#define EDIM   64

// ---------------------------------------------------------------------------
// Portable PTX helpers (base compute_103 target — NO tcgen05)
// ---------------------------------------------------------------------------
__device__ __forceinline__ uint32_t smem_u32(const void* p) {
    uint32_t a;
    asm("{ .reg .u64 t; cvta.to.shared.u64 t, %1; cvt.u32.u64 %0, t; }"
        : "=r"(a) : "l"(p));
    return a;
}

#define SWZ(o) ((o) ^ (((o) >> 3) & 0x70))

#define CP_ASYNC16(dst, src) \
    asm volatile("cp.async.cg.shared.global [%0], [%1], 16;\n" :: "r"(dst), "l"(src))
#define CP_COMMIT() asm volatile("cp.async.commit_group;\n" ::: "memory")
#define CP_WAIT1()  asm volatile("cp.async.wait_group 1;\n" ::: "memory")
#define CP_WAIT0()  asm volatile("cp.async.wait_group 0;\n" ::: "memory")
#define STS_ZERO16(addr) \
    asm volatile("st.shared.v4.b32 [%0], {%1,%1,%1,%1};\n" :: "r"(addr), "r"(0u) : "memory")

__device__ __forceinline__ void ldsm4(uint32_t* r, uint32_t a) {
    asm volatile("ldmatrix.sync.aligned.m8n8.x4.shared.b16 {%0,%1,%2,%3}, [%4];\n"
        : "=r"(r[0]), "=r"(r[1]), "=r"(r[2]), "=r"(r[3]) : "r"(a));
}
__device__ __forceinline__ void ldsm4t(uint32_t* r, uint32_t a) {
    asm volatile("ldmatrix.sync.aligned.m8n8.x4.trans.shared.b16 {%0,%1,%2,%3}, [%4];\n"
        : "=r"(r[0]), "=r"(r[1]), "=r"(r[2]), "=r"(r[3]) : "r"(a));
}
__device__ __forceinline__ void mma16816(float* c, const uint32_t* a,
                                         uint32_t b0, uint32_t b1) {
    asm volatile(
        "mma.sync.aligned.m16n8k16.row.col.f32.bf16.bf16.f32 "
        "{%0,%1,%2,%3}, {%4,%5,%6,%7}, {%8,%9}, {%0,%1,%2,%3};\n"
        : "+f"(c[0]), "+f"(c[1]), "+f"(c[2]), "+f"(c[3])
        : "r"(a[0]), "r"(a[1]), "r"(a[2]), "r"(a[3]), "r"(b0), "r"(b1));
}
__device__ __forceinline__ void mma16816h(float* c, const uint32_t* a,
                                          uint32_t b0, uint32_t b1) {
    asm volatile(
        "mma.sync.aligned.m16n8k16.row.col.f32.f16.f16.f32 "
        "{%0,%1,%2,%3}, {%4,%5,%6,%7}, {%8,%9}, {%0,%1,%2,%3};\n"
        : "+f"(c[0]), "+f"(c[1]), "+f"(c[2]), "+f"(c[3])
        : "r"(a[0]), "r"(a[1]), "r"(a[2]), "r"(a[3]), "r"(b0), "r"(b1));
}

__device__ __forceinline__ void pack_split(float a, float b, uint32_t& hi, uint32_t& lo) {
    __nv_bfloat162 h = __floats2bfloat162_rn(a, b);
    float ra = a - __bfloat162float(h.x);
    float rb = b - __bfloat162float(h.y);
    __nv_bfloat162 l = __floats2bfloat162_rn(ra, rb);
    hi = *reinterpret_cast<uint32_t*>(&h);
    lo = *reinterpret_cast<uint32_t*>(&l);
}

// ---------------------------------------------------------------------------
// Scratch (device globals — no allocation allowed)
// ---------------------------------------------------------------------------
__device__ __nv_bfloat16 g_th[BL * DMODEL],  g_tl[BL * DMODEL];
__device__ __nv_bfloat16 g_sh[SEQ_S * DLLM], g_sl[SEQ_S * DLLM];
__device__ __nv_bfloat16 g_vh[SEQ_S * DLLM], g_vl2[SEQ_S * DLLM];
__device__ __nv_bfloat16 g_qsh[BL * DINNER],    g_qsl[BL * DINNER];
__device__ __nv_bfloat16 g_qlh[BL * DINNER],    g_qll[BL * DINNER];
__device__ __nv_bfloat16 g_ksh[SEQ_S * DINNER], g_ksl[SEQ_S * DINNER];
__device__ __nv_bfloat16 g_vsh[SEQ_S * DINNER], g_vsl[SEQ_S * DINNER];
__device__ __nv_bfloat16 g_klh[SEQ_S * DINNER], g_kll[SEQ_S * DINNER];
__device__ __nv_bfloat16 g_vlh[SEQ_S * DINNER], g_vll[SEQ_S * DINNER];
__device__ __half        g_af16[BL * DINNER];          // attn out, fp16 single
__device__ __nv_bfloat16 g_wqsh[DINNER * DMODEL], g_wqsl[DINNER * DMODEL];
__device__ __nv_bfloat16 g_wqlh[DINNER * DMODEL], g_wqll[DINNER * DMODEL];
__device__ __nv_bfloat16 g_wksh[DINNER * DLLM],   g_wksl[DINNER * DLLM];
__device__ __nv_bfloat16 g_wvsh[DINNER * DLLM],   g_wvsl[DINNER * DLLM];
__device__ __nv_bfloat16 g_wklh[DINNER * DLLM],   g_wkll[DINNER * DLLM];
__device__ __nv_bfloat16 g_wvlh[DINNER * DLLM],   g_wvll[DINNER * DLLM];
__device__ __half        g_wof16[DLLM * DINNER];       // Wo^T, fp16 single

// ---------------------------------------------------------------------------
// Merged prepass: jobs 0-5 -> bf16 hi/lo transposed; job 6 (Wo) -> fp16 single.
// ---------------------------------------------------------------------------
struct PrepassParams {
    const float* W[7];
    __nv_bfloat16 *Th[7], *Tl[7];
    int K[7], N[7];
    int t_ofs[8];
    const float* X[3];
    __nv_bfloat16 *H[3], *L[3];
    int s_ofs[4];
    int total_trans;
};

__global__ __launch_bounds__(256)
void prepass(PrepassParams p)
{
    __shared__ float tsm[32][33];
    const int bid = blockIdx.x;
    if (bid < p.total_trans) {
        int w = 0;
        while (bid >= p.t_ofs[w + 1]) w++;
        const int t = bid - p.t_ofs[w];
        const int K = p.K[w], N = p.N[w];
        const int tiles_x = N >> 5;
        const int n0 = (t % tiles_x) << 5, k0 = (t / tiles_x) << 5;
        const float* __restrict__ W = p.W[w];
        const int tx = threadIdx.x & 31, ty = threadIdx.x >> 5;
#pragma unroll
        for (int i = 0; i < 32; i += 8)
            tsm[ty + i][tx] = W[(size_t)(k0 + ty + i) * N + n0 + tx];
        __syncthreads();
        if (w == 6) {
            __half* __restrict__ T = reinterpret_cast<__half*>(p.Th[w]);
#pragma unroll
            for (int i = 0; i < 32; i += 8) {
                int n = n0 + ty + i;
                T[(size_t)n * K + k0 + tx] = __float2half(tsm[tx][ty + i]);
            }
        } else {
            __nv_bfloat16* __restrict__ Th = p.Th[w];
            __nv_bfloat16* __restrict__ Tl = p.Tl[w];
#pragma unroll
            for (int i = 0; i < 32; i += 8) {
                int n = n0 + ty + i;
                float v = tsm[tx][ty + i];
                __nv_bfloat16 h = __float2bfloat16(v);
                Th[(size_t)n * K + k0 + tx] = h;
                Tl[(size_t)n * K + k0 + tx] = __float2bfloat16(v - __bfloat162float(h));
            }
        }
    } else {
        const int sb = bid - p.total_trans;
        int a = 0;
        while (sb >= p.s_ofs[a + 1]) a++;
        const int rel = sb - p.s_ofs[a];
        const float* __restrict__ X = p.X[a];
        __nv_bfloat16* __restrict__ H = p.H[a];
        __nv_bfloat16* __restrict__ L = p.L[a];
#pragma unroll
        for (int i = 0; i < 16; i++) {
            int idx = rel * 16384 + (i * 256 + threadIdx.x) * 4;
            float4 v = *(const float4*)(X + idx);
            uint32_t h01, l01, h23, l23;
            pack_split(v.x, v.y, h01, l01);
            pack_split(v.z, v.w, h23, l23);
            *(uint2*)(H + idx) = make_uint2(h01, h23);
            *(uint2*)(L + idx) = make_uint2(l01, l23);
        }
    }
}

// ---------------------------------------------------------------------------
// Projection GEMM (R6 proven config): 128x64, BK=64, 2-stage, 96KB, 2 CTAs/SM,
// two-sync loop. Flat 1D grid over 6 jobs, bf16-split epilogue.
// ---------------------------------------------------------------------------
struct GemmJobs {
    const __nv_bfloat16 *Ah[6], *Al[6], *Bh[6], *Bl[6];
    const float* bias[6];
    __nv_bfloat16 *Ch[6], *Cl[6];
    int M[6], K[6];
    int ofs[7];
};

#define G_AH 0
#define G_AL 16384
#define G_BH 32768
#define G_BL 40960
#define GSTG 49152
#define PROJ_SMEM (2 * GSTG)

__global__ __launch_bounds__(256, 2)
void gemm_proj(GemmJobs p)
{
    extern __shared__ __align__(1024) char smem[];
    const int bid = blockIdx.x;
    int z = 0;
    while (bid >= p.ofs[z + 1]) z++;
    const int rel = bid - p.ofs[z];
    const int bx = rel & 15, by = rel >> 4;
    const int M = p.M[z], K = p.K[z];
    const int N = DINNER;

    const __nv_bfloat16* __restrict__ Ah = p.Ah[z];
    const __nv_bfloat16* __restrict__ Al = p.Al[z];
    const __nv_bfloat16* __restrict__ Bh = p.Bh[z];
    const __nv_bfloat16* __restrict__ Bl = p.Bl[z];

    const int tid = threadIdx.x;
    const int wid = tid >> 5, lid = tid & 31;
    const int wm = wid & 3, wn = wid >> 2;
    const int m0 = by * 128, n0 = bx * 64;
    const uint32_t sb = smem_u32(smem);

    float c[2][4][4];
#pragma unroll
    for (int i = 0; i < 2; i++)
#pragma unroll
        for (int j = 0; j < 4; j++)
#pragma unroll
            for (int q = 0; q < 4; q++) c[i][j][q] = 0.f;

    const int NC = K >> 6;

    auto load_stage = [&](int cchunk) {
        const uint32_t st_ = sb + (cchunk & 1) * GSTG;
        const int k0_ = cchunk << 6;
#pragma unroll
        for (int i_ = 0; i_ < 4; i_++) {
            int idx_ = i_ * 256 + tid;
            int r_ = idx_ >> 3, u_ = idx_ & 7;
            uint32_t sw_ = SWZ((uint32_t)(r_ * 128 + u_ * 16));
            int gm_ = m0 + r_;
            if (gm_ < M) {
                CP_ASYNC16(st_ + G_AH + sw_, (const char*)(Ah + (size_t)gm_ * K + k0_) + u_ * 16);
                CP_ASYNC16(st_ + G_AL + sw_, (const char*)(Al + (size_t)gm_ * K + k0_) + u_ * 16);
            } else {
                STS_ZERO16(st_ + G_AH + sw_);
                STS_ZERO16(st_ + G_AL + sw_);
            }
        }
#pragma unroll
        for (int i_ = 0; i_ < 2; i_++) {
            int idx_ = i_ * 256 + tid;
            int r_ = idx_ >> 3, u_ = idx_ & 7;
            uint32_t sw_ = SWZ((uint32_t)(r_ * 128 + u_ * 16));
            int gn_ = n0 + r_;
            CP_ASYNC16(st_ + G_BH + sw_, (const char*)(Bh + (size_t)gn_ * K + k0_) + u_ * 16);
            CP_ASYNC16(st_ + G_BL + sw_, (const char*)(Bl + (size_t)gn_ * K + k0_) + u_ * 16);
        }
        CP_COMMIT();
    };

    load_stage(0);

    const int q8 = lid >> 3, lr = lid & 7;

    for (int cc = 0; cc < NC; cc++) {
        __syncthreads();                       // all warps done with buffer (cc+1)&1
        if (cc + 1 < NC) { load_stage(cc + 1); } else { CP_COMMIT(); }
        CP_WAIT1();                            // chunk cc resident
        __syncthreads();

        const uint32_t st = sb + (cc & 1) * GSTG;
#pragma unroll
        for (int ks = 0; ks < 4; ks++) {
            const int kb = ks * 32;
            uint32_t ah[2][4], al[2][4], bh[4][2], bl[4][2];
#pragma unroll
            for (int mi = 0; mi < 2; mi++) {
                uint32_t off = SWZ((uint32_t)(
                    (wm * 32 + mi * 16 + lr + (q8 & 1) * 8) * 128 + kb + (q8 >> 1) * 16));
                ldsm4(ah[mi], st + G_AH + off);
                ldsm4(al[mi], st + G_AL + off);
            }
#pragma unroll
            for (int njp = 0; njp < 2; njp++) {
                uint32_t off = SWZ((uint32_t)(
                    (wn * 32 + njp * 16 + lr + (q8 >> 1) * 8) * 128 + kb + (q8 & 1) * 16));
                uint32_t t0[4], t1[4];
                ldsm4(t0, st + G_BH + off);
                ldsm4(t1, st + G_BL + off);
                bh[2 * njp][0] = t0[0]; bh[2 * njp][1] = t0[1];
                bh[2 * njp + 1][0] = t0[2]; bh[2 * njp + 1][1] = t0[3];
                bl[2 * njp][0] = t1[0]; bl[2 * njp][1] = t1[1];
                bl[2 * njp + 1][0] = t1[2]; bl[2 * njp + 1][1] = t1[3];
            }
#pragma unroll
            for (int mi = 0; mi < 2; mi++)
#pragma unroll
                for (int nj = 0; nj < 4; nj++) {
                    mma16816(c[mi][nj], ah[mi], bh[nj][0], bh[nj][1]);
                    mma16816(c[mi][nj], ah[mi], bl[nj][0], bl[nj][1]);
                    mma16816(c[mi][nj], al[mi], bh[nj][0], bh[nj][1]);
                }
        }
    }

    const int lr4 = lid >> 2, lc = (lid & 3) * 2;
    const float* __restrict__ bias = p.bias[z];
    __nv_bfloat16* Ch = p.Ch[z];
    __nv_bfloat16* Cl = p.Cl[z];
#pragma unroll
    for (int mi = 0; mi < 2; mi++) {
        int row = m0 + wm * 32 + mi * 16 + lr4;
#pragma unroll
        for (int nj = 0; nj < 4; nj++) {
            int col = n0 + wn * 32 + nj * 8 + lc;
            float2 b2 = *(const float2*)(bias + col);
            uint32_t h0, l0, h1, l1;
            pack_split(c[mi][nj][0] + b2.x, c[mi][nj][1] + b2.y, h0, l0);
            pack_split(c[mi][nj][2] + b2.x, c[mi][nj][3] + b2.y, h1, l1);
            if (row < M) {
                *(uint32_t*)(Ch + (size_t)row * N + col) = h0;
                *(uint32_t*)(Cl + (size_t)row * N + col) = l0;
            }
            if (row + 8 < M) {
                *(uint32_t*)(Ch + (size_t)(row + 8) * N + col) = h1;
                *(uint32_t*)(Cl + (size_t)(row + 8) * N + col) = l1;
            }
        }
    }
}

// ---------------------------------------------------------------------------
// Output GEMM — fp16 single-term: C[8192,4096] = A_f16 @ Wo_f16^T + bias.
// Tile 128x128, BK=64, 3-stage (96KB) -> 2 CTAs/SM.
// ---------------------------------------------------------------------------
#define F_A 0
#define F_B 16384
#define FSTG 32768
#define OUTF_SMEM (3 * FSTG)   // 96 KB

__global__ __launch_bounds__(256, 2)
void gemm_out_f16(const __half* __restrict__ A, const __half* __restrict__ B,
                  const float* __restrict__ bias, float* __restrict__ C)
{
    extern __shared__ __align__(1024) char smem[];
    const int tid = threadIdx.x;
    const int wid = tid >> 5, lid = tid & 31;
    const int wm = wid & 3, wn = wid >> 2;
    const int m0 = blockIdx.y * 128, n0 = blockIdx.x * 128;
    const uint32_t sb = smem_u32(smem);
    const int K = DINNER, N = DLLM;
    const int NC = K >> 6;   // 16

    float c[2][8][4];
#pragma unroll
    for (int i = 0; i < 2; i++)
#pragma unroll
        for (int j = 0; j < 8; j++)
#pragma unroll
            for (int q = 0; q < 4; q++) c[i][j][q] = 0.f;

    auto load_stage = [&](int cchunk) {
        const uint32_t st_ = sb + (cchunk % 3) * FSTG;
        const int k0_ = cchunk << 6;
#pragma unroll
        for (int i_ = 0; i_ < 4; i_++) {
            int idx_ = i_ * 256 + tid;
            int r_ = idx_ >> 3, u_ = idx_ & 7;
            uint32_t sw_ = SWZ((uint32_t)(r_ * 128 + u_ * 16));
            CP_ASYNC16(st_ + F_A + sw_, (const char*)(A + (size_t)(m0 + r_) * K + k0_) + u_ * 16);
            CP_ASYNC16(st_ + F_B + sw_, (const char*)(B + (size_t)(n0 + r_) * K + k0_) + u_ * 16);
        }
        CP_COMMIT();
    };

    load_stage(0);
    load_stage(1);

    const int q8 = lid >> 3, lr = lid & 7;

    for (int cc = 0; cc < NC; cc++) {
        CP_WAIT1();
        __syncthreads();
        if (cc + 2 < NC) { load_stage(cc + 2); } else { CP_COMMIT(); }

        const uint32_t st = sb + (cc % 3) * FSTG;
#pragma unroll
        for (int ks = 0; ks < 4; ks++) {
            const int kb = ks * 32;
            uint32_t ah[2][4], bh[8][2];
#pragma unroll
            for (int mi = 0; mi < 2; mi++) {
                uint32_t off = SWZ((uint32_t)(
                    (wm * 32 + mi * 16 + lr + (q8 & 1) * 8) * 128 + kb + (q8 >> 1) * 16));
                ldsm4(ah[mi], st + F_A + off);
            }
#pragma unroll
            for (int njp = 0; njp < 4; njp++) {
                uint32_t off = SWZ((uint32_t)(
                    (wn * 64 + njp * 16 + lr + (q8 >> 1) * 8) * 128 + kb + (q8 & 1) * 16));
                uint32_t t0[4];
                ldsm4(t0, st + F_B + off);
                bh[2 * njp][0] = t0[0]; bh[2 * njp][1] = t0[1];
                bh[2 * njp + 1][0] = t0[2]; bh[2 * njp + 1][1] = t0[3];
            }
#pragma unroll
            for (int mi = 0; mi < 2; mi++)
#pragma unroll
                for (int nj = 0; nj < 8; nj++)
                    mma16816h(c[mi][nj], ah[mi], bh[nj][0], bh[nj][1]);
        }
    }

    const int lr4 = lid >> 2, lc = (lid & 3) * 2;
#pragma unroll
    for (int mi = 0; mi < 2; mi++) {
        int row = m0 + wm * 32 + mi * 16 + lr4;
#pragma unroll
        for (int nj = 0; nj < 8; nj++) {
            int col = n0 + wn * 64 + nj * 8 + lc;
            float2 b2 = *(const float2*)(bias + col);
            *(float2*)(C + (size_t)row * N + col) =
                make_float2(c[mi][nj][0] + b2.x, c[mi][nj][1] + b2.y);
            *(float2*)(C + (size_t)(row + 8) * N + col) =
                make_float2(c[mi][nj][2] + b2.x, c[mi][nj][3] + b2.y);
        }
    }
}

// ---------------------------------------------------------------------------
// HMMA flash attention (R6 proven version: 2-stage, two-sync), fp16 output.
// ---------------------------------------------------------------------------
struct AttnParams {
    const __nv_bfloat16 *qh[2], *ql[2], *kh[2], *kl[2], *vh[2], *vl[2];
    const float *alpha, *beta;
    __half *of;
};

#define ATT_STAGE 32768
#define A_KH 0
#define A_KL 8192
#define A_VH 16384
#define A_VL 24576
#define ATT_SMEM (2 * ATT_STAGE)
#define NCH 16
#define SOFTMAX_SCALE 0.125f

__global__ __launch_bounds__(128)
void attn_mma(AttnParams p)
{
    extern __shared__ __align__(1024) char smem[];
    const uint32_t sb = smem_u32(smem);
    const int tid = threadIdx.x;
    const int w = tid >> 5, lid = tid & 31;
    const int q8 = lid >> 3, lr = lid & 7;
    const int h = blockIdx.y;
    const int qbase = blockIdx.x * 64;
    const int colbase = h * EDIM;

    const float alpha = *p.alpha;
    const float beta  = *p.beta;

    float osave[8][4];

    for (int st = 0; st < 2; st++) {
        const __nv_bfloat16* __restrict__ qhp = p.qh[st];
        const __nv_bfloat16* __restrict__ qlp = p.ql[st];
        const __nv_bfloat16* __restrict__ khp = p.kh[st];
        const __nv_bfloat16* __restrict__ klp = p.kl[st];
        const __nv_bfloat16* __restrict__ vhp = p.vh[st];
        const __nv_bfloat16* __restrict__ vlp = p.vl[st];

#pragma unroll
        for (int i = 0; i < 4; i++) {
            int idx = i * 128 + tid;
            int r = idx >> 3, u = idx & 7;
            uint32_t sw = SWZ((uint32_t)(r * 128 + u * 16));
            CP_ASYNC16(sb + A_KH + sw,
                       (const char*)(qhp + (size_t)(qbase + r) * DINNER + colbase) + u * 16);
            CP_ASYNC16(sb + A_KL + sw,
                       (const char*)(qlp + (size_t)(qbase + r) * DINNER + colbase) + u * 16);
        }
        CP_COMMIT();
        CP_WAIT0();
        __syncthreads();

        uint32_t qfh[4][4], qfl[4][4];
#pragma unroll
        for (int ks = 0; ks < 4; ks++) {
            uint32_t off = SWZ((uint32_t)(
                (w * 16 + lr + (q8 & 1) * 8) * 128 + ks * 32 + (q8 >> 1) * 16));
            ldsm4(qfh[ks], sb + A_KH + off);
            ldsm4(qfl[ks], sb + A_KL + off);
        }
        __syncthreads();

        float o[8][4];
#pragma unroll
        for (int t = 0; t < 8; t++)
#pragma unroll
            for (int i = 0; i < 4; i++) o[t][i] = 0.f;
        float m0r = -INFINITY, m1r = -INFINITY;
        float l0 = 0.f, l1 = 0.f;

#define LOAD_KV(cchunk) do { \
            const uint32_t stg_ = sb + ((cchunk) & 1) * ATT_STAGE; \
            const int s0_ = (cchunk) * 64; \
            _Pragma("unroll") \
            for (int i_ = 0; i_ < 4; i_++) { \
                int idx_ = i_ * 128 + tid; \
                int r_ = idx_ >> 3, u_ = idx_ & 7; \
                uint32_t sw_ = SWZ((uint32_t)(r_ * 128 + u_ * 16)); \
                if (s0_ + r_ < SEQ_S) { \
                    const size_t go_ = (size_t)(s0_ + r_) * DINNER + colbase; \
                    CP_ASYNC16(stg_ + A_KH + sw_, (const char*)(khp + go_) + u_ * 16); \
                    CP_ASYNC16(stg_ + A_KL + sw_, (const char*)(klp + go_) + u_ * 16); \
                    CP_ASYNC16(stg_ + A_VH + sw_, (const char*)(vhp + go_) + u_ * 16); \
                    CP_ASYNC16(stg_ + A_VL + sw_, (const char*)(vlp + go_) + u_ * 16); \
                } else { \
                    STS_ZERO16(stg_ + A_KH + sw_); \
                    STS_ZERO16(stg_ + A_KL + sw_); \
                    STS_ZERO16(stg_ + A_VH + sw_); \
                    STS_ZERO16(stg_ + A_VL + sw_); \
                } \
            } \
            CP_COMMIT(); \
        } while (0)

        LOAD_KV(0);

        for (int cc = 0; cc < NCH; cc++) {
            __syncthreads();
            if (cc + 1 < NCH) { LOAD_KV(cc + 1); } else { CP_COMMIT(); }
            CP_WAIT1();
            __syncthreads();
            const uint32_t stg = sb + (cc & 1) * ATT_STAGE;

            float s[8][4];
#pragma unroll
            for (int t = 0; t < 8; t++)
#pragma unroll
                for (int i = 0; i < 4; i++) s[t][i] = 0.f;

#pragma unroll
            for (int ks = 0; ks < 4; ks++) {
                uint32_t bh[8][2], bl[8][2];
#pragma unroll
                for (int njp = 0; njp < 4; njp++) {
                    uint32_t off = SWZ((uint32_t)(
                        (njp * 16 + lr + (q8 >> 1) * 8) * 128 + ks * 32 + (q8 & 1) * 16));
                    uint32_t t0[4], t1[4];
                    ldsm4(t0, stg + A_KH + off);
                    ldsm4(t1, stg + A_KL + off);
                    bh[2 * njp][0] = t0[0]; bh[2 * njp][1] = t0[1];
                    bh[2 * njp + 1][0] = t0[2]; bh[2 * njp + 1][1] = t0[3];
                    bl[2 * njp][0] = t1[0]; bl[2 * njp][1] = t1[1];
                    bl[2 * njp + 1][0] = t1[2]; bl[2 * njp + 1][1] = t1[3];
                }
#pragma unroll
                for (int t = 0; t < 8; t++) {
                    mma16816(s[t], qfh[ks], bh[t][0], bh[t][1]);
                    mma16816(s[t], qfh[ks], bl[t][0], bl[t][1]);
                    mma16816(s[t], qfl[ks], bh[t][0], bh[t][1]);
                }
            }

            if (cc == NCH - 1) {
#pragma unroll
                for (int t = 5; t < 8; t++)
#pragma unroll
                    for (int i = 0; i < 4; i++) s[t][i] = -1e30f;
            }

            float ml0 = -1e30f, ml1 = -1e30f;
#pragma unroll
            for (int t = 0; t < 8; t++) {
                ml0 = fmaxf(ml0, fmaxf(s[t][0], s[t][1]));
                ml1 = fmaxf(ml1, fmaxf(s[t][2], s[t][3]));
            }
            ml0 = fmaxf(ml0, __shfl_xor_sync(0xffffffffu, ml0, 1));
            ml0 = fmaxf(ml0, __shfl_xor_sync(0xffffffffu, ml0, 2));
            ml1 = fmaxf(ml1, __shfl_xor_sync(0xffffffffu, ml1, 1));
            ml1 = fmaxf(ml1, __shfl_xor_sync(0xffffffffu, ml1, 2));

            float mn0 = fmaxf(m0r, ml0), mn1 = fmaxf(m1r, ml1);
            float c0 = __expf((m0r - mn0) * SOFTMAX_SCALE);
            float c1 = __expf((m1r - mn1) * SOFTMAX_SCALE);
            m0r = mn0; m1r = mn1;
            l0 *= c0; l1 *= c1;
#pragma unroll
            for (int t = 0; t < 8; t++) {
                o[t][0] *= c0; o[t][1] *= c0;
                o[t][2] *= c1; o[t][3] *= c1;
            }
#pragma unroll
            for (int t = 0; t < 8; t++) {
                float p0 = __expf((s[t][0] - mn0) * SOFTMAX_SCALE);
                float p1 = __expf((s[t][1] - mn0) * SOFTMAX_SCALE);
                float p2 = __expf((s[t][2] - mn1) * SOFTMAX_SCALE);
                float p3 = __expf((s[t][3] - mn1) * SOFTMAX_SCALE);
                l0 += p0 + p1; l1 += p2 + p3;
                s[t][0] = p0; s[t][1] = p1; s[t][2] = p2; s[t][3] = p3;
            }

#pragma unroll
            for (int ks = 0; ks < 4; ks++) {
                uint32_t pah[4], pal[4];
                pack_split(s[2 * ks][0],     s[2 * ks][1],     pah[0], pal[0]);
                pack_split(s[2 * ks][2],     s[2 * ks][3],     pah[1], pal[1]);
                pack_split(s[2 * ks + 1][0], s[2 * ks + 1][1], pah[2], pal[2]);
                pack_split(s[2 * ks + 1][2], s[2 * ks + 1][3], pah[3], pal[3]);
#pragma unroll
                for (int ep = 0; ep < 4; ep++) {
                    uint32_t off = SWZ((uint32_t)(
                        (ks * 16 + lr + (q8 & 1) * 8) * 128 + ep * 32 + (q8 >> 1) * 16));
                    uint32_t tv0[4], tv1[4];
                    ldsm4t(tv0, stg + A_VH + off);
                    ldsm4t(tv1, stg + A_VL + off);
                    mma16816(o[2 * ep],     pah, tv0[0], tv0[1]);
                    mma16816(o[2 * ep],     pah, tv1[0], tv1[1]);
                    mma16816(o[2 * ep],     pal, tv0[0], tv0[1]);
                    mma16816(o[2 * ep + 1], pah, tv0[2], tv0[3]);
                    mma16816(o[2 * ep + 1], pah, tv1[2], tv1[3]);
                    mma16816(o[2 * ep + 1], pal, tv0[2], tv0[3]);
                }
            }
        }

        l0 += __shfl_xor_sync(0xffffffffu, l0, 1);
        l0 += __shfl_xor_sync(0xffffffffu, l0, 2);
        l1 += __shfl_xor_sync(0xffffffffu, l1, 1);
        l1 += __shfl_xor_sync(0xffffffffu, l1, 2);
        float wgt = (st == 0) ? alpha : beta;
        float f0 = wgt / l0, f1 = wgt / l1;
        if (st == 0) {
#pragma unroll
            for (int t = 0; t < 8; t++) {
                osave[t][0] = o[t][0] * f0; osave[t][1] = o[t][1] * f0;
                osave[t][2] = o[t][2] * f1; osave[t][3] = o[t][3] * f1;
            }
        } else {
#pragma unroll
            for (int t = 0; t < 8; t++) {
                osave[t][0] += o[t][0] * f0; osave[t][1] += o[t][1] * f0;
                osave[t][2] += o[t][2] * f1; osave[t][3] += o[t][3] * f1;
            }
        }
        __syncthreads();
    }

    // ---- write combined output as fp16 single ----
    const int r0 = qbase + w * 16 + (lid >> 2);
#pragma unroll
    for (int t = 0; t < 8; t++) {
        int col = colbase + t * 8 + (lid & 3) * 2;
        __half2 h0 = __floats2half2_rn(osave[t][0], osave[t][1]);
        __half2 h1 = __floats2half2_rn(osave[t][2], osave[t][3]);
        *(uint32_t*)(p.of + (size_t)r0 * DINNER + col) = *reinterpret_cast<uint32_t*>(&h0);
        *(uint32_t*)(p.of + (size_t)(r0 + 8) * DINNER + col) = *reinterpret_cast<uint32_t*>(&h1);
    }
}

// ---------------------------------------------------------------------------
// Launch
// ---------------------------------------------------------------------------
extern "C" void kernel_launch(void* const* d_in, const int* in_sizes, int n_in,
                              void* d_out, int out_size)
{
    const float* target = (const float*)d_in[0];
    const float* source = (const float*)d_in[1];
    const float* value  = (const float*)d_in[2];
    const float* Wq_s = (const float*)d_in[3];  const float* bq_s = (const float*)d_in[4];
    const float* Wk_s = (const float*)d_in[5];  const float* bk_s = (const float*)d_in[6];
    const float* Wv_s = (const float*)d_in[7];  const float* bv_s = (const float*)d_in[8];
    const float* Wq_l = (const float*)d_in[9];  const float* bq_l = (const float*)d_in[10];
    const float* Wk_l = (const float*)d_in[11]; const float* bk_l = (const float*)d_in[12];
    const float* Wv_l = (const float*)d_in[13]; const float* bv_l = (const float*)d_in[14];
    const float* Wo   = (const float*)d_in[15]; const float* bo   = (const float*)d_in[16];
    const float* alpha = (const float*)d_in[17];
    const float* beta  = (const float*)d_in[18];
    float* out = (float*)d_out;

    __nv_bfloat16 *th, *tl, *sh, *sl, *vh, *vl2;
    cudaGetSymbolAddress((void**)&th,  g_th);  cudaGetSymbolAddress((void**)&tl,  g_tl);
    cudaGetSymbolAddress((void**)&sh,  g_sh);  cudaGetSymbolAddress((void**)&sl,  g_sl);
    cudaGetSymbolAddress((void**)&vh,  g_vh);  cudaGetSymbolAddress((void**)&vl2, g_vl2);
    __half *af16, *wof16;
    cudaGetSymbolAddress((void**)&af16,  g_af16);
    cudaGetSymbolAddress((void**)&wof16, g_wof16);

    __nv_bfloat16 *qsh, *qsl, *qlh, *qll, *ksh, *ksl, *vsh, *vsl, *klh, *kll, *vlh, *vll;
    cudaGetSymbolAddress((void**)&qsh, g_qsh); cudaGetSymbolAddress((void**)&qsl, g_qsl);
    cudaGetSymbolAddress((void**)&qlh, g_qlh); cudaGetSymbolAddress((void**)&qll, g_qll);
    cudaGetSymbolAddress((void**)&ksh, g_ksh); cudaGetSymbolAddress((void**)&ksl, g_ksl);
    cudaGetSymbolAddress((void**)&vsh, g_vsh); cudaGetSymbolAddress((void**)&vsl, g_vsl);
    cudaGetSymbolAddress((void**)&klh, g_klh); cudaGetSymbolAddress((void**)&kll, g_kll);
    cudaGetSymbolAddress((void**)&vlh, g_vlh); cudaGetSymbolAddress((void**)&vll, g_vll);

    __nv_bfloat16 *wqsh, *wqsl, *wqlh, *wqll, *wksh, *wksl, *wvsh, *wvsl;
    __nv_bfloat16 *wklh, *wkll, *wvlh, *wvll;
    cudaGetSymbolAddress((void**)&wqsh, g_wqsh); cudaGetSymbolAddress((void**)&wqsl, g_wqsl);
    cudaGetSymbolAddress((void**)&wqlh, g_wqlh); cudaGetSymbolAddress((void**)&wqll, g_wqll);
    cudaGetSymbolAddress((void**)&wksh, g_wksh); cudaGetSymbolAddress((void**)&wksl, g_wksl);
    cudaGetSymbolAddress((void**)&wvsh, g_wvsh); cudaGetSymbolAddress((void**)&wvsl, g_wvsl);
    cudaGetSymbolAddress((void**)&wklh, g_wklh); cudaGetSymbolAddress((void**)&wkll, g_wkll);
    cudaGetSymbolAddress((void**)&wvlh, g_wvlh); cudaGetSymbolAddress((void**)&wvll, g_wvll);

    cudaFuncSetAttribute(gemm_proj,    cudaFuncAttributeMaxDynamicSharedMemorySize, PROJ_SMEM);
    cudaFuncSetAttribute(gemm_out_f16, cudaFuncAttributeMaxDynamicSharedMemorySize, OUTF_SMEM);
    cudaFuncSetAttribute(attn_mma,     cudaFuncAttributeMaxDynamicSharedMemorySize, ATT_SMEM);

    // --- merged prepass (Wo -> fp16 single; others -> bf16 hi/lo) ---
    {
        PrepassParams pp = {};
        const float* Ws[7]   = {Wq_s, Wq_l, Wk_s, Wv_s, Wk_l, Wv_l, Wo};
        __nv_bfloat16* Ths[7] = {wqsh, wqlh, wksh, wvsh, wklh, wvlh,
                                 (__nv_bfloat16*)wof16};
        __nv_bfloat16* Tls[7] = {wqsl, wqll, wksl, wvsl, wkll, wvll,
                                 (__nv_bfloat16*)wof16};
        const int Ks[7] = {DMODEL, DMODEL, DLLM, DLLM, DLLM, DLLM, DINNER};
        const int Ns[7] = {DINNER, DINNER, DINNER, DINNER, DINNER, DINNER, DLLM};
        int acc = 0;
        pp.t_ofs[0] = 0;
        for (int i = 0; i < 7; i++) {
            pp.W[i] = Ws[i]; pp.Th[i] = Ths[i]; pp.Tl[i] = Tls[i];
            pp.K[i] = Ks[i]; pp.N[i] = Ns[i];
            acc += (Ks[i] / 32) * (Ns[i] / 32);
            pp.t_ofs[i + 1] = acc;
        }
        pp.total_trans = acc;
        pp.X[0] = target; pp.H[0] = th; pp.L[0] = tl;
        pp.X[1] = source; pp.H[1] = sh; pp.L[1] = sl;
        pp.X[2] = value;  pp.H[2] = vh; pp.L[2] = vl2;
        pp.s_ofs[0] = 0;
        pp.s_ofs[1] = (BL * DMODEL) / 16384;
        pp.s_ofs[2] = pp.s_ofs[1] + (SEQ_S * DLLM) / 16384;
        pp.s_ofs[3] = pp.s_ofs[2] + (SEQ_S * DLLM) / 16384;
        prepass<<<pp.total_trans + pp.s_ofs[3], 256>>>(pp);
    }

    // --- all 6 projection GEMMs, one flat launch (TN=64, 2 CTAs/SM) ---
    {
        GemmJobs p = {};
        const __nv_bfloat16* Ahs[6] = {th, th, sh, vh, sh, vh};
        const __nv_bfloat16* Als[6] = {tl, tl, sl, vl2, sl, vl2};
        const __nv_bfloat16* Bhs[6] = {wqsh, wqlh, wksh, wvsh, wklh, wvlh};
        const __nv_bfloat16* Bls[6] = {wqsl, wqll, wksl, wvsl, wkll, wvll};
        const float* bs[6] = {bq_s, bq_l, bk_s, bv_s, bk_l, bv_l};
        __nv_bfloat16* Chs[6] = {qsh, qlh, ksh, vsh, klh, vlh};
        __nv_bfloat16* Cls[6] = {qsl, qll, ksl, vsl, kll, vll};
        const int Ms[6] = {BL, BL, SEQ_S, SEQ_S, SEQ_S, SEQ_S};
        const int Ks2[6] = {DMODEL, DMODEL, DLLM, DLLM, DLLM, DLLM};
        int acc = 0;
        p.ofs[0] = 0;
        for (int i = 0; i < 6; i++) {
            p.Ah[i] = Ahs[i]; p.Al[i] = Als[i]; p.Bh[i] = Bhs[i]; p.Bl[i] = Bls[i];
            p.bias[i] = bs[i]; p.Ch[i] = Chs[i]; p.Cl[i] = Cls[i];
            p.M[i] = Ms[i]; p.K[i] = Ks2[i];
            acc += 16 * ((Ms[i] + 127) / 128);
            p.ofs[i + 1] = acc;
        }
        gemm_proj<<<acc, 256, PROJ_SMEM>>>(p);
    }

    // --- fused dual-stream flash attention (fp16 output) ---
    {
        AttnParams ap = {};
        ap.qh[0] = qsh; ap.ql[0] = qsl; ap.kh[0] = ksh; ap.kl[0] = ksl;
        ap.vh[0] = vsh; ap.vl[0] = vsl;
        ap.qh[1] = qlh; ap.ql[1] = qll; ap.kh[1] = klh; ap.kl[1] = kll;
        ap.vh[1] = vlh; ap.vl[1] = vll;
        ap.alpha = alpha; ap.beta = beta;
        ap.of = af16;
        dim3 g(BL / 64, NHEAD);
        attn_mma<<<g, 128, ATT_SMEM>>>(ap);
    }

    // --- output projection: single-term fp16 ---
    {
        dim3 g(DLLM / 128, BL / 128);
        gemm_out_f16<<<g, 256, OUTF_SMEM>>>(af16, wof16, bo, out);
    }
}

// round 10
// speedup vs baseline: 2.1987x; 1.6975x over previous
#include <cuda_runtime.h>
#include <cuda_fp16.h>
#include <math.h>
#include <stdint.h>

#define BL     8192
#define DMODEL 1024
#define DLLM   4096
#define DINNER 1024
#define SEQ_S  1000
#define NHEAD  16
#define EDIM   64

// ---------------------------------------------------------------------------
// Portable PTX helpers (base compute_103 target — NO tcgen05)
// ---------------------------------------------------------------------------
__device__ __forceinline__ uint32_t smem_u32(const void* p) {
    uint32_t a;
    asm("{ .reg .u64 t; cvta.to.shared.u64 t, %1; cvt.u32.u64 %0, t; }"
        : "=r"(a) : "l"(p));
    return a;
}

#define SWZ(o) ((o) ^ (((o) >> 3) & 0x70))

#define CP_ASYNC16(dst, src) \
    asm volatile("cp.async.cg.shared.global [%0], [%1], 16;\n" :: "r"(dst), "l"(src))
#define CP_COMMIT() asm volatile("cp.async.commit_group;\n" ::: "memory")
#define CP_WAIT1()  asm volatile("cp.async.wait_group 1;\n" ::: "memory")
#define CP_WAIT0()  asm volatile("cp.async.wait_group 0;\n" ::: "memory")
#define STS_ZERO16(addr) \
    asm volatile("st.shared.v4.b32 [%0], {%1,%1,%1,%1};\n" :: "r"(addr), "r"(0u) : "memory")

__device__ __forceinline__ void ldsm4(uint32_t* r, uint32_t a) {
    asm volatile("ldmatrix.sync.aligned.m8n8.x4.shared.b16 {%0,%1,%2,%3}, [%4];\n"
        : "=r"(r[0]), "=r"(r[1]), "=r"(r[2]), "=r"(r[3]) : "r"(a));
}
__device__ __forceinline__ void ldsm4t(uint32_t* r, uint32_t a) {
    asm volatile("ldmatrix.sync.aligned.m8n8.x4.trans.shared.b16 {%0,%1,%2,%3}, [%4];\n"
        : "=r"(r[0]), "=r"(r[1]), "=r"(r[2]), "=r"(r[3]) : "r"(a));
}
__device__ __forceinline__ void mma16816h(float* c, const uint32_t* a,
                                          uint32_t b0, uint32_t b1) {
    asm volatile(
        "mma.sync.aligned.m16n8k16.row.col.f32.f16.f16.f32 "
        "{%0,%1,%2,%3}, {%4,%5,%6,%7}, {%8,%9}, {%0,%1,%2,%3};\n"
        : "+f"(c[0]), "+f"(c[1]), "+f"(c[2]), "+f"(c[3])
        : "r"(a[0]), "r"(a[1]), "r"(a[2]), "r"(a[3]), "r"(b0), "r"(b1));
}

// ---------------------------------------------------------------------------
// Scratch (device globals — no allocation allowed) — ALL fp16 single
// ---------------------------------------------------------------------------
__device__ __half g_tf[BL * DMODEL];
__device__ __half g_sf[SEQ_S * DLLM];
__device__ __half g_vf[SEQ_S * DLLM];
__device__ __half g_qs[BL * DINNER], g_ql[BL * DINNER];
__device__ __half g_ks[SEQ_S * DINNER], g_vs[SEQ_S * DINNER];
__device__ __half g_kl[SEQ_S * DINNER], g_vl[SEQ_S * DINNER];
__device__ __half g_af16[BL * DINNER];
__device__ __half g_wqs[DINNER * DMODEL], g_wql[DINNER * DMODEL];
__device__ __half g_wks[DINNER * DLLM],   g_wvs[DINNER * DLLM];
__device__ __half g_wkl[DINNER * DLLM],   g_wvl[DINNER * DLLM];
__device__ __half g_wo[DLLM * DINNER];

// ---------------------------------------------------------------------------
// Merged prepass: 7 fp32->fp16 transposes + 3 fp32->fp16 flat converts.
// ---------------------------------------------------------------------------
struct PrepassParams {
    const float* W[7];
    __half* T[7];
    int K[7], N[7];
    int t_ofs[8];
    const float* X[3];
    __half* H[3];
    int s_ofs[4];
    int total_trans;
};

__global__ __launch_bounds__(256)
void prepass(PrepassParams p)
{
    __shared__ float tsm[32][33];
    const int bid = blockIdx.x;
    if (bid < p.total_trans) {
        int w = 0;
        while (bid >= p.t_ofs[w + 1]) w++;
        const int t = bid - p.t_ofs[w];
        const int K = p.K[w], N = p.N[w];
        const int tiles_x = N >> 5;
        const int n0 = (t % tiles_x) << 5, k0 = (t / tiles_x) << 5;
        const float* __restrict__ W = p.W[w];
        __half* __restrict__ T = p.T[w];
        const int tx = threadIdx.x & 31, ty = threadIdx.x >> 5;
#pragma unroll
        for (int i = 0; i < 32; i += 8)
            tsm[ty + i][tx] = W[(size_t)(k0 + ty + i) * N + n0 + tx];
        __syncthreads();
#pragma unroll
        for (int i = 0; i < 32; i += 8) {
            int n = n0 + ty + i;
            T[(size_t)n * K + k0 + tx] = __float2half(tsm[tx][ty + i]);
        }
    } else {
        const int sb = bid - p.total_trans;
        int a = 0;
        while (sb >= p.s_ofs[a + 1]) a++;
        const int rel = sb - p.s_ofs[a];
        const float* __restrict__ X = p.X[a];
        __half* __restrict__ H = p.H[a];
#pragma unroll
        for (int i = 0; i < 16; i++) {
            int idx = rel * 16384 + (i * 256 + threadIdx.x) * 4;
            float4 v = *(const float4*)(X + idx);
            __half2 h01 = __floats2half2_rn(v.x, v.y);
            __half2 h23 = __floats2half2_rn(v.z, v.w);
            uint2 o;
            o.x = *reinterpret_cast<uint32_t*>(&h01);
            o.y = *reinterpret_cast<uint32_t*>(&h23);
            *(uint2*)(H + idx) = o;
        }
    }
}

// ---------------------------------------------------------------------------
// fp16 single-term GEMM, 128x128 tile, BK=64, 3-stage (96KB) -> 2 CTAs/SM.
// Shared structure for projections (fp16 out, flat jobs) and output (fp32).
// ---------------------------------------------------------------------------
#define F_A 0
#define F_B 16384
#define FSTG 32768
#define GEMM_SMEM (3 * FSTG)   // 96 KB

// ---- projection variant: 6 jobs, N = DINNER, fp16 epilogue, M guarded ----
struct ProjJobs {
    const __half *A[6], *B[6];
    const float* bias[6];
    __half* C[6];
    int M[6], K[6];
    int ofs[7];
};

__global__ __launch_bounds__(256, 2)
void gemm_proj_f16(ProjJobs p)
{
    extern __shared__ __align__(1024) char smem[];
    const int bid = blockIdx.x;
    int z = 0;
    while (bid >= p.ofs[z + 1]) z++;
    const int rel = bid - p.ofs[z];
    const int bx = rel & 7, by = rel >> 3;        // gx = DINNER/128 = 8
    const int M = p.M[z], K = p.K[z];
    const int N = DINNER;

    const __half* __restrict__ A = p.A[z];
    const __half* __restrict__ B = p.B[z];

    const int tid = threadIdx.x;
    const int wid = tid >> 5, lid = tid & 31;
    const int wm = wid & 3, wn = wid >> 2;
    const int m0 = by * 128, n0 = bx * 128;
    const uint32_t sb = smem_u32(smem);
    const int NC = K >> 6;

    float c[2][8][4];
#pragma unroll
    for (int i = 0; i < 2; i++)
#pragma unroll
        for (int j = 0; j < 8; j++)
#pragma unroll
            for (int q = 0; q < 4; q++) c[i][j][q] = 0.f;

    auto load_stage = [&](int cchunk) {
        const uint32_t st_ = sb + (cchunk % 3) * FSTG;
        const int k0_ = cchunk << 6;
#pragma unroll
        for (int i_ = 0; i_ < 4; i_++) {
            int idx_ = i_ * 256 + tid;
            int r_ = idx_ >> 3, u_ = idx_ & 7;
            uint32_t sw_ = SWZ((uint32_t)(r_ * 128 + u_ * 16));
            int gm_ = m0 + r_;
            if (gm_ < M)
                CP_ASYNC16(st_ + F_A + sw_, (const char*)(A + (size_t)gm_ * K + k0_) + u_ * 16);
            else
                STS_ZERO16(st_ + F_A + sw_);
            CP_ASYNC16(st_ + F_B + sw_, (const char*)(B + (size_t)(n0 + r_) * K + k0_) + u_ * 16);
        }
        CP_COMMIT();
    };

    load_stage(0);
    load_stage(1);

    const int q8 = lid >> 3, lr = lid & 7;

    for (int cc = 0; cc < NC; cc++) {
        CP_WAIT1();
        __syncthreads();
        if (cc + 2 < NC) { load_stage(cc + 2); } else { CP_COMMIT(); }

        const uint32_t st = sb + (cc % 3) * FSTG;
#pragma unroll
        for (int ks = 0; ks < 4; ks++) {
            const int kb = ks * 32;
            uint32_t ah[2][4], bh[8][2];
#pragma unroll
            for (int mi = 0; mi < 2; mi++) {
                uint32_t off = SWZ((uint32_t)(
                    (wm * 32 + mi * 16 + lr + (q8 & 1) * 8) * 128 + kb + (q8 >> 1) * 16));
                ldsm4(ah[mi], st + F_A + off);
            }
#pragma unroll
            for (int njp = 0; njp < 4; njp++) {
                uint32_t off = SWZ((uint32_t)(
                    (wn * 64 + njp * 16 + lr + (q8 >> 1) * 8) * 128 + kb + (q8 & 1) * 16));
                uint32_t t0[4];
                ldsm4(t0, st + F_B + off);
                bh[2 * njp][0] = t0[0]; bh[2 * njp][1] = t0[1];
                bh[2 * njp + 1][0] = t0[2]; bh[2 * njp + 1][1] = t0[3];
            }
#pragma unroll
            for (int mi = 0; mi < 2; mi++)
#pragma unroll
                for (int nj = 0; nj < 8; nj++)
                    mma16816h(c[mi][nj], ah[mi], bh[nj][0], bh[nj][1]);
        }
    }

    const int lr4 = lid >> 2, lc = (lid & 3) * 2;
    const float* __restrict__ bias = p.bias[z];
    __half* __restrict__ C = p.C[z];
#pragma unroll
    for (int mi = 0; mi < 2; mi++) {
        int row = m0 + wm * 32 + mi * 16 + lr4;
#pragma unroll
        for (int nj = 0; nj < 8; nj++) {
            int col = n0 + wn * 64 + nj * 8 + lc;
            float2 b2 = *(const float2*)(bias + col);
            __half2 h0 = __floats2half2_rn(c[mi][nj][0] + b2.x, c[mi][nj][1] + b2.y);
            __half2 h1 = __floats2half2_rn(c[mi][nj][2] + b2.x, c[mi][nj][3] + b2.y);
            if (row < M)
                *(uint32_t*)(C + (size_t)row * N + col) = *reinterpret_cast<uint32_t*>(&h0);
            if (row + 8 < M)
                *(uint32_t*)(C + (size_t)(row + 8) * N + col) = *reinterpret_cast<uint32_t*>(&h1);
        }
    }
}

// ---- output variant: fixed dims, fp32 epilogue (R9 measured 174us) ----
__global__ __launch_bounds__(256, 2)
void gemm_out_f16(const __half* __restrict__ A, const __half* __restrict__ B,
                  const float* __restrict__ bias, float* __restrict__ C)
{
    extern __shared__ __align__(1024) char smem[];
    const int tid = threadIdx.x;
    const int wid = tid >> 5, lid = tid & 31;
    const int wm = wid & 3, wn = wid >> 2;
    const int m0 = blockIdx.y * 128, n0 = blockIdx.x * 128;
    const uint32_t sb = smem_u32(smem);
    const int K = DINNER, N = DLLM;
    const int NC = K >> 6;

    float c[2][8][4];
#pragma unroll
    for (int i = 0; i < 2; i++)
#pragma unroll
        for (int j = 0; j < 8; j++)
#pragma unroll
            for (int q = 0; q < 4; q++) c[i][j][q] = 0.f;

    auto load_stage = [&](int cchunk) {
        const uint32_t st_ = sb + (cchunk % 3) * FSTG;
        const int k0_ = cchunk << 6;
#pragma unroll
        for (int i_ = 0; i_ < 4; i_++) {
            int idx_ = i_ * 256 + tid;
            int r_ = idx_ >> 3, u_ = idx_ & 7;
            uint32_t sw_ = SWZ((uint32_t)(r_ * 128 + u_ * 16));
            CP_ASYNC16(st_ + F_A + sw_, (const char*)(A + (size_t)(m0 + r_) * K + k0_) + u_ * 16);
            CP_ASYNC16(st_ + F_B + sw_, (const char*)(B + (size_t)(n0 + r_) * K + k0_) + u_ * 16);
        }
        CP_COMMIT();
    };

    load_stage(0);
    load_stage(1);

    const int q8 = lid >> 3, lr = lid & 7;

    for (int cc = 0; cc < NC; cc++) {
        CP_WAIT1();
        __syncthreads();
        if (cc + 2 < NC) { load_stage(cc + 2); } else { CP_COMMIT(); }

        const uint32_t st = sb + (cc % 3) * FSTG;
#pragma unroll
        for (int ks = 0; ks < 4; ks++) {
            const int kb = ks * 32;
            uint32_t ah[2][4], bh[8][2];
#pragma unroll
            for (int mi = 0; mi < 2; mi++) {
                uint32_t off = SWZ((uint32_t)(
                    (wm * 32 + mi * 16 + lr + (q8 & 1) * 8) * 128 + kb + (q8 >> 1) * 16));
                ldsm4(ah[mi], st + F_A + off);
            }
#pragma unroll
            for (int njp = 0; njp < 4; njp++) {
                uint32_t off = SWZ((uint32_t)(
                    (wn * 64 + njp * 16 + lr + (q8 >> 1) * 8) * 128 + kb + (q8 & 1) * 16));
                uint32_t t0[4];
                ldsm4(t0, st + F_B + off);
                bh[2 * njp][0] = t0[0]; bh[2 * njp][1] = t0[1];
                bh[2 * njp + 1][0] = t0[2]; bh[2 * njp + 1][1] = t0[3];
            }
#pragma unroll
            for (int mi = 0; mi < 2; mi++)
#pragma unroll
                for (int nj = 0; nj < 8; nj++)
                    mma16816h(c[mi][nj], ah[mi], bh[nj][0], bh[nj][1]);
        }
    }

    const int lr4 = lid >> 2, lc = (lid & 3) * 2;
#pragma unroll
    for (int mi = 0; mi < 2; mi++) {
        int row = m0 + wm * 32 + mi * 16 + lr4;
#pragma unroll
        for (int nj = 0; nj < 8; nj++) {
            int col = n0 + wn * 64 + nj * 8 + lc;
            float2 b2 = *(const float2*)(bias + col);
            *(float2*)(C + (size_t)row * N + col) =
                make_float2(c[mi][nj][0] + b2.x, c[mi][nj][1] + b2.y);
            *(float2*)(C + (size_t)(row + 8) * N + col) =
                make_float2(c[mi][nj][2] + b2.x, c[mi][nj][3] + b2.y);
        }
    }
}

// ---------------------------------------------------------------------------
// HMMA flash attention, dual-stream, single-term fp16 (QK and PV), 2-stage.
// Block = 64 queries x 1 head, 4 warps. Stage = K 8KB + V 8KB = 16KB.
// ---------------------------------------------------------------------------
struct AttnParams {
    const __half *q[2], *k[2], *v[2];
    const float *alpha, *beta;
    __half* of;
};

#define ATT_STAGE 16384
#define A_K 0
#define A_V 8192
#define ATT_SMEM (2 * ATT_STAGE)   // 32 KB
#define NCH 16
#define SOFTMAX_SCALE 0.125f

__global__ __launch_bounds__(128)
void attn_mma(AttnParams p)
{
    extern __shared__ __align__(1024) char smem[];
    const uint32_t sb = smem_u32(smem);
    const int tid = threadIdx.x;
    const int w = tid >> 5, lid = tid & 31;
    const int q8 = lid >> 3, lr = lid & 7;
    const int h = blockIdx.y;
    const int qbase = blockIdx.x * 64;
    const int colbase = h * EDIM;

    const float alpha = *p.alpha;
    const float beta  = *p.beta;

    float osave[8][4];

    for (int st = 0; st < 2; st++) {
        const __half* __restrict__ qp = p.q[st];
        const __half* __restrict__ kp = p.k[st];
        const __half* __restrict__ vp = p.v[st];

        // ---- stage Q (64x64 fp16 = 8KB) into A_K region of stage 0 ----
#pragma unroll
        for (int i = 0; i < 4; i++) {
            int idx = i * 128 + tid;
            int r = idx >> 3, u = idx & 7;
            uint32_t sw = SWZ((uint32_t)(r * 128 + u * 16));
            CP_ASYNC16(sb + A_K + sw,
                       (const char*)(qp + (size_t)(qbase + r) * DINNER + colbase) + u * 16);
        }
        CP_COMMIT();
        CP_WAIT0();
        __syncthreads();

        uint32_t qf[4][4];
#pragma unroll
        for (int ks = 0; ks < 4; ks++) {
            uint32_t off = SWZ((uint32_t)(
                (w * 16 + lr + (q8 & 1) * 8) * 128 + ks * 32 + (q8 >> 1) * 16));
            ldsm4(qf[ks], sb + A_K + off);
        }
        __syncthreads();

        float o[8][4];
#pragma unroll
        for (int t = 0; t < 8; t++)
#pragma unroll
            for (int i = 0; i < 4; i++) o[t][i] = 0.f;
        float m0r = -INFINITY, m1r = -INFINITY;
        float l0 = 0.f, l1 = 0.f;

#define LOAD_KV(cchunk) do { \
            const uint32_t stg_ = sb + ((cchunk) & 1) * ATT_STAGE; \
            const int s0_ = (cchunk) * 64; \
            _Pragma("unroll") \
            for (int i_ = 0; i_ < 4; i_++) { \
                int idx_ = i_ * 128 + tid; \
                int r_ = idx_ >> 3, u_ = idx_ & 7; \
                uint32_t sw_ = SWZ((uint32_t)(r_ * 128 + u_ * 16)); \
                if (s0_ + r_ < SEQ_S) { \
                    const size_t go_ = (size_t)(s0_ + r_) * DINNER + colbase; \
                    CP_ASYNC16(stg_ + A_K + sw_, (const char*)(kp + go_) + u_ * 16); \
                    CP_ASYNC16(stg_ + A_V + sw_, (const char*)(vp + go_) + u_ * 16); \
                } else { \
                    STS_ZERO16(stg_ + A_K + sw_); \
                    STS_ZERO16(stg_ + A_V + sw_); \
                } \
            } \
            CP_COMMIT(); \
        } while (0)

        LOAD_KV(0);

        for (int cc = 0; cc < NCH; cc++) {
            __syncthreads();
            if (cc + 1 < NCH) { LOAD_KV(cc + 1); } else { CP_COMMIT(); }
            CP_WAIT1();
            __syncthreads();
            const uint32_t stg = sb + (cc & 1) * ATT_STAGE;

            float s[8][4];
#pragma unroll
            for (int t = 0; t < 8; t++)
#pragma unroll
                for (int i = 0; i < 4; i++) s[t][i] = 0.f;

#pragma unroll
            for (int ks = 0; ks < 4; ks++) {
                uint32_t bh[8][2];
#pragma unroll
                for (int njp = 0; njp < 4; njp++) {
                    uint32_t off = SWZ((uint32_t)(
                        (njp * 16 + lr + (q8 >> 1) * 8) * 128 + ks * 32 + (q8 & 1) * 16));
                    uint32_t t0[4];
                    ldsm4(t0, stg + A_K + off);
                    bh[2 * njp][0] = t0[0]; bh[2 * njp][1] = t0[1];
                    bh[2 * njp + 1][0] = t0[2]; bh[2 * njp + 1][1] = t0[3];
                }
#pragma unroll
                for (int t = 0; t < 8; t++)
                    mma16816h(s[t], qf[ks], bh[t][0], bh[t][1]);
            }

            if (cc == NCH - 1) {
#pragma unroll
                for (int t = 5; t < 8; t++)
#pragma unroll
                    for (int i = 0; i < 4; i++) s[t][i] = -1e30f;
            }

            float ml0 = -1e30f, ml1 = -1e30f;
#pragma unroll
            for (int t = 0; t < 8; t++) {
                ml0 = fmaxf(ml0, fmaxf(s[t][0], s[t][1]));
                ml1 = fmaxf(ml1, fmaxf(s[t][2], s[t][3]));
            }
            ml0 = fmaxf(ml0, __shfl_xor_sync(0xffffffffu, ml0, 1));
            ml0 = fmaxf(ml0, __shfl_xor_sync(0xffffffffu, ml0, 2));
            ml1 = fmaxf(ml1, __shfl_xor_sync(0xffffffffu, ml1, 1));
            ml1 = fmaxf(ml1, __shfl_xor_sync(0xffffffffu, ml1, 2));

            float mn0 = fmaxf(m0r, ml0), mn1 = fmaxf(m1r, ml1);
            float c0 = __expf((m0r - mn0) * SOFTMAX_SCALE);
            float c1 = __expf((m1r - mn1) * SOFTMAX_SCALE);
            m0r = mn0; m1r = mn1;
            l0 *= c0; l1 *= c1;
#pragma unroll
            for (int t = 0; t < 8; t++) {
                o[t][0] *= c0; o[t][1] *= c0;
                o[t][2] *= c1; o[t][3] *= c1;
            }
#pragma unroll
            for (int t = 0; t < 8; t++) {
                float p0 = __expf((s[t][0] - mn0) * SOFTMAX_SCALE);
                float p1 = __expf((s[t][1] - mn0) * SOFTMAX_SCALE);
                float p2 = __expf((s[t][2] - mn1) * SOFTMAX_SCALE);
                float p3 = __expf((s[t][3] - mn1) * SOFTMAX_SCALE);
                l0 += p0 + p1; l1 += p2 + p3;
                s[t][0] = p0; s[t][1] = p1; s[t][2] = p2; s[t][3] = p3;
            }

            // ---- O += P V (single-term fp16) ----
#pragma unroll
            for (int ks = 0; ks < 4; ks++) {
                uint32_t pa[4];
                __half2 pp0 = __floats2half2_rn(s[2 * ks][0],     s[2 * ks][1]);
                __half2 pp1 = __floats2half2_rn(s[2 * ks][2],     s[2 * ks][3]);
                __half2 pp2 = __floats2half2_rn(s[2 * ks + 1][0], s[2 * ks + 1][1]);
                __half2 pp3 = __floats2half2_rn(s[2 * ks + 1][2], s[2 * ks + 1][3]);
                pa[0] = *reinterpret_cast<uint32_t*>(&pp0);
                pa[1] = *reinterpret_cast<uint32_t*>(&pp1);
                pa[2] = *reinterpret_cast<uint32_t*>(&pp2);
                pa[3] = *reinterpret_cast<uint32_t*>(&pp3);
#pragma unroll
                for (int ep = 0; ep < 4; ep++) {
                    uint32_t off = SWZ((uint32_t)(
                        (ks * 16 + lr + (q8 & 1) * 8) * 128 + ep * 32 + (q8 >> 1) * 16));
                    uint32_t tv0[4];
                    ldsm4t(tv0, stg + A_V + off);
                    mma16816h(o[2 * ep],     pa, tv0[0], tv0[1]);
                    mma16816h(o[2 * ep + 1], pa, tv0[2], tv0[3]);
                }
            }
        }

        l0 += __shfl_xor_sync(0xffffffffu, l0, 1);
        l0 += __shfl_xor_sync(0xffffffffu, l0, 2);
        l1 += __shfl_xor_sync(0xffffffffu, l1, 1);
        l1 += __shfl_xor_sync(0xffffffffu, l1, 2);
        float wgt = (st == 0) ? alpha : beta;
        float f0 = wgt / l0, f1 = wgt / l1;
        if (st == 0) {
#pragma unroll
            for (int t = 0; t < 8; t++) {
                osave[t][0] = o[t][0] * f0; osave[t][1] = o[t][1] * f0;
                osave[t][2] = o[t][2] * f1; osave[t][3] = o[t][3] * f1;
            }
        } else {
#pragma unroll
            for (int t = 0; t < 8; t++) {
                osave[t][0] += o[t][0] * f0; osave[t][1] += o[t][1] * f0;
                osave[t][2] += o[t][2] * f1; osave[t][3] += o[t][3] * f1;
            }
        }
        __syncthreads();
    }

    const int r0 = qbase + w * 16 + (lid >> 2);
#pragma unroll
    for (int t = 0; t < 8; t++) {
        int col = colbase + t * 8 + (lid & 3) * 2;
        __half2 h0 = __floats2half2_rn(osave[t][0], osave[t][1]);
        __half2 h1 = __floats2half2_rn(osave[t][2], osave[t][3]);
        *(uint32_t*)(p.of + (size_t)r0 * DINNER + col) = *reinterpret_cast<uint32_t*>(&h0);
        *(uint32_t*)(p.of + (size_t)(r0 + 8) * DINNER + col) = *reinterpret_cast<uint32_t*>(&h1);
    }
}

// ---------------------------------------------------------------------------
// Launch
// ---------------------------------------------------------------------------
extern "C" void kernel_launch(void* const* d_in, const int* in_sizes, int n_in,
                              void* d_out, int out_size)
{
    const float* target = (const float*)d_in[0];
    const float* source = (const float*)d_in[1];
    const float* value  = (const float*)d_in[2];
    const float* Wq_s = (const float*)d_in[3];  const float* bq_s = (const float*)d_in[4];
    const float* Wk_s = (const float*)d_in[5];  const float* bk_s = (const float*)d_in[6];
    const float* Wv_s = (const float*)d_in[7];  const float* bv_s = (const float*)d_in[8];
    const float* Wq_l = (const float*)d_in[9];  const float* bq_l = (const float*)d_in[10];
    const float* Wk_l = (const float*)d_in[11]; const float* bk_l = (const float*)d_in[12];
    const float* Wv_l = (const float*)d_in[13]; const float* bv_l = (const float*)d_in[14];
    const float* Wo   = (const float*)d_in[15]; const float* bo   = (const float*)d_in[16];
    const float* alpha = (const float*)d_in[17];
    const float* beta  = (const float*)d_in[18];
    float* out = (float*)d_out;

    __half *tf, *sf, *vf, *af16;
    cudaGetSymbolAddress((void**)&tf, g_tf);
    cudaGetSymbolAddress((void**)&sf, g_sf);
    cudaGetSymbolAddress((void**)&vf, g_vf);
    cudaGetSymbolAddress((void**)&af16, g_af16);

    __half *qs, *ql, *ks, *vs, *kl, *vl;
    cudaGetSymbolAddress((void**)&qs, g_qs); cudaGetSymbolAddress((void**)&ql, g_ql);
    cudaGetSymbolAddress((void**)&ks, g_ks); cudaGetSymbolAddress((void**)&vs, g_vs);
    cudaGetSymbolAddress((void**)&kl, g_kl); cudaGetSymbolAddress((void**)&vl, g_vl);

    __half *wqs, *wql, *wks, *wvs, *wkl, *wvl, *wo;
    cudaGetSymbolAddress((void**)&wqs, g_wqs); cudaGetSymbolAddress((void**)&wql, g_wql);
    cudaGetSymbolAddress((void**)&wks, g_wks); cudaGetSymbolAddress((void**)&wvs, g_wvs);
    cudaGetSymbolAddress((void**)&wkl, g_wkl); cudaGetSymbolAddress((void**)&wvl, g_wvl);
    cudaGetSymbolAddress((void**)&wo,  g_wo);

    cudaFuncSetAttribute(gemm_proj_f16, cudaFuncAttributeMaxDynamicSharedMemorySize, GEMM_SMEM);
    cudaFuncSetAttribute(gemm_out_f16,  cudaFuncAttributeMaxDynamicSharedMemorySize, GEMM_SMEM);
    cudaFuncSetAttribute(attn_mma,      cudaFuncAttributeMaxDynamicSharedMemorySize, ATT_SMEM);

    // --- merged prepass (all fp32 -> fp16) ---
    {
        PrepassParams pp = {};
        const float* Ws[7] = {Wq_s, Wq_l, Wk_s, Wv_s, Wk_l, Wv_l, Wo};
        __half* Ts[7] = {wqs, wql, wks, wvs, wkl, wvl, wo};
        const int Ks[7] = {DMODEL, DMODEL, DLLM, DLLM, DLLM, DLLM, DINNER};
        const int Ns[7] = {DINNER, DINNER, DINNER, DINNER, DINNER, DINNER, DLLM};
        int acc = 0;
        pp.t_ofs[0] = 0;
        for (int i = 0; i < 7; i++) {
            pp.W[i] = Ws[i]; pp.T[i] = Ts[i];
            pp.K[i] = Ks[i]; pp.N[i] = Ns[i];
            acc += (Ks[i] / 32) * (Ns[i] / 32);
            pp.t_ofs[i + 1] = acc;
        }
        pp.total_trans = acc;
        pp.X[0] = target; pp.H[0] = tf;
        pp.X[1] = source; pp.H[1] = sf;
        pp.X[2] = value;  pp.H[2] = vf;
        pp.s_ofs[0] = 0;
        pp.s_ofs[1] = (BL * DMODEL) / 16384;
        pp.s_ofs[2] = pp.s_ofs[1] + (SEQ_S * DLLM) / 16384;
        pp.s_ofs[3] = pp.s_ofs[2] + (SEQ_S * DLLM) / 16384;
        prepass<<<pp.total_trans + pp.s_ofs[3], 256>>>(pp);
    }

    // --- 6 projection GEMMs, one flat launch (fp16 single-term) ---
    {
        ProjJobs p = {};
        const __half* As[6] = {tf, tf, sf, vf, sf, vf};
        const __half* Bs[6] = {wqs, wql, wks, wvs, wkl, wvl};
        const float* bs[6] = {bq_s, bq_l, bk_s, bv_s, bk_l, bv_l};
        __half* Cs[6] = {qs, ql, ks, vs, kl, vl};
        const int Ms[6] = {BL, BL, SEQ_S, SEQ_S, SEQ_S, SEQ_S};
        const int Ks2[6] = {DMODEL, DMODEL, DLLM, DLLM, DLLM, DLLM};
        int acc = 0;
        p.ofs[0] = 0;
        for (int i = 0; i < 6; i++) {
            p.A[i] = As[i]; p.B[i] = Bs[i]; p.bias[i] = bs[i]; p.C[i] = Cs[i];
            p.M[i] = Ms[i]; p.K[i] = Ks2[i];
            acc += 8 * ((Ms[i] + 127) / 128);      // gx = 8
            p.ofs[i + 1] = acc;
        }
        gemm_proj_f16<<<acc, 256, GEMM_SMEM>>>(p); // 1280 blocks
    }

    // --- fused dual-stream flash attention (single-term fp16) ---
    {
        AttnParams ap = {};
        ap.q[0] = qs; ap.k[0] = ks; ap.v[0] = vs;
        ap.q[1] = ql; ap.k[1] = kl; ap.v[1] = vl;
        ap.alpha = alpha; ap.beta = beta;
        ap.of = af16;
        dim3 g(BL / 64, NHEAD);
        attn_mma<<<g, 128, ATT_SMEM>>>(ap);
    }

    // --- output projection (single-term fp16, measured best) ---
    {
        dim3 g(DLLM / 128, BL / 128);
        gemm_out_f16<<<g, 256, GEMM_SMEM>>>(af16, wo, bo, out);
    }
}

// round 11
// speedup vs baseline: 2.2491x; 1.0229x over previous
#include <cuda_runtime.h>
#include <cuda_fp16.h>
#include <math.h>
#include <stdint.h>

#define BL     8192
#define DMODEL 1024
#define DLLM   4096
#define DINNER 1024
#define SEQ_S  1000
#define NHEAD  16
#define EDIM   64

// ---------------------------------------------------------------------------
// Portable PTX helpers (base compute_103 target — NO tcgen05)
// ---------------------------------------------------------------------------
__device__ __forceinline__ uint32_t smem_u32(const void* p) {
    uint32_t a;
    asm("{ .reg .u64 t; cvta.to.shared.u64 t, %1; cvt.u32.u64 %0, t; }"
        : "=r"(a) : "l"(p));
    return a;
}

#define SWZ(o) ((o) ^ (((o) >> 3) & 0x70))

#define CP_ASYNC16(dst, src) \
    asm volatile("cp.async.cg.shared.global [%0], [%1], 16;\n" :: "r"(dst), "l"(src))
#define CP_COMMIT() asm volatile("cp.async.commit_group;\n" ::: "memory")
#define CP_WAIT1()  asm volatile("cp.async.wait_group 1;\n" ::: "memory")
#define CP_WAIT0()  asm volatile("cp.async.wait_group 0;\n" ::: "memory")
#define STS_ZERO16(addr) \
    asm volatile("st.shared.v4.b32 [%0], {%1,%1,%1,%1};\n" :: "r"(addr), "r"(0u) : "memory")

__device__ __forceinline__ void ldsm4(uint32_t* r, uint32_t a) {
    asm volatile("ldmatrix.sync.aligned.m8n8.x4.shared.b16 {%0,%1,%2,%3}, [%4];\n"
        : "=r"(r[0]), "=r"(r[1]), "=r"(r[2]), "=r"(r[3]) : "r"(a));
}
__device__ __forceinline__ void ldsm4t(uint32_t* r, uint32_t a) {
    asm volatile("ldmatrix.sync.aligned.m8n8.x4.trans.shared.b16 {%0,%1,%2,%3}, [%4];\n"
        : "=r"(r[0]), "=r"(r[1]), "=r"(r[2]), "=r"(r[3]) : "r"(a));
}
__device__ __forceinline__ void mma16816h(float* c, const uint32_t* a,
                                          uint32_t b0, uint32_t b1) {
    asm volatile(
        "mma.sync.aligned.m16n8k16.row.col.f32.f16.f16.f32 "
        "{%0,%1,%2,%3}, {%4,%5,%6,%7}, {%8,%9}, {%0,%1,%2,%3};\n"
        : "+f"(c[0]), "+f"(c[1]), "+f"(c[2]), "+f"(c[3])
        : "r"(a[0]), "r"(a[1]), "r"(a[2]), "r"(a[3]), "r"(b0), "r"(b1));
}

// ---------------------------------------------------------------------------
// Scratch (device globals — no allocation allowed) — ALL fp16 single
// ---------------------------------------------------------------------------
__device__ __half g_tf[BL * DMODEL];
__device__ __half g_sf[SEQ_S * DLLM];
__device__ __half g_vf[SEQ_S * DLLM];
__device__ __half g_qs[BL * DINNER], g_ql[BL * DINNER];
__device__ __half g_ks[SEQ_S * DINNER], g_vs[SEQ_S * DINNER];
__device__ __half g_kl[SEQ_S * DINNER], g_vl[SEQ_S * DINNER];
__device__ __half g_af16[BL * DINNER];
__device__ __half g_wqs[DINNER * DMODEL], g_wql[DINNER * DMODEL];
__device__ __half g_wks[DINNER * DLLM],   g_wvs[DINNER * DLLM];
__device__ __half g_wkl[DINNER * DLLM],   g_wvl[DINNER * DLLM];
__device__ __half g_wo[DLLM * DINNER];

// ---------------------------------------------------------------------------
// Merged prepass: 7 fp32->fp16 transposes + 3 fp32->fp16 flat converts.
// ---------------------------------------------------------------------------
struct PrepassParams {
    const float* W[7];
    __half* T[7];
    int K[7], N[7];
    int t_ofs[8];
    const float* X[3];
    __half* H[3];
    int s_ofs[4];
    int total_trans;
};

__global__ __launch_bounds__(256)
void prepass(PrepassParams p)
{
    __shared__ float tsm[32][33];
    const int bid = blockIdx.x;
    if (bid < p.total_trans) {
        int w = 0;
        while (bid >= p.t_ofs[w + 1]) w++;
        const int t = bid - p.t_ofs[w];
        const int K = p.K[w], N = p.N[w];
        const int tiles_x = N >> 5;
        const int n0 = (t % tiles_x) << 5, k0 = (t / tiles_x) << 5;
        const float* __restrict__ W = p.W[w];
        __half* __restrict__ T = p.T[w];
        const int tx = threadIdx.x & 31, ty = threadIdx.x >> 5;
#pragma unroll
        for (int i = 0; i < 32; i += 8)
            tsm[ty + i][tx] = W[(size_t)(k0 + ty + i) * N + n0 + tx];
        __syncthreads();
#pragma unroll
        for (int i = 0; i < 32; i += 8) {
            int n = n0 + ty + i;
            T[(size_t)n * K + k0 + tx] = __float2half(tsm[tx][ty + i]);
        }
    } else {
        const int sb = bid - p.total_trans;
        int a = 0;
        while (sb >= p.s_ofs[a + 1]) a++;
        const int rel = sb - p.s_ofs[a];
        const float* __restrict__ X = p.X[a];
        __half* __restrict__ H = p.H[a];
#pragma unroll
        for (int i = 0; i < 16; i++) {
            int idx = rel * 16384 + (i * 256 + threadIdx.x) * 4;
            float4 v = *(const float4*)(X + idx);
            __half2 h01 = __floats2half2_rn(v.x, v.y);
            __half2 h23 = __floats2half2_rn(v.z, v.w);
            uint2 o;
            o.x = *reinterpret_cast<uint32_t*>(&h01);
            o.y = *reinterpret_cast<uint32_t*>(&h23);
            *(uint2*)(H + idx) = o;
        }
    }
}

// ---------------------------------------------------------------------------
// fp16 single-term GEMM, 128x128 tile, BK=64, 3-stage (96KB) -> 2 CTAs/SM.
// ---------------------------------------------------------------------------
#define F_A 0
#define F_B 16384
#define FSTG 32768
#define GEMM_SMEM (3 * FSTG)   // 96 KB

struct ProjJobs {
    const __half *A[6], *B[6];
    const float* bias[6];
    __half* C[6];
    int M[6], K[6];
    int ofs[7];
};

__global__ __launch_bounds__(256, 2)
void gemm_proj_f16(ProjJobs p)
{
    extern __shared__ __align__(1024) char smem[];
    const int bid = blockIdx.x;
    int z = 0;
    while (bid >= p.ofs[z + 1]) z++;
    const int rel = bid - p.ofs[z];
    const int bx = rel & 7, by = rel >> 3;
    const int M = p.M[z], K = p.K[z];
    const int N = DINNER;

    const __half* __restrict__ A = p.A[z];
    const __half* __restrict__ B = p.B[z];

    const int tid = threadIdx.x;
    const int wid = tid >> 5, lid = tid & 31;
    const int wm = wid & 3, wn = wid >> 2;
    const int m0 = by * 128, n0 = bx * 128;
    const uint32_t sb = smem_u32(smem);
    const int NC = K >> 6;

    float c[2][8][4];
#pragma unroll
    for (int i = 0; i < 2; i++)
#pragma unroll
        for (int j = 0; j < 8; j++)
#pragma unroll
            for (int q = 0; q < 4; q++) c[i][j][q] = 0.f;

    auto load_stage = [&](int cchunk) {
        const uint32_t st_ = sb + (cchunk % 3) * FSTG;
        const int k0_ = cchunk << 6;
#pragma unroll
        for (int i_ = 0; i_ < 4; i_++) {
            int idx_ = i_ * 256 + tid;
            int r_ = idx_ >> 3, u_ = idx_ & 7;
            uint32_t sw_ = SWZ((uint32_t)(r_ * 128 + u_ * 16));
            int gm_ = m0 + r_;
            if (gm_ < M)
                CP_ASYNC16(st_ + F_A + sw_, (const char*)(A + (size_t)gm_ * K + k0_) + u_ * 16);
            else
                STS_ZERO16(st_ + F_A + sw_);
            CP_ASYNC16(st_ + F_B + sw_, (const char*)(B + (size_t)(n0 + r_) * K + k0_) + u_ * 16);
        }
        CP_COMMIT();
    };

    load_stage(0);
    load_stage(1);

    const int q8 = lid >> 3, lr = lid & 7;

    for (int cc = 0; cc < NC; cc++) {
        CP_WAIT1();
        __syncthreads();
        if (cc + 2 < NC) { load_stage(cc + 2); } else { CP_COMMIT(); }

        const uint32_t st = sb + (cc % 3) * FSTG;
#pragma unroll
        for (int ks = 0; ks < 4; ks++) {
            const int kb = ks * 32;
            uint32_t ah[2][4], bh[8][2];
#pragma unroll
            for (int mi = 0; mi < 2; mi++) {
                uint32_t off = SWZ((uint32_t)(
                    (wm * 32 + mi * 16 + lr + (q8 & 1) * 8) * 128 + kb + (q8 >> 1) * 16));
                ldsm4(ah[mi], st + F_A + off);
            }
#pragma unroll
            for (int njp = 0; njp < 4; njp++) {
                uint32_t off = SWZ((uint32_t)(
                    (wn * 64 + njp * 16 + lr + (q8 >> 1) * 8) * 128 + kb + (q8 & 1) * 16));
                uint32_t t0[4];
                ldsm4(t0, st + F_B + off);
                bh[2 * njp][0] = t0[0]; bh[2 * njp][1] = t0[1];
                bh[2 * njp + 1][0] = t0[2]; bh[2 * njp + 1][1] = t0[3];
            }
#pragma unroll
            for (int mi = 0; mi < 2; mi++)
#pragma unroll
                for (int nj = 0; nj < 8; nj++)
                    mma16816h(c[mi][nj], ah[mi], bh[nj][0], bh[nj][1]);
        }
    }

    const int lr4 = lid >> 2, lc = (lid & 3) * 2;
    const float* __restrict__ bias = p.bias[z];
    __half* __restrict__ C = p.C[z];
#pragma unroll
    for (int mi = 0; mi < 2; mi++) {
        int row = m0 + wm * 32 + mi * 16 + lr4;
#pragma unroll
        for (int nj = 0; nj < 8; nj++) {
            int col = n0 + wn * 64 + nj * 8 + lc;
            float2 b2 = *(const float2*)(bias + col);
            __half2 h0 = __floats2half2_rn(c[mi][nj][0] + b2.x, c[mi][nj][1] + b2.y);
            __half2 h1 = __floats2half2_rn(c[mi][nj][2] + b2.x, c[mi][nj][3] + b2.y);
            if (row < M)
                *(uint32_t*)(C + (size_t)row * N + col) = *reinterpret_cast<uint32_t*>(&h0);
            if (row + 8 < M)
                *(uint32_t*)(C + (size_t)(row + 8) * N + col) = *reinterpret_cast<uint32_t*>(&h1);
        }
    }
}

__global__ __launch_bounds__(256, 2)
void gemm_out_f16(const __half* __restrict__ A, const __half* __restrict__ B,
                  const float* __restrict__ bias, float* __restrict__ C)
{
    extern __shared__ __align__(1024) char smem[];
    const int tid = threadIdx.x;
    const int wid = tid >> 5, lid = tid & 31;
    const int wm = wid & 3, wn = wid >> 2;
    const int m0 = blockIdx.y * 128, n0 = blockIdx.x * 128;
    const uint32_t sb = smem_u32(smem);
    const int K = DINNER, N = DLLM;
    const int NC = K >> 6;

    float c[2][8][4];
#pragma unroll
    for (int i = 0; i < 2; i++)
#pragma unroll
        for (int j = 0; j < 8; j++)
#pragma unroll
            for (int q = 0; q < 4; q++) c[i][j][q] = 0.f;

    auto load_stage = [&](int cchunk) {
        const uint32_t st_ = sb + (cchunk % 3) * FSTG;
        const int k0_ = cchunk << 6;
#pragma unroll
        for (int i_ = 0; i_ < 4; i_++) {
            int idx_ = i_ * 256 + tid;
            int r_ = idx_ >> 3, u_ = idx_ & 7;
            uint32_t sw_ = SWZ((uint32_t)(r_ * 128 + u_ * 16));
            CP_ASYNC16(st_ + F_A + sw_, (const char*)(A + (size_t)(m0 + r_) * K + k0_) + u_ * 16);
            CP_ASYNC16(st_ + F_B + sw_, (const char*)(B + (size_t)(n0 + r_) * K + k0_) + u_ * 16);
        }
        CP_COMMIT();
    };

    load_stage(0);
    load_stage(1);

    const int q8 = lid >> 3, lr = lid & 7;

    for (int cc = 0; cc < NC; cc++) {
        CP_WAIT1();
        __syncthreads();
        if (cc + 2 < NC) { load_stage(cc + 2); } else { CP_COMMIT(); }

        const uint32_t st = sb + (cc % 3) * FSTG;
#pragma unroll
        for (int ks = 0; ks < 4; ks++) {
            const int kb = ks * 32;
            uint32_t ah[2][4], bh[8][2];
#pragma unroll
            for (int mi = 0; mi < 2; mi++) {
                uint32_t off = SWZ((uint32_t)(
                    (wm * 32 + mi * 16 + lr + (q8 & 1) * 8) * 128 + kb + (q8 >> 1) * 16));
                ldsm4(ah[mi], st + F_A + off);
            }
#pragma unroll
            for (int njp = 0; njp < 4; njp++) {
                uint32_t off = SWZ((uint32_t)(
                    (wn * 64 + njp * 16 + lr + (q8 >> 1) * 8) * 128 + kb + (q8 & 1) * 16));
                uint32_t t0[4];
                ldsm4(t0, st + F_B + off);
                bh[2 * njp][0] = t0[0]; bh[2 * njp][1] = t0[1];
                bh[2 * njp + 1][0] = t0[2]; bh[2 * njp + 1][1] = t0[3];
            }
#pragma unroll
            for (int mi = 0; mi < 2; mi++)
#pragma unroll
                for (int nj = 0; nj < 8; nj++)
                    mma16816h(c[mi][nj], ah[mi], bh[nj][0], bh[nj][1]);
        }
    }

    const int lr4 = lid >> 2, lc = (lid & 3) * 2;
#pragma unroll
    for (int mi = 0; mi < 2; mi++) {
        int row = m0 + wm * 32 + mi * 16 + lr4;
#pragma unroll
        for (int nj = 0; nj < 8; nj++) {
            int col = n0 + wn * 64 + nj * 8 + lc;
            float2 b2 = *(const float2*)(bias + col);
            *(float2*)(C + (size_t)row * N + col) =
                make_float2(c[mi][nj][0] + b2.x, c[mi][nj][1] + b2.y);
            *(float2*)(C + (size_t)(row + 8) * N + col) =
                make_float2(c[mi][nj][2] + b2.x, c[mi][nj][3] + b2.y);
        }
    }
}

// ---------------------------------------------------------------------------
// HMMA flash attention, dual-stream, single-term fp16 — q-tile 128 rows,
// 8 warps (256 threads), 2-stage KV (16KB/stage). Per-warp code unchanged.
// ---------------------------------------------------------------------------
struct AttnParams {
    const __half *q[2], *k[2], *v[2];
    const float *alpha, *beta;
    __half* of;
};

#define ATT_STAGE 16384
#define A_K 0
#define A_V 8192
#define ATT_SMEM (2 * ATT_STAGE)   // 32 KB
#define NCH 16
#define SOFTMAX_SCALE 0.125f

__global__ __launch_bounds__(256)
void attn_mma(AttnParams p)
{
    extern __shared__ __align__(1024) char smem[];
    const uint32_t sb = smem_u32(smem);
    const int tid = threadIdx.x;
    const int w = tid >> 5, lid = tid & 31;
    const int q8 = lid >> 3, lr = lid & 7;
    const int h = blockIdx.y;
    const int qbase = blockIdx.x * 128;
    const int colbase = h * EDIM;

    const float alpha = *p.alpha;
    const float beta  = *p.beta;

    float osave[8][4];

    for (int st = 0; st < 2; st++) {
        const __half* __restrict__ qp = p.q[st];
        const __half* __restrict__ kp = p.k[st];
        const __half* __restrict__ vp = p.v[st];

        // ---- stage Q (128x64 fp16 = 16KB) across stage-0 K+V regions ----
#pragma unroll
        for (int i = 0; i < 4; i++) {
            int idx = i * 256 + tid;            // 1024 = 128 rows x 8 chunks
            int r = idx >> 3, u = idx & 7;
            uint32_t sw = SWZ((uint32_t)(r * 128 + u * 16));
            CP_ASYNC16(sb + sw,
                       (const char*)(qp + (size_t)(qbase + r) * DINNER + colbase) + u * 16);
        }
        CP_COMMIT();
        CP_WAIT0();
        __syncthreads();

        uint32_t qf[4][4];
#pragma unroll
        for (int ks = 0; ks < 4; ks++) {
            uint32_t off = SWZ((uint32_t)(
                (w * 16 + lr + (q8 & 1) * 8) * 128 + ks * 32 + (q8 >> 1) * 16));
            ldsm4(qf[ks], sb + off);
        }
        __syncthreads();

        float o[8][4];
#pragma unroll
        for (int t = 0; t < 8; t++)
#pragma unroll
            for (int i = 0; i < 4; i++) o[t][i] = 0.f;
        float m0r = -INFINITY, m1r = -INFINITY;
        float l0 = 0.f, l1 = 0.f;

#define LOAD_KV(cchunk) do { \
            const uint32_t stg_ = sb + ((cchunk) & 1) * ATT_STAGE; \
            const int s0_ = (cchunk) * 64; \
            _Pragma("unroll") \
            for (int i_ = 0; i_ < 2; i_++) { \
                int idx_ = i_ * 256 + tid; \
                int r_ = idx_ >> 3, u_ = idx_ & 7; \
                uint32_t sw_ = SWZ((uint32_t)(r_ * 128 + u_ * 16)); \
                if (s0_ + r_ < SEQ_S) { \
                    const size_t go_ = (size_t)(s0_ + r_) * DINNER + colbase; \
                    CP_ASYNC16(stg_ + A_K + sw_, (const char*)(kp + go_) + u_ * 16); \
                    CP_ASYNC16(stg_ + A_V + sw_, (const char*)(vp + go_) + u_ * 16); \
                } else { \
                    STS_ZERO16(stg_ + A_K + sw_); \
                    STS_ZERO16(stg_ + A_V + sw_); \
                } \
            } \
            CP_COMMIT(); \
        } while (0)

        LOAD_KV(0);

        for (int cc = 0; cc < NCH; cc++) {
            __syncthreads();
            if (cc + 1 < NCH) { LOAD_KV(cc + 1); } else { CP_COMMIT(); }
            CP_WAIT1();
            __syncthreads();
            const uint32_t stg = sb + (cc & 1) * ATT_STAGE;

            float s[8][4];
#pragma unroll
            for (int t = 0; t < 8; t++)
#pragma unroll
                for (int i = 0; i < 4; i++) s[t][i] = 0.f;

#pragma unroll
            for (int ks = 0; ks < 4; ks++) {
                uint32_t bh[8][2];
#pragma unroll
                for (int njp = 0; njp < 4; njp++) {
                    uint32_t off = SWZ((uint32_t)(
                        (njp * 16 + lr + (q8 >> 1) * 8) * 128 + ks * 32 + (q8 & 1) * 16));
                    uint32_t t0[4];
                    ldsm4(t0, stg + A_K + off);
                    bh[2 * njp][0] = t0[0]; bh[2 * njp][1] = t0[1];
                    bh[2 * njp + 1][0] = t0[2]; bh[2 * njp + 1][1] = t0[3];
                }
#pragma unroll
                for (int t = 0; t < 8; t++)
                    mma16816h(s[t], qf[ks], bh[t][0], bh[t][1]);
            }

            if (cc == NCH - 1) {
#pragma unroll
                for (int t = 5; t < 8; t++)
#pragma unroll
                    for (int i = 0; i < 4; i++) s[t][i] = -1e30f;
            }

            float ml0 = -1e30f, ml1 = -1e30f;
#pragma unroll
            for (int t = 0; t < 8; t++) {
                ml0 = fmaxf(ml0, fmaxf(s[t][0], s[t][1]));
                ml1 = fmaxf(ml1, fmaxf(s[t][2], s[t][3]));
            }
            ml0 = fmaxf(ml0, __shfl_xor_sync(0xffffffffu, ml0, 1));
            ml0 = fmaxf(ml0, __shfl_xor_sync(0xffffffffu, ml0, 2));
            ml1 = fmaxf(ml1, __shfl_xor_sync(0xffffffffu, ml1, 1));
            ml1 = fmaxf(ml1, __shfl_xor_sync(0xffffffffu, ml1, 2));

            float mn0 = fmaxf(m0r, ml0), mn1 = fmaxf(m1r, ml1);
            float c0 = __expf((m0r - mn0) * SOFTMAX_SCALE);
            float c1 = __expf((m1r - mn1) * SOFTMAX_SCALE);
            m0r = mn0; m1r = mn1;
            l0 *= c0; l1 *= c1;
#pragma unroll
            for (int t = 0; t < 8; t++) {
                o[t][0] *= c0; o[t][1] *= c0;
                o[t][2] *= c1; o[t][3] *= c1;
            }
#pragma unroll
            for (int t = 0; t < 8; t++) {
                float p0 = __expf((s[t][0] - mn0) * SOFTMAX_SCALE);
                float p1 = __expf((s[t][1] - mn0) * SOFTMAX_SCALE);
                float p2 = __expf((s[t][2] - mn1) * SOFTMAX_SCALE);
                float p3 = __expf((s[t][3] - mn1) * SOFTMAX_SCALE);
                l0 += p0 + p1; l1 += p2 + p3;
                s[t][0] = p0; s[t][1] = p1; s[t][2] = p2; s[t][3] = p3;
            }

#pragma unroll
            for (int ks = 0; ks < 4; ks++) {
                uint32_t pa[4];
                __half2 pp0 = __floats2half2_rn(s[2 * ks][0],     s[2 * ks][1]);
                __half2 pp1 = __floats2half2_rn(s[2 * ks][2],     s[2 * ks][3]);
                __half2 pp2 = __floats2half2_rn(s[2 * ks + 1][0], s[2 * ks + 1][1]);
                __half2 pp3 = __floats2half2_rn(s[2 * ks + 1][2], s[2 * ks + 1][3]);
                pa[0] = *reinterpret_cast<uint32_t*>(&pp0);
                pa[1] = *reinterpret_cast<uint32_t*>(&pp1);
                pa[2] = *reinterpret_cast<uint32_t*>(&pp2);
                pa[3] = *reinterpret_cast<uint32_t*>(&pp3);
#pragma unroll
                for (int ep = 0; ep < 4; ep++) {
                    uint32_t off = SWZ((uint32_t)(
                        (ks * 16 + lr + (q8 & 1) * 8) * 128 + ep * 32 + (q8 >> 1) * 16));
                    uint32_t tv0[4];
                    ldsm4t(tv0, stg + A_V + off);
                    mma16816h(o[2 * ep],     pa, tv0[0], tv0[1]);
                    mma16816h(o[2 * ep + 1], pa, tv0[2], tv0[3]);
                }
            }
        }

        l0 += __shfl_xor_sync(0xffffffffu, l0, 1);
        l0 += __shfl_xor_sync(0xffffffffu, l0, 2);
        l1 += __shfl_xor_sync(0xffffffffu, l1, 1);
        l1 += __shfl_xor_sync(0xffffffffu, l1, 2);
        float wgt = (st == 0) ? alpha : beta;
        float f0 = wgt / l0, f1 = wgt / l1;
        if (st == 0) {
#pragma unroll
            for (int t = 0; t < 8; t++) {
                osave[t][0] = o[t][0] * f0; osave[t][1] = o[t][1] * f0;
                osave[t][2] = o[t][2] * f1; osave[t][3] = o[t][3] * f1;
            }
        } else {
#pragma unroll
            for (int t = 0; t < 8; t++) {
                osave[t][0] += o[t][0] * f0; osave[t][1] += o[t][1] * f0;
                osave[t][2] += o[t][2] * f1; osave[t][3] += o[t][3] * f1;
            }
        }
        __syncthreads();
    }

    const int r0 = qbase + w * 16 + (lid >> 2);
#pragma unroll
    for (int t = 0; t < 8; t++) {
        int col = colbase + t * 8 + (lid & 3) * 2;
        __half2 h0 = __floats2half2_rn(osave[t][0], osave[t][1]);
        __half2 h1 = __floats2half2_rn(osave[t][2], osave[t][3]);
        *(uint32_t*)(p.of + (size_t)r0 * DINNER + col) = *reinterpret_cast<uint32_t*>(&h0);
        *(uint32_t*)(p.of + (size_t)(r0 + 8) * DINNER + col) = *reinterpret_cast<uint32_t*>(&h1);
    }
}

// ---------------------------------------------------------------------------
// Launch
// ---------------------------------------------------------------------------
extern "C" void kernel_launch(void* const* d_in, const int* in_sizes, int n_in,
                              void* d_out, int out_size)
{
    const float* target = (const float*)d_in[0];
    const float* source = (const float*)d_in[1];
    const float* value  = (const float*)d_in[2];
    const float* Wq_s = (const float*)d_in[3];  const float* bq_s = (const float*)d_in[4];
    const float* Wk_s = (const float*)d_in[5];  const float* bk_s = (const float*)d_in[6];
    const float* Wv_s = (const float*)d_in[7];  const float* bv_s = (const float*)d_in[8];
    const float* Wq_l = (const float*)d_in[9];  const float* bq_l = (const float*)d_in[10];
    const float* Wk_l = (const float*)d_in[11]; const float* bk_l = (const float*)d_in[12];
    const float* Wv_l = (const float*)d_in[13]; const float* bv_l = (const float*)d_in[14];
    const float* Wo   = (const float*)d_in[15]; const float* bo   = (const float*)d_in[16];
    const float* alpha = (const float*)d_in[17];
    const float* beta  = (const float*)d_in[18];
    float* out = (float*)d_out;

    __half *tf, *sf, *vf, *af16;
    cudaGetSymbolAddress((void**)&tf, g_tf);
    cudaGetSymbolAddress((void**)&sf, g_sf);
    cudaGetSymbolAddress((void**)&vf, g_vf);
    cudaGetSymbolAddress((void**)&af16, g_af16);

    __half *qs, *ql, *ks, *vs, *kl, *vl;
    cudaGetSymbolAddress((void**)&qs, g_qs); cudaGetSymbolAddress((void**)&ql, g_ql);
    cudaGetSymbolAddress((void**)&ks, g_ks); cudaGetSymbolAddress((void**)&vs, g_vs);
    cudaGetSymbolAddress((void**)&kl, g_kl); cudaGetSymbolAddress((void**)&vl, g_vl);

    __half *wqs, *wql, *wks, *wvs, *wkl, *wvl, *wo;
    cudaGetSymbolAddress((void**)&wqs, g_wqs); cudaGetSymbolAddress((void**)&wql, g_wql);
    cudaGetSymbolAddress((void**)&wks, g_wks); cudaGetSymbolAddress((void**)&wvs, g_wvs);
    cudaGetSymbolAddress((void**)&wkl, g_wkl); cudaGetSymbolAddress((void**)&wvl, g_wvl);
    cudaGetSymbolAddress((void**)&wo,  g_wo);

    cudaFuncSetAttribute(gemm_proj_f16, cudaFuncAttributeMaxDynamicSharedMemorySize, GEMM_SMEM);
    cudaFuncSetAttribute(gemm_out_f16,  cudaFuncAttributeMaxDynamicSharedMemorySize, GEMM_SMEM);
    cudaFuncSetAttribute(attn_mma,      cudaFuncAttributeMaxDynamicSharedMemorySize, ATT_SMEM);

    // --- merged prepass (all fp32 -> fp16) ---
    {
        PrepassParams pp = {};
        const float* Ws[7] = {Wq_s, Wq_l, Wk_s, Wv_s, Wk_l, Wv_l, Wo};
        __half* Ts[7] = {wqs, wql, wks, wvs, wkl, wvl, wo};
        const int Ks[7] = {DMODEL, DMODEL, DLLM, DLLM, DLLM, DLLM, DINNER};
        const int Ns[7] = {DINNER, DINNER, DINNER, DINNER, DINNER, DINNER, DLLM};
        int acc = 0;
        pp.t_ofs[0] = 0;
        for (int i = 0; i < 7; i++) {
            pp.W[i] = Ws[i]; pp.T[i] = Ts[i];
            pp.K[i] = Ks[i]; pp.N[i] = Ns[i];
            acc += (Ks[i] / 32) * (Ns[i] / 32);
            pp.t_ofs[i + 1] = acc;
        }
        pp.total_trans = acc;
        pp.X[0] = target; pp.H[0] = tf;
        pp.X[1] = source; pp.H[1] = sf;
        pp.X[2] = value;  pp.H[2] = vf;
        pp.s_ofs[0] = 0;
        pp.s_ofs[1] = (BL * DMODEL) / 16384;
        pp.s_ofs[2] = pp.s_ofs[1] + (SEQ_S * DLLM) / 16384;
        pp.s_ofs[3] = pp.s_ofs[2] + (SEQ_S * DLLM) / 16384;
        prepass<<<pp.total_trans + pp.s_ofs[3], 256>>>(pp);
    }

    // --- 6 projection GEMMs, one flat launch ---
    {
        ProjJobs p = {};
        const __half* As[6] = {tf, tf, sf, vf, sf, vf};
        const __half* Bs[6] = {wqs, wql, wks, wvs, wkl, wvl};
        const float* bs[6] = {bq_s, bq_l, bk_s, bv_s, bk_l, bv_l};
        __half* Cs[6] = {qs, ql, ks, vs, kl, vl};
        const int Ms[6] = {BL, BL, SEQ_S, SEQ_S, SEQ_S, SEQ_S};
        const int Ks2[6] = {DMODEL, DMODEL, DLLM, DLLM, DLLM, DLLM};
        int acc = 0;
        p.ofs[0] = 0;
        for (int i = 0; i < 6; i++) {
            p.A[i] = As[i]; p.B[i] = Bs[i]; p.bias[i] = bs[i]; p.C[i] = Cs[i];
            p.M[i] = Ms[i]; p.K[i] = Ks2[i];
            acc += 8 * ((Ms[i] + 127) / 128);
            p.ofs[i + 1] = acc;
        }
        gemm_proj_f16<<<acc, 256, GEMM_SMEM>>>(p);
    }

    // --- fused dual-stream flash attention (q-tile 128) ---
    {
        AttnParams ap = {};
        ap.q[0] = qs; ap.k[0] = ks; ap.v[0] = vs;
        ap.q[1] = ql; ap.k[1] = kl; ap.v[1] = vl;
        ap.alpha = alpha; ap.beta = beta;
        ap.of = af16;
        dim3 g(BL / 128, NHEAD);                 // (64, 16)
        attn_mma<<<g, 256, ATT_SMEM>>>(ap);
    }

    // --- output projection ---
    {
        dim3 g(DLLM / 128, BL / 128);
        gemm_out_f16<<<g, 256, GEMM_SMEM>>>(af16, wo, bo, out);
    }
}

// round 12
// speedup vs baseline: 2.3142x; 1.0289x over previous
#include <cuda_runtime.h>
#include <cuda_fp16.h>
#include <math.h>
#include <stdint.h>

#define BL     8192
#define DMODEL 1024
#define DLLM   4096
#define DINNER 1024
#define SEQ_S  1000
#define NHEAD  16
#define EDIM   64

// ---------------------------------------------------------------------------
// Portable PTX helpers (base compute_103 target — NO tcgen05)
// ---------------------------------------------------------------------------
__device__ __forceinline__ uint32_t smem_u32(const void* p) {
    uint32_t a;
    asm("{ .reg .u64 t; cvta.to.shared.u64 t, %1; cvt.u32.u64 %0, t; }"
        : "=r"(a) : "l"(p));
    return a;
}

#define SWZ(o) ((o) ^ (((o) >> 3) & 0x70))

#define CP_ASYNC16(dst, src) \
    asm volatile("cp.async.cg.shared.global [%0], [%1], 16;\n" :: "r"(dst), "l"(src))
#define CP_COMMIT() asm volatile("cp.async.commit_group;\n" ::: "memory")
#define CP_WAIT1()  asm volatile("cp.async.wait_group 1;\n" ::: "memory")
#define CP_WAIT2()  asm volatile("cp.async.wait_group 2;\n" ::: "memory")
#define CP_WAIT0()  asm volatile("cp.async.wait_group 0;\n" ::: "memory")
#define STS_ZERO16(addr) \
    asm volatile("st.shared.v4.b32 [%0], {%1,%1,%1,%1};\n" :: "r"(addr), "r"(0u) : "memory")

__device__ __forceinline__ void ldsm4(uint32_t* r, uint32_t a) {
    asm volatile("ldmatrix.sync.aligned.m8n8.x4.shared.b16 {%0,%1,%2,%3}, [%4];\n"
        : "=r"(r[0]), "=r"(r[1]), "=r"(r[2]), "=r"(r[3]) : "r"(a));
}
__device__ __forceinline__ void ldsm4t(uint32_t* r, uint32_t a) {
    asm volatile("ldmatrix.sync.aligned.m8n8.x4.trans.shared.b16 {%0,%1,%2,%3}, [%4];\n"
        : "=r"(r[0]), "=r"(r[1]), "=r"(r[2]), "=r"(r[3]) : "r"(a));
}
__device__ __forceinline__ void mma16816h(float* c, const uint32_t* a,
                                          uint32_t b0, uint32_t b1) {
    asm volatile(
        "mma.sync.aligned.m16n8k16.row.col.f32.f16.f16.f32 "
        "{%0,%1,%2,%3}, {%4,%5,%6,%7}, {%8,%9}, {%0,%1,%2,%3};\n"
        : "+f"(c[0]), "+f"(c[1]), "+f"(c[2]), "+f"(c[3])
        : "r"(a[0]), "r"(a[1]), "r"(a[2]), "r"(a[3]), "r"(b0), "r"(b1));
}

// ---------------------------------------------------------------------------
// Scratch (device globals — no allocation allowed) — ALL fp16 single
// ---------------------------------------------------------------------------
__device__ __half g_tf[BL * DMODEL];
__device__ __half g_sf[SEQ_S * DLLM];
__device__ __half g_vf[SEQ_S * DLLM];
__device__ __half g_qs[BL * DINNER], g_ql[BL * DINNER];
__device__ __half g_ks[SEQ_S * DINNER], g_vs[SEQ_S * DINNER];
__device__ __half g_kl[SEQ_S * DINNER], g_vl[SEQ_S * DINNER];
__device__ __half g_af16[BL * DINNER];
__device__ __half g_wqs[DINNER * DMODEL], g_wql[DINNER * DMODEL];
__device__ __half g_wks[DINNER * DLLM],   g_wvs[DINNER * DLLM];
__device__ __half g_wkl[DINNER * DLLM],   g_wvl[DINNER * DLLM];
__device__ __half g_wo[DLLM * DINNER];

// ---------------------------------------------------------------------------
// Merged prepass: 7 fp32->fp16 transposes + 3 fp32->fp16 flat converts.
// ---------------------------------------------------------------------------
struct PrepassParams {
    const float* W[7];
    __half* T[7];
    int K[7], N[7];
    int t_ofs[8];
    const float* X[3];
    __half* H[3];
    int s_ofs[4];
    int total_trans;
};

__global__ __launch_bounds__(256)
void prepass(PrepassParams p)
{
    __shared__ float tsm[32][33];
    const int bid = blockIdx.x;
    if (bid < p.total_trans) {
        int w = 0;
        while (bid >= p.t_ofs[w + 1]) w++;
        const int t = bid - p.t_ofs[w];
        const int K = p.K[w], N = p.N[w];
        const int tiles_x = N >> 5;
        const int n0 = (t % tiles_x) << 5, k0 = (t / tiles_x) << 5;
        const float* __restrict__ W = p.W[w];
        __half* __restrict__ T = p.T[w];
        const int tx = threadIdx.x & 31, ty = threadIdx.x >> 5;
#pragma unroll
        for (int i = 0; i < 32; i += 8)
            tsm[ty + i][tx] = W[(size_t)(k0 + ty + i) * N + n0 + tx];
        __syncthreads();
#pragma unroll
        for (int i = 0; i < 32; i += 8) {
            int n = n0 + ty + i;
            T[(size_t)n * K + k0 + tx] = __float2half(tsm[tx][ty + i]);
        }
    } else {
        const int sb = bid - p.total_trans;
        int a = 0;
        while (sb >= p.s_ofs[a + 1]) a++;
        const int rel = sb - p.s_ofs[a];
        const float* __restrict__ X = p.X[a];
        __half* __restrict__ H = p.H[a];
#pragma unroll
        for (int i = 0; i < 16; i++) {
            int idx = rel * 16384 + (i * 256 + threadIdx.x) * 4;
            float4 v = *(const float4*)(X + idx);
            __half2 h01 = __floats2half2_rn(v.x, v.y);
            __half2 h23 = __floats2half2_rn(v.z, v.w);
            uint2 o;
            o.x = *reinterpret_cast<uint32_t*>(&h01);
            o.y = *reinterpret_cast<uint32_t*>(&h23);
            *(uint2*)(H + idx) = o;
        }
    }
}

// ---------------------------------------------------------------------------
// fp16 single-term GEMM, 128x128 tile, BK=64, 3-stage (96KB) -> 2 CTAs/SM.
// ---------------------------------------------------------------------------
#define F_A 0
#define F_B 16384
#define FSTG 32768
#define GEMM_SMEM (3 * FSTG)   // 96 KB

struct ProjJobs {
    const __half *A[6], *B[6];
    const float* bias[6];
    __half* C[6];
    int M[6], K[6];
    int ofs[7];
};

__global__ __launch_bounds__(256, 2)
void gemm_proj_f16(ProjJobs p)
{
    extern __shared__ __align__(1024) char smem[];
    const int bid = blockIdx.x;
    int z = 0;
    while (bid >= p.ofs[z + 1]) z++;
    const int rel = bid - p.ofs[z];
    const int bx = rel & 7, by = rel >> 3;
    const int M = p.M[z], K = p.K[z];
    const int N = DINNER;

    const __half* __restrict__ A = p.A[z];
    const __half* __restrict__ B = p.B[z];

    const int tid = threadIdx.x;
    const int wid = tid >> 5, lid = tid & 31;
    const int wm = wid & 3, wn = wid >> 2;
    const int m0 = by * 128, n0 = bx * 128;
    const uint32_t sb = smem_u32(smem);
    const int NC = K >> 6;

    float c[2][8][4];
#pragma unroll
    for (int i = 0; i < 2; i++)
#pragma unroll
        for (int j = 0; j < 8; j++)
#pragma unroll
            for (int q = 0; q < 4; q++) c[i][j][q] = 0.f;

    auto load_stage = [&](int cchunk) {
        const uint32_t st_ = sb + (cchunk % 3) * FSTG;
        const int k0_ = cchunk << 6;
#pragma unroll
        for (int i_ = 0; i_ < 4; i_++) {
            int idx_ = i_ * 256 + tid;
            int r_ = idx_ >> 3, u_ = idx_ & 7;
            uint32_t sw_ = SWZ((uint32_t)(r_ * 128 + u_ * 16));
            int gm_ = m0 + r_;
            if (gm_ < M)
                CP_ASYNC16(st_ + F_A + sw_, (const char*)(A + (size_t)gm_ * K + k0_) + u_ * 16);
            else
                STS_ZERO16(st_ + F_A + sw_);
            CP_ASYNC16(st_ + F_B + sw_, (const char*)(B + (size_t)(n0 + r_) * K + k0_) + u_ * 16);
        }
        CP_COMMIT();
    };

    load_stage(0);
    load_stage(1);

    const int q8 = lid >> 3, lr = lid & 7;

    for (int cc = 0; cc < NC; cc++) {
        CP_WAIT1();
        __syncthreads();
        if (cc + 2 < NC) { load_stage(cc + 2); } else { CP_COMMIT(); }

        const uint32_t st = sb + (cc % 3) * FSTG;
#pragma unroll
        for (int ks = 0; ks < 4; ks++) {
            const int kb = ks * 32;
            uint32_t ah[2][4], bh[8][2];
#pragma unroll
            for (int mi = 0; mi < 2; mi++) {
                uint32_t off = SWZ((uint32_t)(
                    (wm * 32 + mi * 16 + lr + (q8 & 1) * 8) * 128 + kb + (q8 >> 1) * 16));
                ldsm4(ah[mi], st + F_A + off);
            }
#pragma unroll
            for (int njp = 0; njp < 4; njp++) {
                uint32_t off = SWZ((uint32_t)(
                    (wn * 64 + njp * 16 + lr + (q8 >> 1) * 8) * 128 + kb + (q8 & 1) * 16));
                uint32_t t0[4];
                ldsm4(t0, st + F_B + off);
                bh[2 * njp][0] = t0[0]; bh[2 * njp][1] = t0[1];
                bh[2 * njp + 1][0] = t0[2]; bh[2 * njp + 1][1] = t0[3];
            }
#pragma unroll
            for (int mi = 0; mi < 2; mi++)
#pragma unroll
                for (int nj = 0; nj < 8; nj++)
                    mma16816h(c[mi][nj], ah[mi], bh[nj][0], bh[nj][1]);
        }
    }

    const int lr4 = lid >> 2, lc = (lid & 3) * 2;
    const float* __restrict__ bias = p.bias[z];
    __half* __restrict__ C = p.C[z];
#pragma unroll
    for (int mi = 0; mi < 2; mi++) {
        int row = m0 + wm * 32 + mi * 16 + lr4;
#pragma unroll
        for (int nj = 0; nj < 8; nj++) {
            int col = n0 + wn * 64 + nj * 8 + lc;
            float2 b2 = *(const float2*)(bias + col);
            __half2 h0 = __floats2half2_rn(c[mi][nj][0] + b2.x, c[mi][nj][1] + b2.y);
            __half2 h1 = __floats2half2_rn(c[mi][nj][2] + b2.x, c[mi][nj][3] + b2.y);
            if (row < M)
                *(uint32_t*)(C + (size_t)row * N + col) = *reinterpret_cast<uint32_t*>(&h0);
            if (row + 8 < M)
                *(uint32_t*)(C + (size_t)(row + 8) * N + col) = *reinterpret_cast<uint32_t*>(&h1);
        }
    }
}

__global__ __launch_bounds__(256, 2)
void gemm_out_f16(const __half* __restrict__ A, const __half* __restrict__ B,
                  const float* __restrict__ bias, float* __restrict__ C)
{
    extern __shared__ __align__(1024) char smem[];
    const int tid = threadIdx.x;
    const int wid = tid >> 5, lid = tid & 31;
    const int wm = wid & 3, wn = wid >> 2;
    const int m0 = blockIdx.y * 128, n0 = blockIdx.x * 128;
    const uint32_t sb = smem_u32(smem);
    const int K = DINNER, N = DLLM;
    const int NC = K >> 6;

    float c[2][8][4];
#pragma unroll
    for (int i = 0; i < 2; i++)
#pragma unroll
        for (int j = 0; j < 8; j++)
#pragma unroll
            for (int q = 0; q < 4; q++) c[i][j][q] = 0.f;

    auto load_stage = [&](int cchunk) {
        const uint32_t st_ = sb + (cchunk % 3) * FSTG;
        const int k0_ = cchunk << 6;
#pragma unroll
        for (int i_ = 0; i_ < 4; i_++) {
            int idx_ = i_ * 256 + tid;
            int r_ = idx_ >> 3, u_ = idx_ & 7;
            uint32_t sw_ = SWZ((uint32_t)(r_ * 128 + u_ * 16));
            CP_ASYNC16(st_ + F_A + sw_, (const char*)(A + (size_t)(m0 + r_) * K + k0_) + u_ * 16);
            CP_ASYNC16(st_ + F_B + sw_, (const char*)(B + (size_t)(n0 + r_) * K + k0_) + u_ * 16);
        }
        CP_COMMIT();
    };

    load_stage(0);
    load_stage(1);

    const int q8 = lid >> 3, lr = lid & 7;

    for (int cc = 0; cc < NC; cc++) {
        CP_WAIT1();
        __syncthreads();
        if (cc + 2 < NC) { load_stage(cc + 2); } else { CP_COMMIT(); }

        const uint32_t st = sb + (cc % 3) * FSTG;
#pragma unroll
        for (int ks = 0; ks < 4; ks++) {
            const int kb = ks * 32;
            uint32_t ah[2][4], bh[8][2];
#pragma unroll
            for (int mi = 0; mi < 2; mi++) {
                uint32_t off = SWZ((uint32_t)(
                    (wm * 32 + mi * 16 + lr + (q8 & 1) * 8) * 128 + kb + (q8 >> 1) * 16));
                ldsm4(ah[mi], st + F_A + off);
            }
#pragma unroll
            for (int njp = 0; njp < 4; njp++) {
                uint32_t off = SWZ((uint32_t)(
                    (wn * 64 + njp * 16 + lr + (q8 >> 1) * 8) * 128 + kb + (q8 & 1) * 16));
                uint32_t t0[4];
                ldsm4(t0, st + F_B + off);
                bh[2 * njp][0] = t0[0]; bh[2 * njp][1] = t0[1];
                bh[2 * njp + 1][0] = t0[2]; bh[2 * njp + 1][1] = t0[3];
            }
#pragma unroll
            for (int mi = 0; mi < 2; mi++)
#pragma unroll
                for (int nj = 0; nj < 8; nj++)
                    mma16816h(c[mi][nj], ah[mi], bh[nj][0], bh[nj][1]);
        }
    }

    const int lr4 = lid >> 2, lc = (lid & 3) * 2;
#pragma unroll
    for (int mi = 0; mi < 2; mi++) {
        int row = m0 + wm * 32 + mi * 16 + lr4;
#pragma unroll
        for (int nj = 0; nj < 8; nj++) {
            int col = n0 + wn * 64 + nj * 8 + lc;
            float2 b2 = *(const float2*)(bias + col);
            *(float2*)(C + (size_t)row * N + col) =
                make_float2(c[mi][nj][0] + b2.x, c[mi][nj][1] + b2.y);
            *(float2*)(C + (size_t)(row + 8) * N + col) =
                make_float2(c[mi][nj][2] + b2.x, c[mi][nj][3] + b2.y);
        }
    }
}

// ---------------------------------------------------------------------------
// HMMA flash attention: q-tile 128, 8 warps, 3-stage KV (48KB),
// wait1->sync->issue pipeline, Q staged in stage-2, 2 CTAs/SM forced.
// ---------------------------------------------------------------------------
struct AttnParams {
    const __half *q[2], *k[2], *v[2];
    const float *alpha, *beta;
    __half* of;
};

#define ATT_STAGE 16384
#define A_K 0
#define A_V 8192
#define ATT_SMEM (3 * ATT_STAGE)   // 48 KB -> 2 CTAs/SM
#define NCH 16
#define SOFTMAX_SCALE 0.125f

__global__ __launch_bounds__(256, 2)
void attn_mma(AttnParams p)
{
    extern __shared__ __align__(1024) char smem[];
    const uint32_t sb = smem_u32(smem);
    const int tid = threadIdx.x;
    const int w = tid >> 5, lid = tid & 31;
    const int q8 = lid >> 3, lr = lid & 7;
    const int h = blockIdx.y;
    const int qbase = blockIdx.x * 128;
    const int colbase = h * EDIM;

    const float alpha = *p.alpha;
    const float beta  = *p.beta;

    float osave[8][4];

    for (int st = 0; st < 2; st++) {
        const __half* __restrict__ qp = p.q[st];
        const __half* __restrict__ kp = p.k[st];
        const __half* __restrict__ vp = p.v[st];

        // ---- stage Q (128x64 = 16KB) into stage-2 region ----
        const uint32_t qst = sb + 2 * ATT_STAGE;
#pragma unroll
        for (int i = 0; i < 4; i++) {
            int idx = i * 256 + tid;            // 1024 = 128 rows x 8 chunks
            int r = idx >> 3, u = idx & 7;
            uint32_t sw = SWZ((uint32_t)(r * 128 + u * 16));
            CP_ASYNC16(qst + sw,
                       (const char*)(qp + (size_t)(qbase + r) * DINNER + colbase) + u * 16);
        }
        CP_COMMIT();

#define LOAD_KV(cchunk) do { \
            const uint32_t stg_ = sb + ((cchunk) % 3) * ATT_STAGE; \
            const int s0_ = (cchunk) * 64; \
            _Pragma("unroll") \
            for (int i_ = 0; i_ < 2; i_++) { \
                int idx_ = i_ * 256 + tid; \
                int r_ = idx_ >> 3, u_ = idx_ & 7; \
                uint32_t sw_ = SWZ((uint32_t)(r_ * 128 + u_ * 16)); \
                if (s0_ + r_ < SEQ_S) { \
                    const size_t go_ = (size_t)(s0_ + r_) * DINNER + colbase; \
                    CP_ASYNC16(stg_ + A_K + sw_, (const char*)(kp + go_) + u_ * 16); \
                    CP_ASYNC16(stg_ + A_V + sw_, (const char*)(vp + go_) + u_ * 16); \
                } else { \
                    STS_ZERO16(stg_ + A_K + sw_); \
                    STS_ZERO16(stg_ + A_V + sw_); \
                } \
            } \
            CP_COMMIT(); \
        } while (0)

        LOAD_KV(0);
        LOAD_KV(1);

        CP_WAIT2();            // Q complete (kv0/kv1 may still be in flight)
        __syncthreads();

        uint32_t qf[4][4];
#pragma unroll
        for (int ks = 0; ks < 4; ks++) {
            uint32_t off = SWZ((uint32_t)(
                (w * 16 + lr + (q8 & 1) * 8) * 128 + ks * 32 + (q8 >> 1) * 16));
            ldsm4(qf[ks], qst + off);
        }
        // stage-2 reuse (kv2) is issued only after the first in-loop sync,
        // which orders all warps' qf loads before the overwrite.

        float o[8][4];
#pragma unroll
        for (int t = 0; t < 8; t++)
#pragma unroll
            for (int i = 0; i < 4; i++) o[t][i] = 0.f;
        float m0r = -INFINITY, m1r = -INFINITY;
        float l0 = 0.f, l1 = 0.f;

        for (int cc = 0; cc < NCH; cc++) {
            CP_WAIT1();            // chunk cc done (cc+1 in flight)
            __syncthreads();       // qf reads + prior-chunk compute ordered
            if (cc + 2 < NCH) { LOAD_KV(cc + 2); } else { CP_COMMIT(); }
            const uint32_t stg = sb + (cc % 3) * ATT_STAGE;

            float s[8][4];
#pragma unroll
            for (int t = 0; t < 8; t++)
#pragma unroll
                for (int i = 0; i < 4; i++) s[t][i] = 0.f;

#pragma unroll
            for (int ks = 0; ks < 4; ks++) {
                uint32_t bh[8][2];
#pragma unroll
                for (int njp = 0; njp < 4; njp++) {
                    uint32_t off = SWZ((uint32_t)(
                        (njp * 16 + lr + (q8 >> 1) * 8) * 128 + ks * 32 + (q8 & 1) * 16));
                    uint32_t t0[4];
                    ldsm4(t0, stg + A_K + off);
                    bh[2 * njp][0] = t0[0]; bh[2 * njp][1] = t0[1];
                    bh[2 * njp + 1][0] = t0[2]; bh[2 * njp + 1][1] = t0[3];
                }
#pragma unroll
                for (int t = 0; t < 8; t++)
                    mma16816h(s[t], qf[ks], bh[t][0], bh[t][1]);
            }

            if (cc == NCH - 1) {
#pragma unroll
                for (int t = 5; t < 8; t++)
#pragma unroll
                    for (int i = 0; i < 4; i++) s[t][i] = -1e30f;
            }

            float ml0 = -1e30f, ml1 = -1e30f;
#pragma unroll
            for (int t = 0; t < 8; t++) {
                ml0 = fmaxf(ml0, fmaxf(s[t][0], s[t][1]));
                ml1 = fmaxf(ml1, fmaxf(s[t][2], s[t][3]));
            }
            ml0 = fmaxf(ml0, __shfl_xor_sync(0xffffffffu, ml0, 1));
            ml0 = fmaxf(ml0, __shfl_xor_sync(0xffffffffu, ml0, 2));
            ml1 = fmaxf(ml1, __shfl_xor_sync(0xffffffffu, ml1, 1));
            ml1 = fmaxf(ml1, __shfl_xor_sync(0xffffffffu, ml1, 2));

            float mn0 = fmaxf(m0r, ml0), mn1 = fmaxf(m1r, ml1);
            float c0 = __expf((m0r - mn0) * SOFTMAX_SCALE);
            float c1 = __expf((m1r - mn1) * SOFTMAX_SCALE);
            m0r = mn0; m1r = mn1;
            l0 *= c0; l1 *= c1;
#pragma unroll
            for (int t = 0; t < 8; t++) {
                o[t][0] *= c0; o[t][1] *= c0;
                o[t][2] *= c1; o[t][3] *= c1;
            }
#pragma unroll
            for (int t = 0; t < 8; t++) {
                float p0 = __expf((s[t][0] - mn0) * SOFTMAX_SCALE);
                float p1 = __expf((s[t][1] - mn0) * SOFTMAX_SCALE);
                float p2 = __expf((s[t][2] - mn1) * SOFTMAX_SCALE);
                float p3 = __expf((s[t][3] - mn1) * SOFTMAX_SCALE);
                l0 += p0 + p1; l1 += p2 + p3;
                s[t][0] = p0; s[t][1] = p1; s[t][2] = p2; s[t][3] = p3;
            }

#pragma unroll
            for (int ks = 0; ks < 4; ks++) {
                uint32_t pa[4];
                __half2 pp0 = __floats2half2_rn(s[2 * ks][0],     s[2 * ks][1]);
                __half2 pp1 = __floats2half2_rn(s[2 * ks][2],     s[2 * ks][3]);
                __half2 pp2 = __floats2half2_rn(s[2 * ks + 1][0], s[2 * ks + 1][1]);
                __half2 pp3 = __floats2half2_rn(s[2 * ks + 1][2], s[2 * ks + 1][3]);
                pa[0] = *reinterpret_cast<uint32_t*>(&pp0);
                pa[1] = *reinterpret_cast<uint32_t*>(&pp1);
                pa[2] = *reinterpret_cast<uint32_t*>(&pp2);
                pa[3] = *reinterpret_cast<uint32_t*>(&pp3);
#pragma unroll
                for (int ep = 0; ep < 4; ep++) {
                    uint32_t off = SWZ((uint32_t)(
                        (ks * 16 + lr + (q8 & 1) * 8) * 128 + ep * 32 + (q8 >> 1) * 16));
                    uint32_t tv0[4];
                    ldsm4t(tv0, stg + A_V + off);
                    mma16816h(o[2 * ep],     pa, tv0[0], tv0[1]);
                    mma16816h(o[2 * ep + 1], pa, tv0[2], tv0[3]);
                }
            }
        }

        l0 += __shfl_xor_sync(0xffffffffu, l0, 1);
        l0 += __shfl_xor_sync(0xffffffffu, l0, 2);
        l1 += __shfl_xor_sync(0xffffffffu, l1, 1);
        l1 += __shfl_xor_sync(0xffffffffu, l1, 2);
        float wgt = (st == 0) ? alpha : beta;
        float f0 = wgt / l0, f1 = wgt / l1;
        if (st == 0) {
#pragma unroll
            for (int t = 0; t < 8; t++) {
                osave[t][0] = o[t][0] * f0; osave[t][1] = o[t][1] * f0;
                osave[t][2] = o[t][2] * f1; osave[t][3] = o[t][3] * f1;
            }
        } else {
#pragma unroll
            for (int t = 0; t < 8; t++) {
                osave[t][0] += o[t][0] * f0; osave[t][1] += o[t][1] * f0;
                osave[t][2] += o[t][2] * f1; osave[t][3] += o[t][3] * f1;
            }
        }
        __syncthreads();   // all warps done with smem before next stream restages
    }

    const int r0 = qbase + w * 16 + (lid >> 2);
#pragma unroll
    for (int t = 0; t < 8; t++) {
        int col = colbase + t * 8 + (lid & 3) * 2;
        __half2 h0 = __floats2half2_rn(osave[t][0], osave[t][1]);
        __half2 h1 = __floats2half2_rn(osave[t][2], osave[t][3]);
        *(uint32_t*)(p.of + (size_t)r0 * DINNER + col) = *reinterpret_cast<uint32_t*>(&h0);
        *(uint32_t*)(p.of + (size_t)(r0 + 8) * DINNER + col) = *reinterpret_cast<uint32_t*>(&h1);
    }
}

// ---------------------------------------------------------------------------
// Launch
// ---------------------------------------------------------------------------
extern "C" void kernel_launch(void* const* d_in, const int* in_sizes, int n_in,
                              void* d_out, int out_size)
{
    const float* target = (const float*)d_in[0];
    const float* source = (const float*)d_in[1];
    const float* value  = (const float*)d_in[2];
    const float* Wq_s = (const float*)d_in[3];  const float* bq_s = (const float*)d_in[4];
    const float* Wk_s = (const float*)d_in[5];  const float* bk_s = (const float*)d_in[6];
    const float* Wv_s = (const float*)d_in[7];  const float* bv_s = (const float*)d_in[8];
    const float* Wq_l = (const float*)d_in[9];  const float* bq_l = (const float*)d_in[10];
    const float* Wk_l = (const float*)d_in[11]; const float* bk_l = (const float*)d_in[12];
    const float* Wv_l = (const float*)d_in[13]; const float* bv_l = (const float*)d_in[14];
    const float* Wo   = (const float*)d_in[15]; const float* bo   = (const float*)d_in[16];
    const float* alpha = (const float*)d_in[17];
    const float* beta  = (const float*)d_in[18];
    float* out = (float*)d_out;

    __half *tf, *sf, *vf, *af16;
    cudaGetSymbolAddress((void**)&tf, g_tf);
    cudaGetSymbolAddress((void**)&sf, g_sf);
    cudaGetSymbolAddress((void**)&vf, g_vf);
    cudaGetSymbolAddress((void**)&af16, g_af16);

    __half *qs, *ql, *ks, *vs, *kl, *vl;
    cudaGetSymbolAddress((void**)&qs, g_qs); cudaGetSymbolAddress((void**)&ql, g_ql);
    cudaGetSymbolAddress((void**)&ks, g_ks); cudaGetSymbolAddress((void**)&vs, g_vs);
    cudaGetSymbolAddress((void**)&kl, g_kl); cudaGetSymbolAddress((void**)&vl, g_vl);

    __half *wqs, *wql, *wks, *wvs, *wkl, *wvl, *wo;
    cudaGetSymbolAddress((void**)&wqs, g_wqs); cudaGetSymbolAddress((void**)&wql, g_wql);
    cudaGetSymbolAddress((void**)&wks, g_wks); cudaGetSymbolAddress((void**)&wvs, g_wvs);
    cudaGetSymbolAddress((void**)&wkl, g_wkl); cudaGetSymbolAddress((void**)&wvl, g_wvl);
    cudaGetSymbolAddress((void**)&wo,  g_wo);

    cudaFuncSetAttribute(gemm_proj_f16, cudaFuncAttributeMaxDynamicSharedMemorySize, GEMM_SMEM);
    cudaFuncSetAttribute(gemm_out_f16,  cudaFuncAttributeMaxDynamicSharedMemorySize, GEMM_SMEM);
    cudaFuncSetAttribute(attn_mma,      cudaFuncAttributeMaxDynamicSharedMemorySize, ATT_SMEM);

    // --- merged prepass (all fp32 -> fp16) ---
    {
        PrepassParams pp = {};
        const float* Ws[7] = {Wq_s, Wq_l, Wk_s, Wv_s, Wk_l, Wv_l, Wo};
        __half* Ts[7] = {wqs, wql, wks, wvs, wkl, wvl, wo};
        const int Ks[7] = {DMODEL, DMODEL, DLLM, DLLM, DLLM, DLLM, DINNER};
        const int Ns[7] = {DINNER, DINNER, DINNER, DINNER, DINNER, DINNER, DLLM};
        int acc = 0;
        pp.t_ofs[0] = 0;
        for (int i = 0; i < 7; i++) {
            pp.W[i] = Ws[i]; pp.T[i] = Ts[i];
            pp.K[i] = Ks[i]; pp.N[i] = Ns[i];
            acc += (Ks[i] / 32) * (Ns[i] / 32);
            pp.t_ofs[i + 1] = acc;
        }
        pp.total_trans = acc;
        pp.X[0] = target; pp.H[0] = tf;
        pp.X[1] = source; pp.H[1] = sf;
        pp.X[2] = value;  pp.H[2] = vf;
        pp.s_ofs[0] = 0;
        pp.s_ofs[1] = (BL * DMODEL) / 16384;
        pp.s_ofs[2] = pp.s_ofs[1] + (SEQ_S * DLLM) / 16384;
        pp.s_ofs[3] = pp.s_ofs[2] + (SEQ_S * DLLM) / 16384;
        prepass<<<pp.total_trans + pp.s_ofs[3], 256>>>(pp);
    }

    // --- 6 projection GEMMs, one flat launch ---
    {
        ProjJobs p = {};
        const __half* As[6] = {tf, tf, sf, vf, sf, vf};
        const __half* Bs[6] = {wqs, wql, wks, wvs, wkl, wvl};
        const float* bs[6] = {bq_s, bq_l, bk_s, bv_s, bk_l, bv_l};
        __half* Cs[6] = {qs, ql, ks, vs, kl, vl};
        const int Ms[6] = {BL, BL, SEQ_S, SEQ_S, SEQ_S, SEQ_S};
        const int Ks2[6] = {DMODEL, DMODEL, DLLM, DLLM, DLLM, DLLM};
        int acc = 0;
        p.ofs[0] = 0;
        for (int i = 0; i < 6; i++) {
            p.A[i] = As[i]; p.B[i] = Bs[i]; p.bias[i] = bs[i]; p.C[i] = Cs[i];
            p.M[i] = Ms[i]; p.K[i] = Ks2[i];
            acc += 8 * ((Ms[i] + 127) / 128);
            p.ofs[i + 1] = acc;
        }
        gemm_proj_f16<<<acc, 256, GEMM_SMEM>>>(p);
    }

    // --- fused dual-stream flash attention (q-tile 128, 3-stage, 2 CTAs/SM) ---
    {
        AttnParams ap = {};
        ap.q[0] = qs; ap.k[0] = ks; ap.v[0] = vs;
        ap.q[1] = ql; ap.k[1] = kl; ap.v[1] = vl;
        ap.alpha = alpha; ap.beta = beta;
        ap.of = af16;
        dim3 g(BL / 128, NHEAD);                 // (64, 16)
        attn_mma<<<g, 256, ATT_SMEM>>>(ap);
    }

    // --- output projection ---
    {
        dim3 g(DLLM / 128, BL / 128);
        gemm_out_f16<<<g, 256, GEMM_SMEM>>>(af16, wo, bo, out);
    }
}